// round 1
// baseline (speedup 1.0000x reference)
#include <cuda_runtime.h>

#define S_LEN 2048
#define B_SZ 4
#define NH 16
#define DH 64
#define DM 1024
#define MROWS (B_SZ * S_LEN)   // 8192

// ---------------- scratch (device globals; no allocations allowed) ----------
__device__ float g_q[MROWS * DM];
__device__ float g_k[MROWS * DM];
__device__ float g_v[MROWS * DM];
__device__ float g_attn[MROWS * DM];
__device__ float g_maskadd[B_SZ * S_LEN];
__device__ int   g_mask_mode;

// ---------------- mask dtype detection --------------------------------------
// The reference mask is jnp.bool_. The harness may deliver it as int8 (raw
// bool bytes), int32, or float32. Inspect the first 8192 bytes (in-bounds
// under every hypothesis: the smallest case, int8, is exactly 8192 bytes):
//   - any byte value > 1            -> float32 (1.0f = 00 00 80 3f)
//   - else any byte at i%4!=0 set   -> int8/bool bytes
//   - else                          -> int32 (0/1 values, only byte0 ever set)
__global__ void detect_mask_kernel(const unsigned char* __restrict__ m) {
    __shared__ int f_nonbin, f_off;
    int tid = threadIdx.x;
    if (tid == 0) { f_nonbin = 0; f_off = 0; }
    __syncthreads();
    int loc_nb = 0, loc_off = 0;
    for (int i = tid; i < B_SZ * S_LEN; i += blockDim.x) {
        unsigned char v = m[i];
        if (v > 1) loc_nb = 1;
        if ((i & 3) && v) loc_off = 1;
    }
    if (loc_nb) atomicOr(&f_nonbin, 1);
    if (loc_off) atomicOr(&f_off, 1);
    __syncthreads();
    if (tid == 0) g_mask_mode = f_nonbin ? 2 : (f_off ? 1 : 0);
}

__global__ void expand_mask_kernel(const void* __restrict__ mraw) {
    int i = blockIdx.x * blockDim.x + threadIdx.x;
    if (i >= B_SZ * S_LEN) return;
    int mode = g_mask_mode;
    bool t;
    if (mode == 0)      t = ((const int*)mraw)[i] != 0;
    else if (mode == 1) t = ((const unsigned char*)mraw)[i] != 0;
    else                t = ((const float*)mraw)[i] != 0.0f;
    g_maskadd[i] = t ? 0.0f : -1e30f;
}

// ---------------- fp32 SIMT GEMM: C[M x 1024] = A[M x 1024] @ W + bias ------
// 128x128 CTA tile, BK=16, 256 threads, 8x8 per-thread microtile (4+4 split).
__device__ __forceinline__ void gemm_cta(const float* __restrict__ A,
                                         const float* __restrict__ W,
                                         const float* __restrict__ bias,
                                         float* __restrict__ C) {
    __shared__ float As[16][132];   // [k][m] transposed
    __shared__ float Bs[16][132];   // [k][n]

    const int tid = threadIdx.x;
    const int ty = tid >> 4, tx = tid & 15;
    const int m0 = blockIdx.y * 128;
    const int n0 = blockIdx.x * 128;

    float acc[8][8];
#pragma unroll
    for (int i = 0; i < 8; ++i)
#pragma unroll
        for (int j = 0; j < 8; ++j) acc[i][j] = 0.0f;

    for (int kt = 0; kt < DM / 16; ++kt) {
        // A tile: 128 rows x 16 k, transposed into As[k][m]
#pragma unroll
        for (int t = 0; t < 2; ++t) {
            int f = tid + t * 256;          // 0..511
            int r = f >> 2, kq = f & 3;
            float4 v = *(const float4*)&A[(m0 + r) * DM + kt * 16 + kq * 4];
            As[kq * 4 + 0][r] = v.x;
            As[kq * 4 + 1][r] = v.y;
            As[kq * 4 + 2][r] = v.z;
            As[kq * 4 + 3][r] = v.w;
        }
        // B tile: 16 k rows x 128 n, stored directly
#pragma unroll
        for (int t = 0; t < 2; ++t) {
            int f = tid + t * 256;
            int r = f >> 5, c4 = f & 31;
            *(float4*)&Bs[r][c4 * 4] =
                *(const float4*)&W[(kt * 16 + r) * DM + n0 + c4 * 4];
        }
        __syncthreads();

#pragma unroll
        for (int kk = 0; kk < 16; ++kk) {
            float a[8], b[8];
            *(float4*)&a[0] = *(const float4*)&As[kk][ty * 4];
            *(float4*)&a[4] = *(const float4*)&As[kk][64 + ty * 4];
            *(float4*)&b[0] = *(const float4*)&Bs[kk][tx * 4];
            *(float4*)&b[4] = *(const float4*)&Bs[kk][64 + tx * 4];
#pragma unroll
            for (int i = 0; i < 8; ++i)
#pragma unroll
                for (int j = 0; j < 8; ++j)
                    acc[i][j] += a[i] * b[j];
        }
        __syncthreads();
    }

    // epilogue: add bias, write float4s
#pragma unroll
    for (int i = 0; i < 8; ++i) {
        int r = m0 + ((i < 4) ? (ty * 4 + i) : (64 + ty * 4 + i - 4));
#pragma unroll
        for (int jh = 0; jh < 2; ++jh) {
            int c = n0 + jh * 64 + tx * 4;
            float4 bv = *(const float4*)&bias[c];
            float4 o;
            o.x = acc[i][jh * 4 + 0] + bv.x;
            o.y = acc[i][jh * 4 + 1] + bv.y;
            o.z = acc[i][jh * 4 + 2] + bv.z;
            o.w = acc[i][jh * 4 + 3] + bv.w;
            *(float4*)&C[r * DM + c] = o;
        }
    }
}

__global__ __launch_bounds__(256)
void qkv_kernel(const float* __restrict__ x,
                const float* __restrict__ Wq, const float* __restrict__ bq,
                const float* __restrict__ Wk, const float* __restrict__ bk,
                const float* __restrict__ Wv, const float* __restrict__ bv) {
    const float* W; const float* b; float* out;
    if (blockIdx.z == 0)      { W = Wq; b = bq; out = g_q; }
    else if (blockIdx.z == 1) { W = Wk; b = bk; out = g_k; }
    else                      { W = Wv; b = bv; out = g_v; }
    gemm_cta(x, W, b, out);
}

__global__ __launch_bounds__(256)
void oproj_kernel(const float* __restrict__ Wo, const float* __restrict__ bo,
                  float* __restrict__ out) {
    gemm_cta(g_attn, Wo, bo, out);
}

// ---------------- flash attention (fp32, online softmax) --------------------
// CTA: 64 queries of one (b,h); loop over 32 key blocks of 64.
// 256 threads as 16x16; each thread owns a 4x4 S tile and a 4(rows)x4(cols)
// O tile (cols tx*4..+3 of Dh).
#define AST 68   // smem row stride in floats (17 float4s -> conflict-friendly)

__global__ __launch_bounds__(256)
void attn_kernel() {
    extern __shared__ float sm[];
    float* Qs = sm;                  // 64*AST
    float* Ks = Qs + 64 * AST;
    float* Vs = Ks + 64 * AST;
    float* Ps = Vs + 64 * AST;
    float* Ms = Ps + 64 * AST;       // 64 mask addends

    const int tid = threadIdx.x;
    const int ty = tid >> 4, tx = tid & 15;
    const int qb = blockIdx.x;       // 0..31
    const int bh = blockIdx.y;       // 0..63
    const int b = bh >> 4, h = bh & 15;
    const int qrow0 = b * S_LEN + qb * 64;

    // load Q tile [64 x 64]
#pragma unroll
    for (int t = 0; t < 4; ++t) {
        int f = tid + t * 256;       // 0..1023
        int r = f >> 4, d4 = f & 15;
        *(float4*)&Qs[r * AST + d4 * 4] =
            *(const float4*)&g_q[(qrow0 + r) * DM + h * DH + d4 * 4];
    }

    float O[4][4];
    float m_i[4], l_i[4];
#pragma unroll
    for (int i = 0; i < 4; ++i) {
        m_i[i] = -1e30f; l_i[i] = 0.0f;
#pragma unroll
        for (int j = 0; j < 4; ++j) O[i][j] = 0.0f;
    }

    for (int kb = 0; kb < S_LEN / 64; ++kb) {
        __syncthreads();   // previous iteration done reading Ks/Vs/Ps (covers Qs load too)
        // load K,V tiles + mask addends
#pragma unroll
        for (int t = 0; t < 4; ++t) {
            int f = tid + t * 256;
            int r = f >> 4, d4 = f & 15;
            int row = b * S_LEN + kb * 64 + r;
            *(float4*)&Ks[r * AST + d4 * 4] =
                *(const float4*)&g_k[row * DM + h * DH + d4 * 4];
            *(float4*)&Vs[r * AST + d4 * 4] =
                *(const float4*)&g_v[row * DM + h * DH + d4 * 4];
        }
        if (tid < 64) Ms[tid] = g_maskadd[b * S_LEN + kb * 64 + tid];
        __syncthreads();

        // S = Q K^T  (4x4 per thread, dot over Dh=64 in float4 steps)
        float sacc[4][4];
#pragma unroll
        for (int i = 0; i < 4; ++i)
#pragma unroll
            for (int j = 0; j < 4; ++j) sacc[i][j] = 0.0f;

#pragma unroll
        for (int d4 = 0; d4 < 16; ++d4) {
            float4 a[4], kv[4];
#pragma unroll
            for (int i = 0; i < 4; ++i)
                a[i] = *(const float4*)&Qs[(ty * 4 + i) * AST + d4 * 4];
#pragma unroll
            for (int j = 0; j < 4; ++j)
                kv[j] = *(const float4*)&Ks[(tx * 4 + j) * AST + d4 * 4];
#pragma unroll
            for (int i = 0; i < 4; ++i)
#pragma unroll
                for (int j = 0; j < 4; ++j) {
                    sacc[i][j] += a[i].x * kv[j].x;
                    sacc[i][j] += a[i].y * kv[j].y;
                    sacc[i][j] += a[i].z * kv[j].z;
                    sacc[i][j] += a[i].w * kv[j].w;
                }
        }

        // masked + scaled scores; online softmax update
        float mk[4];
#pragma unroll
        for (int j = 0; j < 4; ++j) mk[j] = Ms[tx * 4 + j];

#pragma unroll
        for (int i = 0; i < 4; ++i) {
            float s[4];
#pragma unroll
            for (int j = 0; j < 4; ++j) s[j] = sacc[i][j] * 0.125f + mk[j];

            float rm = fmaxf(fmaxf(s[0], s[1]), fmaxf(s[2], s[3]));
#pragma unroll
            for (int off = 8; off > 0; off >>= 1)
                rm = fmaxf(rm, __shfl_xor_sync(0xffffffffu, rm, off));

            float mnew = fmaxf(m_i[i], rm);
            float alpha = __expf(m_i[i] - mnew);
            float p[4], rs = 0.0f;
#pragma unroll
            for (int j = 0; j < 4; ++j) { p[j] = __expf(s[j] - mnew); rs += p[j]; }
#pragma unroll
            for (int off = 8; off > 0; off >>= 1)
                rs += __shfl_xor_sync(0xffffffffu, rs, off);

            l_i[i] = l_i[i] * alpha + rs;
            m_i[i] = mnew;
#pragma unroll
            for (int j = 0; j < 4; ++j) {
                O[i][j] *= alpha;
                Ps[(ty * 4 + i) * AST + tx * 4 + j] = p[j];
            }
        }
        __syncthreads();

        // O += P @ V
#pragma unroll 8
        for (int k = 0; k < 64; ++k) {
            float4 v = *(const float4*)&Vs[k * AST + tx * 4];
#pragma unroll
            for (int i = 0; i < 4; ++i) {
                float p = Ps[(ty * 4 + i) * AST + k];
                O[i][0] += p * v.x;
                O[i][1] += p * v.y;
                O[i][2] += p * v.z;
                O[i][3] += p * v.w;
            }
        }
    }

    // finalize and write
#pragma unroll
    for (int i = 0; i < 4; ++i) {
        float inv = 1.0f / l_i[i];
        float4 o;
        o.x = O[i][0] * inv; o.y = O[i][1] * inv;
        o.z = O[i][2] * inv; o.w = O[i][3] * inv;
        *(float4*)&g_attn[(qrow0 + ty * 4 + i) * DM + h * DH + tx * 4] = o;
    }
}

// ---------------- launch -----------------------------------------------------
extern "C" void kernel_launch(void* const* d_in, const int* in_sizes, int n_in,
                              void* d_out, int out_size) {
    const float* x  = (const float*)d_in[0];
    const void*  mk = d_in[1];
    const float* Wq = (const float*)d_in[2];
    const float* bq = (const float*)d_in[3];
    const float* Wk = (const float*)d_in[4];
    const float* bk = (const float*)d_in[5];
    const float* Wv = (const float*)d_in[6];
    const float* bv = (const float*)d_in[7];
    const float* Wo = (const float*)d_in[8];
    const float* bo = (const float*)d_in[9];
    float* out = (float*)d_out;

    detect_mask_kernel<<<1, 256>>>((const unsigned char*)mk);
    expand_mask_kernel<<<(B_SZ * S_LEN + 255) / 256, 256>>>(mk);

    qkv_kernel<<<dim3(DM / 128, MROWS / 128, 3), 256>>>(x, Wq, bq, Wk, bk, Wv, bv);

    int smem = (4 * 64 * AST + 64) * (int)sizeof(float);   // ~69.9 KB
    static int attn_smem_set = 0;
    cudaFuncSetAttribute(attn_kernel, cudaFuncAttributeMaxDynamicSharedMemorySize, smem);
    (void)attn_smem_set;
    attn_kernel<<<dim3(S_LEN / 64, B_SZ * NH), 256, smem>>>();

    oproj_kernel<<<dim3(DM / 128, MROWS / 128), 256>>>(Wo, bo, out);
}

// round 5
// speedup vs baseline: 1.1369x; 1.1369x over previous
#include <cuda_runtime.h>
#include <cuda_bf16.h>
#include <cstdint>

#define S_LEN 2048
#define B_SZ 4
#define NH 16
#define DH 64
#define DM 1024
#define MROWS (B_SZ * S_LEN)   // 8192
#define GK 1024

// ---------------- scratch (device globals; no allocations allowed) ----------
// NOTE: these are referenced ONLY from device code. Passing a __device__
// symbol as a host-side kernel argument silently yields the host shadow
// address (writable via ATS on GB300!) — that was the R3/R4 bug.
__device__ float g_q[MROWS * DM];
__device__ float g_k[MROWS * DM];
__device__ float g_v[MROWS * DM];
__device__ float g_attn[MROWS * DM];
__device__ float g_maskadd[B_SZ * S_LEN];
__device__ int   g_mask_mode;

__device__ __nv_bfloat16 g_xhi[MROWS * DM];
__device__ __nv_bfloat16 g_xlo[MROWS * DM];
__device__ __nv_bfloat16 g_ahi[MROWS * DM];
__device__ __nv_bfloat16 g_alo[MROWS * DM];
__device__ __nv_bfloat16 g_wthi[4 * DM * DM];   // W^T, [N][K] K-major
__device__ __nv_bfloat16 g_wtlo[4 * DM * DM];

// ---------------- PTX helpers ------------------------------------------------
#define MMA_BF16(c, a, b0, b1)                                              \
    asm volatile("mma.sync.aligned.m16n8k16.row.col.f32.bf16.bf16.f32 "     \
                 "{%0,%1,%2,%3}, {%4,%5,%6,%7}, {%8,%9}, {%0,%1,%2,%3};"    \
                 : "+f"((c)[0]), "+f"((c)[1]), "+f"((c)[2]), "+f"((c)[3])   \
                 : "r"((a)[0]), "r"((a)[1]), "r"((a)[2]), "r"((a)[3]),      \
                   "r"(b0), "r"(b1))

// ---------------- mask dtype detection --------------------------------------
__global__ void detect_mask_kernel(const unsigned char* __restrict__ m) {
    __shared__ int f_nonbin, f_off;
    int tid = threadIdx.x;
    if (tid == 0) { f_nonbin = 0; f_off = 0; }
    __syncthreads();
    int loc_nb = 0, loc_off = 0;
    for (int i = tid; i < B_SZ * S_LEN; i += blockDim.x) {
        unsigned char v = m[i];
        if (v > 1) loc_nb = 1;
        if ((i & 3) && v) loc_off = 1;
    }
    if (loc_nb) atomicOr(&f_nonbin, 1);
    if (loc_off) atomicOr(&f_off, 1);
    __syncthreads();
    if (tid == 0) g_mask_mode = f_nonbin ? 2 : (f_off ? 1 : 0);
}

__global__ void expand_mask_kernel(const void* __restrict__ mraw) {
    int i = blockIdx.x * blockDim.x + threadIdx.x;
    if (i >= B_SZ * S_LEN) return;
    int mode = g_mask_mode;
    bool t;
    if (mode == 0)      t = ((const int*)mraw)[i] != 0;
    else if (mode == 1) t = ((const unsigned char*)mraw)[i] != 0;
    else                t = ((const float*)mraw)[i] != 0.0f;
    g_maskadd[i] = t ? 0.0f : -1e30f;
}

// ---------------- fp32 -> bf16 hi/lo conversions (device-global targets) -----
__global__ __launch_bounds__(256)
void conv_x_kernel(const float* __restrict__ src) {
    int i = blockIdx.x * blockDim.x + threadIdx.x;
    if (i >= MROWS * DM) return;
    float v = src[i];
    __nv_bfloat16 h = __float2bfloat16(v);
    g_xhi[i] = h;
    g_xlo[i] = __float2bfloat16(v - __bfloat162float(h));
}

__global__ __launch_bounds__(256)
void conv_attn_kernel() {
    int i = blockIdx.x * blockDim.x + threadIdx.x;
    if (i >= MROWS * DM) return;
    float v = g_attn[i];
    __nv_bfloat16 h = __float2bfloat16(v);
    g_ahi[i] = h;
    g_alo[i] = __float2bfloat16(v - __bfloat162float(h));
}

// ---------------- W transpose + bf16 hi/lo -----------------------------------
__global__ __launch_bounds__(256)
void prep_w_kernel(const float* __restrict__ Wq, const float* __restrict__ Wk,
                   const float* __restrict__ Wv, const float* __restrict__ Wo) {
    __shared__ float t[32][33];
    int z = blockIdx.z;
    const float* W = (z == 0) ? Wq : (z == 1) ? Wk : (z == 2) ? Wv : Wo;
    __nv_bfloat16* oh = g_wthi + (size_t)z * DM * DM;
    __nv_bfloat16* ol = g_wtlo + (size_t)z * DM * DM;
    int x0 = blockIdx.x * 32, y0 = blockIdx.y * 32;
    int tx = threadIdx.x, ty = threadIdx.y;   // (32, 8)
#pragma unroll
    for (int j = 0; j < 4; ++j)
        t[ty + j * 8][tx] = W[(size_t)(y0 + ty + j * 8) * DM + x0 + tx];
    __syncthreads();
#pragma unroll
    for (int j = 0; j < 4; ++j) {
        float v = t[tx][ty + j * 8];   // = W[y0+tx][x0+ty+j*8]
        __nv_bfloat16 h = __float2bfloat16(v);
        size_t o = (size_t)(x0 + ty + j * 8) * DM + y0 + tx;   // Wt[n][k]
        oh[o] = h;
        ol[o] = __float2bfloat16(v - __bfloat162float(h));
    }
}

// ---------------- mma.sync bf16x3 GEMM (direct-LDS fragments) ----------------
// C[8192 x 1024] = A @ W^T + bias.  CTA 128x128, BK=32, 8 warps (4m x 2n),
// warp tile 32x64.  3 passes: Ahi*Bhi + Alo*Bhi + Ahi*Blo into fp32 accum.
#define AS_STRIDE 40   // bf16 elements per smem row (80 B)

__device__ __forceinline__ void gemm_tc_body(const __nv_bfloat16* __restrict__ Ahi,
                                             const __nv_bfloat16* __restrict__ Alo,
                                             const __nv_bfloat16* __restrict__ Bhi,
                                             const __nv_bfloat16* __restrict__ Blo,
                                             const float* __restrict__ bias,
                                             float* __restrict__ C) {
    __shared__ __nv_bfloat16 As[2][128][AS_STRIDE];   // [hi/lo][m][k]
    __shared__ __nv_bfloat16 Bs[2][128][AS_STRIDE];   // [hi/lo][n][k]

    const int tid  = threadIdx.x;
    const int lane = tid & 31, warp = tid >> 5;
    const int wm = (warp & 3) * 32;
    const int wn = (warp >> 2) * 64;
    const int m0 = blockIdx.y * 128;
    const int n0 = blockIdx.x * 128;
    const int grp = lane >> 2;              // groupID
    const int tig = lane & 3;               // threadID_in_group

    float acc[2][8][4];
#pragma unroll
    for (int mt = 0; mt < 2; ++mt)
#pragma unroll
        for (int nt = 0; nt < 8; ++nt)
#pragma unroll
            for (int e = 0; e < 4; ++e) acc[mt][nt][e] = 0.0f;

    for (int kt = 0; kt < GK / 32; ++kt) {
        __syncthreads();
#pragma unroll
        for (int t = 0; t < 2; ++t) {
            int i = tid + t * 256;          // 0..511
            int r = i >> 2, q = i & 3;
            *(uint4*)&As[0][r][q * 8] = *(const uint4*)&Ahi[(size_t)(m0 + r) * GK + kt * 32 + q * 8];
            *(uint4*)&As[1][r][q * 8] = *(const uint4*)&Alo[(size_t)(m0 + r) * GK + kt * 32 + q * 8];
            *(uint4*)&Bs[0][r][q * 8] = *(const uint4*)&Bhi[(size_t)(n0 + r) * GK + kt * 32 + q * 8];
            *(uint4*)&Bs[1][r][q * 8] = *(const uint4*)&Blo[(size_t)(n0 + r) * GK + kt * 32 + q * 8];
        }
        __syncthreads();

#pragma unroll
        for (int ks = 0; ks < 2; ++ks) {
            const int kof = ks * 16 + tig * 2;

            uint32_t bh[8][2], bl[8][2];
#pragma unroll
            for (int nt = 0; nt < 8; ++nt) {
                const int nr = wn + nt * 8 + grp;
                bh[nt][0] = *(const uint32_t*)&Bs[0][nr][kof];
                bh[nt][1] = *(const uint32_t*)&Bs[0][nr][kof + 8];
                bl[nt][0] = *(const uint32_t*)&Bs[1][nr][kof];
                bl[nt][1] = *(const uint32_t*)&Bs[1][nr][kof + 8];
            }

#pragma unroll
            for (int mt = 0; mt < 2; ++mt) {
                const int mr = wm + mt * 16 + grp;
                uint32_t a_h[4], a_l[4];
                a_h[0] = *(const uint32_t*)&As[0][mr][kof];
                a_h[1] = *(const uint32_t*)&As[0][mr + 8][kof];
                a_h[2] = *(const uint32_t*)&As[0][mr][kof + 8];
                a_h[3] = *(const uint32_t*)&As[0][mr + 8][kof + 8];
                a_l[0] = *(const uint32_t*)&As[1][mr][kof];
                a_l[1] = *(const uint32_t*)&As[1][mr + 8][kof];
                a_l[2] = *(const uint32_t*)&As[1][mr][kof + 8];
                a_l[3] = *(const uint32_t*)&As[1][mr + 8][kof + 8];
#pragma unroll
                for (int nt = 0; nt < 8; ++nt) {
                    MMA_BF16(acc[mt][nt], a_h, bh[nt][0], bh[nt][1]);
                    MMA_BF16(acc[mt][nt], a_l, bh[nt][0], bh[nt][1]);
                    MMA_BF16(acc[mt][nt], a_h, bl[nt][0], bl[nt][1]);
                }
            }
        }
    }

#pragma unroll
    for (int mt = 0; mt < 2; ++mt) {
#pragma unroll
        for (int nt = 0; nt < 8; ++nt) {
            int r = m0 + wm + mt * 16 + grp;
            int c = n0 + wn + nt * 8 + tig * 2;
            float2 bb = *(const float2*)&bias[c];
            float2 v0 = { acc[mt][nt][0] + bb.x, acc[mt][nt][1] + bb.y };
            float2 v1 = { acc[mt][nt][2] + bb.x, acc[mt][nt][3] + bb.y };
            *(float2*)&C[(size_t)r * DM + c] = v0;
            *(float2*)&C[(size_t)(r + 8) * DM + c] = v1;
        }
    }
}

__global__ __launch_bounds__(256)
void qkv_tc_kernel(const float* __restrict__ bq, const float* __restrict__ bk,
                   const float* __restrict__ bv) {
    int z = blockIdx.z;
    const __nv_bfloat16* Bh = g_wthi + (size_t)z * DM * DM;
    const __nv_bfloat16* Bl = g_wtlo + (size_t)z * DM * DM;
    const float* bias = (z == 0) ? bq : (z == 1) ? bk : bv;
    float* C = (z == 0) ? g_q : (z == 1) ? g_k : g_v;
    gemm_tc_body(g_xhi, g_xlo, Bh, Bl, bias, C);
}

__global__ __launch_bounds__(256)
void oproj_tc_kernel(const float* __restrict__ bo, float* __restrict__ out) {
    gemm_tc_body(g_ahi, g_alo, g_wthi + (size_t)3 * DM * DM,
                 g_wtlo + (size_t)3 * DM * DM, bo, out);
}

// ---------------- flash attention (fp32, online softmax) — proven R1 code ----
#define AST 68

__global__ __launch_bounds__(256)
void attn_kernel() {
    extern __shared__ float sm[];
    float* Qs = sm;
    float* Ks = Qs + 64 * AST;
    float* Vs = Ks + 64 * AST;
    float* Ps = Vs + 64 * AST;
    float* Ms = Ps + 64 * AST;

    const int tid = threadIdx.x;
    const int ty = tid >> 4, tx = tid & 15;
    const int qb = blockIdx.x;
    const int bh = blockIdx.y;
    const int b = bh >> 4, h = bh & 15;
    const int qrow0 = b * S_LEN + qb * 64;

#pragma unroll
    for (int t = 0; t < 4; ++t) {
        int f = tid + t * 256;
        int r = f >> 4, d4 = f & 15;
        *(float4*)&Qs[r * AST + d4 * 4] =
            *(const float4*)&g_q[(qrow0 + r) * DM + h * DH + d4 * 4];
    }

    float O[4][4];
    float m_i[4], l_i[4];
#pragma unroll
    for (int i = 0; i < 4; ++i) {
        m_i[i] = -1e30f; l_i[i] = 0.0f;
#pragma unroll
        for (int j = 0; j < 4; ++j) O[i][j] = 0.0f;
    }

    for (int kb = 0; kb < S_LEN / 64; ++kb) {
        __syncthreads();
#pragma unroll
        for (int t = 0; t < 4; ++t) {
            int f = tid + t * 256;
            int r = f >> 4, d4 = f & 15;
            int row = b * S_LEN + kb * 64 + r;
            *(float4*)&Ks[r * AST + d4 * 4] =
                *(const float4*)&g_k[row * DM + h * DH + d4 * 4];
            *(float4*)&Vs[r * AST + d4 * 4] =
                *(const float4*)&g_v[row * DM + h * DH + d4 * 4];
        }
        if (tid < 64) Ms[tid] = g_maskadd[b * S_LEN + kb * 64 + tid];
        __syncthreads();

        float sacc[4][4];
#pragma unroll
        for (int i = 0; i < 4; ++i)
#pragma unroll
            for (int j = 0; j < 4; ++j) sacc[i][j] = 0.0f;

#pragma unroll
        for (int d4 = 0; d4 < 16; ++d4) {
            float4 a[4], kv[4];
#pragma unroll
            for (int i = 0; i < 4; ++i)
                a[i] = *(const float4*)&Qs[(ty * 4 + i) * AST + d4 * 4];
#pragma unroll
            for (int j = 0; j < 4; ++j)
                kv[j] = *(const float4*)&Ks[(tx * 4 + j) * AST + d4 * 4];
#pragma unroll
            for (int i = 0; i < 4; ++i)
#pragma unroll
                for (int j = 0; j < 4; ++j) {
                    sacc[i][j] += a[i].x * kv[j].x;
                    sacc[i][j] += a[i].y * kv[j].y;
                    sacc[i][j] += a[i].z * kv[j].z;
                    sacc[i][j] += a[i].w * kv[j].w;
                }
        }

        float mk[4];
#pragma unroll
        for (int j = 0; j < 4; ++j) mk[j] = Ms[tx * 4 + j];

#pragma unroll
        for (int i = 0; i < 4; ++i) {
            float s[4];
#pragma unroll
            for (int j = 0; j < 4; ++j) s[j] = sacc[i][j] * 0.125f + mk[j];

            float rm = fmaxf(fmaxf(s[0], s[1]), fmaxf(s[2], s[3]));
#pragma unroll
            for (int off = 8; off > 0; off >>= 1)
                rm = fmaxf(rm, __shfl_xor_sync(0xffffffffu, rm, off));

            float mnew = fmaxf(m_i[i], rm);
            float alpha = __expf(m_i[i] - mnew);
            float p[4], rs = 0.0f;
#pragma unroll
            for (int j = 0; j < 4; ++j) { p[j] = __expf(s[j] - mnew); rs += p[j]; }
#pragma unroll
            for (int off = 8; off > 0; off >>= 1)
                rs += __shfl_xor_sync(0xffffffffu, rs, off);

            l_i[i] = l_i[i] * alpha + rs;
            m_i[i] = mnew;
#pragma unroll
            for (int j = 0; j < 4; ++j) {
                O[i][j] *= alpha;
                Ps[(ty * 4 + i) * AST + tx * 4 + j] = p[j];
            }
        }
        __syncthreads();

#pragma unroll 8
        for (int k = 0; k < 64; ++k) {
            float4 v = *(float4*)&Vs[k * AST + tx * 4];
#pragma unroll
            for (int i = 0; i < 4; ++i) {
                float p = Ps[(ty * 4 + i) * AST + k];
                O[i][0] += p * v.x;
                O[i][1] += p * v.y;
                O[i][2] += p * v.z;
                O[i][3] += p * v.w;
            }
        }
    }

#pragma unroll
    for (int i = 0; i < 4; ++i) {
        float inv = 1.0f / l_i[i];
        float4 o;
        o.x = O[i][0] * inv; o.y = O[i][1] * inv;
        o.z = O[i][2] * inv; o.w = O[i][3] * inv;
        *(float4*)&g_attn[(qrow0 + ty * 4 + i) * DM + h * DH + tx * 4] = o;
    }
}

// ---------------- launch -----------------------------------------------------
extern "C" void kernel_launch(void* const* d_in, const int* in_sizes, int n_in,
                              void* d_out, int out_size) {
    const float* x  = (const float*)d_in[0];
    const void*  mk = d_in[1];
    const float* Wq = (const float*)d_in[2];
    const float* bq = (const float*)d_in[3];
    const float* Wk = (const float*)d_in[4];
    const float* bk = (const float*)d_in[5];
    const float* Wv = (const float*)d_in[6];
    const float* bv = (const float*)d_in[7];
    const float* Wo = (const float*)d_in[8];
    const float* bo = (const float*)d_in[9];
    float* out = (float*)d_out;

    detect_mask_kernel<<<1, 256>>>((const unsigned char*)mk);
    expand_mask_kernel<<<(B_SZ * S_LEN + 255) / 256, 256>>>(mk);

    prep_w_kernel<<<dim3(32, 32, 4), dim3(32, 8)>>>(Wq, Wk, Wv, Wo);
    conv_x_kernel<<<(MROWS * DM + 255) / 256, 256>>>(x);

    qkv_tc_kernel<<<dim3(DM / 128, MROWS / 128, 3), 256>>>(bq, bk, bv);

    int smem = (4 * 64 * AST + 64) * (int)sizeof(float);
    cudaFuncSetAttribute(attn_kernel, cudaFuncAttributeMaxDynamicSharedMemorySize, smem);
    attn_kernel<<<dim3(S_LEN / 64, B_SZ * NH), 256, smem>>>();

    conv_attn_kernel<<<(MROWS * DM + 255) / 256, 256>>>();
    oproj_tc_kernel<<<dim3(DM / 128, MROWS / 128), 256>>>(bo, out);
}

// round 6
// speedup vs baseline: 3.0652x; 2.6960x over previous
#include <cuda_runtime.h>
#include <cuda_bf16.h>
#include <cuda_fp16.h>
#include <cstdint>

#define S_LEN 2048
#define B_SZ 4
#define NH 16
#define DH 64
#define DM 1024
#define MROWS (B_SZ * S_LEN)   // 8192
#define GK 1024

// ---------------- scratch (device globals; device-code references ONLY) -----
__device__ float g_maskadd[B_SZ * S_LEN];
__device__ int   g_mask_mode;

__device__ __nv_bfloat16 g_xhi[MROWS * DM];
__device__ __nv_bfloat16 g_xlo[MROWS * DM];
__device__ __nv_bfloat16 g_ahi[MROWS * DM];
__device__ __nv_bfloat16 g_alo[MROWS * DM];
__device__ __nv_bfloat16 g_wthi[4 * DM * DM];   // W^T, [N][K] K-major
__device__ __nv_bfloat16 g_wtlo[4 * DM * DM];

__device__ __half g_qhi[MROWS * DM];
__device__ __half g_qlo[MROWS * DM];
__device__ __half g_khi[MROWS * DM];
__device__ __half g_klo[MROWS * DM];
__device__ __half g_vhi[MROWS * DM];
__device__ __half g_vlo[MROWS * DM];

// ---------------- PTX helpers ------------------------------------------------
__device__ __forceinline__ uint32_t smem_u32(const void* p) {
    uint32_t a;
    asm("{ .reg .u64 t; cvta.to.shared.u64 t, %1; cvt.u32.u64 %0, t; }"
        : "=r"(a) : "l"(p));
    return a;
}

#define MMA_BF16(c, a, b0, b1)                                              \
    asm volatile("mma.sync.aligned.m16n8k16.row.col.f32.bf16.bf16.f32 "     \
                 "{%0,%1,%2,%3}, {%4,%5,%6,%7}, {%8,%9}, {%0,%1,%2,%3};"    \
                 : "+f"((c)[0]), "+f"((c)[1]), "+f"((c)[2]), "+f"((c)[3])   \
                 : "r"((a)[0]), "r"((a)[1]), "r"((a)[2]), "r"((a)[3]),      \
                   "r"(b0), "r"(b1))

#define MMA_F16(c, a, b0, b1)                                               \
    asm volatile("mma.sync.aligned.m16n8k16.row.col.f32.f16.f16.f32 "       \
                 "{%0,%1,%2,%3}, {%4,%5,%6,%7}, {%8,%9}, {%0,%1,%2,%3};"    \
                 : "+f"((c)[0]), "+f"((c)[1]), "+f"((c)[2]), "+f"((c)[3])   \
                 : "r"((a)[0]), "r"((a)[1]), "r"((a)[2]), "r"((a)[3]),      \
                   "r"(b0), "r"(b1))

#define LDMATRIX_X4_TRANS(r0, r1, r2, r3, addr)                             \
    asm volatile("ldmatrix.sync.aligned.m8n8.x4.trans.shared.b16 "          \
                 "{%0,%1,%2,%3}, [%4];"                                     \
                 : "=r"(r0), "=r"(r1), "=r"(r2), "=r"(r3) : "r"(addr))

__device__ __forceinline__ uint32_t pack_h2(float a, float b) {
    __half2 h = __floats2half2_rn(a, b);
    return *(uint32_t*)&h;
}

// ---------------- mask dtype detection --------------------------------------
__global__ void detect_mask_kernel(const unsigned char* __restrict__ m) {
    __shared__ int f_nonbin, f_off;
    int tid = threadIdx.x;
    if (tid == 0) { f_nonbin = 0; f_off = 0; }
    __syncthreads();
    int loc_nb = 0, loc_off = 0;
    for (int i = tid; i < B_SZ * S_LEN; i += blockDim.x) {
        unsigned char v = m[i];
        if (v > 1) loc_nb = 1;
        if ((i & 3) && v) loc_off = 1;
    }
    if (loc_nb) atomicOr(&f_nonbin, 1);
    if (loc_off) atomicOr(&f_off, 1);
    __syncthreads();
    if (tid == 0) g_mask_mode = f_nonbin ? 2 : (f_off ? 1 : 0);
}

__global__ void expand_mask_kernel(const void* __restrict__ mraw) {
    int i = blockIdx.x * blockDim.x + threadIdx.x;
    if (i >= B_SZ * S_LEN) return;
    int mode = g_mask_mode;
    bool t;
    if (mode == 0)      t = ((const int*)mraw)[i] != 0;
    else if (mode == 1) t = ((const unsigned char*)mraw)[i] != 0;
    else                t = ((const float*)mraw)[i] != 0.0f;
    g_maskadd[i] = t ? 0.0f : -1e30f;
}

// ---------------- fp32 -> bf16 hi/lo (x) -------------------------------------
__global__ __launch_bounds__(256)
void conv_x_kernel(const float* __restrict__ src) {
    int i = blockIdx.x * blockDim.x + threadIdx.x;
    if (i >= MROWS * DM) return;
    float v = src[i];
    __nv_bfloat16 h = __float2bfloat16(v);
    g_xhi[i] = h;
    g_xlo[i] = __float2bfloat16(v - __bfloat162float(h));
}

// ---------------- W transpose + bf16 hi/lo -----------------------------------
__global__ __launch_bounds__(256)
void prep_w_kernel(const float* __restrict__ Wq, const float* __restrict__ Wk,
                   const float* __restrict__ Wv, const float* __restrict__ Wo) {
    __shared__ float t[32][33];
    int z = blockIdx.z;
    const float* W = (z == 0) ? Wq : (z == 1) ? Wk : (z == 2) ? Wv : Wo;
    __nv_bfloat16* oh = g_wthi + (size_t)z * DM * DM;
    __nv_bfloat16* ol = g_wtlo + (size_t)z * DM * DM;
    int x0 = blockIdx.x * 32, y0 = blockIdx.y * 32;
    int tx = threadIdx.x, ty = threadIdx.y;   // (32, 8)
#pragma unroll
    for (int j = 0; j < 4; ++j)
        t[ty + j * 8][tx] = W[(size_t)(y0 + ty + j * 8) * DM + x0 + tx];
    __syncthreads();
#pragma unroll
    for (int j = 0; j < 4; ++j) {
        float v = t[tx][ty + j * 8];
        __nv_bfloat16 h = __float2bfloat16(v);
        size_t o = (size_t)(x0 + ty + j * 8) * DM + y0 + tx;
        oh[o] = h;
        ol[o] = __float2bfloat16(v - __bfloat162float(h));
    }
}

// ---------------- mma.sync bf16x3 GEMM (proven R5 core) ----------------------
#define AS_STRIDE 40

template <bool HALF_OUT>
__device__ __forceinline__ void gemm_tc_body(const __nv_bfloat16* __restrict__ Ahi,
                                             const __nv_bfloat16* __restrict__ Alo,
                                             const __nv_bfloat16* __restrict__ Bhi,
                                             const __nv_bfloat16* __restrict__ Blo,
                                             const float* __restrict__ bias,
                                             float* __restrict__ Cf,
                                             __half* __restrict__ Chi,
                                             __half* __restrict__ Clo) {
    __shared__ __nv_bfloat16 As[2][128][AS_STRIDE];
    __shared__ __nv_bfloat16 Bs[2][128][AS_STRIDE];

    const int tid  = threadIdx.x;
    const int lane = tid & 31, warp = tid >> 5;
    const int wm = (warp & 3) * 32;
    const int wn = (warp >> 2) * 64;
    const int m0 = blockIdx.y * 128;
    const int n0 = blockIdx.x * 128;
    const int grp = lane >> 2;
    const int tig = lane & 3;

    float acc[2][8][4];
#pragma unroll
    for (int mt = 0; mt < 2; ++mt)
#pragma unroll
        for (int nt = 0; nt < 8; ++nt)
#pragma unroll
            for (int e = 0; e < 4; ++e) acc[mt][nt][e] = 0.0f;

    for (int kt = 0; kt < GK / 32; ++kt) {
        __syncthreads();
#pragma unroll
        for (int t = 0; t < 2; ++t) {
            int i = tid + t * 256;
            int r = i >> 2, q = i & 3;
            *(uint4*)&As[0][r][q * 8] = *(const uint4*)&Ahi[(size_t)(m0 + r) * GK + kt * 32 + q * 8];
            *(uint4*)&As[1][r][q * 8] = *(const uint4*)&Alo[(size_t)(m0 + r) * GK + kt * 32 + q * 8];
            *(uint4*)&Bs[0][r][q * 8] = *(const uint4*)&Bhi[(size_t)(n0 + r) * GK + kt * 32 + q * 8];
            *(uint4*)&Bs[1][r][q * 8] = *(const uint4*)&Blo[(size_t)(n0 + r) * GK + kt * 32 + q * 8];
        }
        __syncthreads();

#pragma unroll
        for (int ks = 0; ks < 2; ++ks) {
            const int kof = ks * 16 + tig * 2;
            uint32_t bh[8][2], bl[8][2];
#pragma unroll
            for (int nt = 0; nt < 8; ++nt) {
                const int nr = wn + nt * 8 + grp;
                bh[nt][0] = *(const uint32_t*)&Bs[0][nr][kof];
                bh[nt][1] = *(const uint32_t*)&Bs[0][nr][kof + 8];
                bl[nt][0] = *(const uint32_t*)&Bs[1][nr][kof];
                bl[nt][1] = *(const uint32_t*)&Bs[1][nr][kof + 8];
            }
#pragma unroll
            for (int mt = 0; mt < 2; ++mt) {
                const int mr = wm + mt * 16 + grp;
                uint32_t a_h[4], a_l[4];
                a_h[0] = *(const uint32_t*)&As[0][mr][kof];
                a_h[1] = *(const uint32_t*)&As[0][mr + 8][kof];
                a_h[2] = *(const uint32_t*)&As[0][mr][kof + 8];
                a_h[3] = *(const uint32_t*)&As[0][mr + 8][kof + 8];
                a_l[0] = *(const uint32_t*)&As[1][mr][kof];
                a_l[1] = *(const uint32_t*)&As[1][mr + 8][kof];
                a_l[2] = *(const uint32_t*)&As[1][mr][kof + 8];
                a_l[3] = *(const uint32_t*)&As[1][mr + 8][kof + 8];
#pragma unroll
                for (int nt = 0; nt < 8; ++nt) {
                    MMA_BF16(acc[mt][nt], a_h, bh[nt][0], bh[nt][1]);
                    MMA_BF16(acc[mt][nt], a_l, bh[nt][0], bh[nt][1]);
                    MMA_BF16(acc[mt][nt], a_h, bl[nt][0], bl[nt][1]);
                }
            }
        }
    }

#pragma unroll
    for (int mt = 0; mt < 2; ++mt) {
#pragma unroll
        for (int nt = 0; nt < 8; ++nt) {
            int r = m0 + wm + mt * 16 + grp;
            int c = n0 + wn + nt * 8 + tig * 2;
            float2 bb = *(const float2*)&bias[c];
            float v0x = acc[mt][nt][0] + bb.x, v0y = acc[mt][nt][1] + bb.y;
            float v1x = acc[mt][nt][2] + bb.x, v1y = acc[mt][nt][3] + bb.y;
            if constexpr (HALF_OUT) {
                __half h0 = __float2half_rn(v0x), h1 = __float2half_rn(v0y);
                __half2 hp; hp.x = h0; hp.y = h1;
                __half2 lp; lp.x = __float2half_rn(v0x - __half2float(h0));
                            lp.y = __float2half_rn(v0y - __half2float(h1));
                *(__half2*)&Chi[(size_t)r * DM + c] = hp;
                *(__half2*)&Clo[(size_t)r * DM + c] = lp;
                __half g0 = __float2half_rn(v1x), g1 = __float2half_rn(v1y);
                __half2 hq; hq.x = g0; hq.y = g1;
                __half2 lq; lq.x = __float2half_rn(v1x - __half2float(g0));
                            lq.y = __float2half_rn(v1y - __half2float(g1));
                *(__half2*)&Chi[(size_t)(r + 8) * DM + c] = hq;
                *(__half2*)&Clo[(size_t)(r + 8) * DM + c] = lq;
            } else {
                float2 o0 = { v0x, v0y }, o1 = { v1x, v1y };
                *(float2*)&Cf[(size_t)r * DM + c] = o0;
                *(float2*)&Cf[(size_t)(r + 8) * DM + c] = o1;
            }
        }
    }
}

__global__ __launch_bounds__(256)
void qkv_tc_kernel(const float* __restrict__ bq, const float* __restrict__ bk,
                   const float* __restrict__ bv) {
    int z = blockIdx.z;
    const __nv_bfloat16* Bh = g_wthi + (size_t)z * DM * DM;
    const __nv_bfloat16* Bl = g_wtlo + (size_t)z * DM * DM;
    const float* bias = (z == 0) ? bq : (z == 1) ? bk : bv;
    __half* Chi = (z == 0) ? g_qhi : (z == 1) ? g_khi : g_vhi;
    __half* Clo = (z == 0) ? g_qlo : (z == 1) ? g_klo : g_vlo;
    gemm_tc_body<true>(g_xhi, g_xlo, Bh, Bl, bias, nullptr, Chi, Clo);
}

__global__ __launch_bounds__(256)
void oproj_tc_kernel(const float* __restrict__ bo, float* __restrict__ out) {
    gemm_tc_body<false>(g_ahi, g_alo, g_wthi + (size_t)3 * DM * DM,
                        g_wtlo + (size_t)3 * DM * DM, bo, out, nullptr, nullptr);
}

// ---------------- mma.sync flash attention -----------------------------------
// CTA: 128 queries of one (b,h); 8 warps x 16 rows; BN=64 keys/iter, 32 iters.
// QK^T: fp16 hi/lo 3-pass. P: fp16 (exact at p_max=1). PV: V fp16 hi/lo 2-pass.
#define KST 72   // fp16 elems per smem row (144 B: conflict-free b32 + ldmatrix)

__global__ __launch_bounds__(256)
void attn_tc_kernel() {
    __shared__ __half Kh[64][KST], Kl[64][KST], Vh[64][KST], Vl[64][KST];
    __shared__ float Ms[64];

    const int tid = threadIdx.x;
    const int lane = tid & 31, warp = tid >> 5;
    const int grp = lane >> 2, tig = lane & 3;
    const int qb = blockIdx.x, bh = blockIdx.y;
    const int b = bh >> 4, h = bh & 15;
    const int row0 = b * S_LEN + qb * 128;
    const int wm = warp * 16;

    // Q fragments (preloaded, fp16 hi/lo)
    uint32_t qh[4][4], ql[4][4];
    {
        const size_t r0 = (size_t)(row0 + wm + grp) * DM;
        const size_t r1 = r0 + 8 * DM;
#pragma unroll
        for (int kc = 0; kc < 4; ++kc) {
            int d = h * DH + kc * 16 + tig * 2;
            qh[kc][0] = *(const uint32_t*)&g_qhi[r0 + d];
            qh[kc][1] = *(const uint32_t*)&g_qhi[r1 + d];
            qh[kc][2] = *(const uint32_t*)&g_qhi[r0 + d + 8];
            qh[kc][3] = *(const uint32_t*)&g_qhi[r1 + d + 8];
            ql[kc][0] = *(const uint32_t*)&g_qlo[r0 + d];
            ql[kc][1] = *(const uint32_t*)&g_qlo[r1 + d];
            ql[kc][2] = *(const uint32_t*)&g_qlo[r0 + d + 8];
            ql[kc][3] = *(const uint32_t*)&g_qlo[r1 + d + 8];
        }
    }

    float o[8][4];
#pragma unroll
    for (int nt = 0; nt < 8; ++nt)
#pragma unroll
        for (int e = 0; e < 4; ++e) o[nt][e] = 0.0f;
    float m0 = -1e30f, m1 = -1e30f, l0 = 0.0f, l1 = 0.0f;

    // register-staged prefetch of K/V tiles
    uint4 pre[8];
    float pmask = 0.0f;
    const int pr = tid >> 3, pc = (tid & 7) * 8;          // row, col*8 (t=0 half)
    const int pr2 = (tid + 256) >> 3, pc2 = (tid & 7) * 8;
    {
        const size_t base = (size_t)(b * S_LEN) * DM + h * DH;
        pre[0] = *(const uint4*)&g_khi[base + (size_t)pr * DM + pc];
        pre[1] = *(const uint4*)&g_klo[base + (size_t)pr * DM + pc];
        pre[2] = *(const uint4*)&g_vhi[base + (size_t)pr * DM + pc];
        pre[3] = *(const uint4*)&g_vlo[base + (size_t)pr * DM + pc];
        pre[4] = *(const uint4*)&g_khi[base + (size_t)pr2 * DM + pc2];
        pre[5] = *(const uint4*)&g_klo[base + (size_t)pr2 * DM + pc2];
        pre[6] = *(const uint4*)&g_vhi[base + (size_t)pr2 * DM + pc2];
        pre[7] = *(const uint4*)&g_vlo[base + (size_t)pr2 * DM + pc2];
        if (tid < 64) pmask = g_maskadd[b * S_LEN + tid];
    }

    for (int kb = 0; kb < S_LEN / 64; ++kb) {
        __syncthreads();
        *(uint4*)&Kh[pr][pc] = pre[0];
        *(uint4*)&Kl[pr][pc] = pre[1];
        *(uint4*)&Vh[pr][pc] = pre[2];
        *(uint4*)&Vl[pr][pc] = pre[3];
        *(uint4*)&Kh[pr2][pc2] = pre[4];
        *(uint4*)&Kl[pr2][pc2] = pre[5];
        *(uint4*)&Vh[pr2][pc2] = pre[6];
        *(uint4*)&Vl[pr2][pc2] = pre[7];
        if (tid < 64) Ms[tid] = pmask;
        __syncthreads();

        if (kb + 1 < S_LEN / 64) {
            const size_t base = (size_t)(b * S_LEN + (kb + 1) * 64) * DM + h * DH;
            pre[0] = *(const uint4*)&g_khi[base + (size_t)pr * DM + pc];
            pre[1] = *(const uint4*)&g_klo[base + (size_t)pr * DM + pc];
            pre[2] = *(const uint4*)&g_vhi[base + (size_t)pr * DM + pc];
            pre[3] = *(const uint4*)&g_vlo[base + (size_t)pr * DM + pc];
            pre[4] = *(const uint4*)&g_khi[base + (size_t)pr2 * DM + pc2];
            pre[5] = *(const uint4*)&g_klo[base + (size_t)pr2 * DM + pc2];
            pre[6] = *(const uint4*)&g_vhi[base + (size_t)pr2 * DM + pc2];
            pre[7] = *(const uint4*)&g_vlo[base + (size_t)pr2 * DM + pc2];
            if (tid < 64) pmask = g_maskadd[b * S_LEN + (kb + 1) * 64 + tid];
        }

        // ---- S = Q K^T (3 passes) ----
        float s[8][4];
#pragma unroll
        for (int nt = 0; nt < 8; ++nt)
#pragma unroll
            for (int e = 0; e < 4; ++e) s[nt][e] = 0.0f;

#pragma unroll
        for (int kc = 0; kc < 4; ++kc) {
            const int kof = kc * 16 + tig * 2;
#pragma unroll
            for (int nt = 0; nt < 8; ++nt) {
                const int nr = nt * 8 + grp;
                uint32_t b0h = *(const uint32_t*)&Kh[nr][kof];
                uint32_t b1h = *(const uint32_t*)&Kh[nr][kof + 8];
                uint32_t b0l = *(const uint32_t*)&Kl[nr][kof];
                uint32_t b1l = *(const uint32_t*)&Kl[nr][kof + 8];
                MMA_F16(s[nt], qh[kc], b0h, b1h);
                MMA_F16(s[nt], ql[kc], b0h, b1h);
                MMA_F16(s[nt], qh[kc], b0l, b1l);
            }
        }

        // ---- mask + scale + online softmax ----
        float tmax0 = -1e30f, tmax1 = -1e30f;
#pragma unroll
        for (int nt = 0; nt < 8; ++nt) {
            float2 mv = *(const float2*)&Ms[nt * 8 + tig * 2];
            s[nt][0] = fmaf(s[nt][0], 0.125f, mv.x);
            s[nt][1] = fmaf(s[nt][1], 0.125f, mv.y);
            s[nt][2] = fmaf(s[nt][2], 0.125f, mv.x);
            s[nt][3] = fmaf(s[nt][3], 0.125f, mv.y);
            tmax0 = fmaxf(tmax0, fmaxf(s[nt][0], s[nt][1]));
            tmax1 = fmaxf(tmax1, fmaxf(s[nt][2], s[nt][3]));
        }
        tmax0 = fmaxf(tmax0, __shfl_xor_sync(0xffffffffu, tmax0, 1));
        tmax0 = fmaxf(tmax0, __shfl_xor_sync(0xffffffffu, tmax0, 2));
        tmax1 = fmaxf(tmax1, __shfl_xor_sync(0xffffffffu, tmax1, 1));
        tmax1 = fmaxf(tmax1, __shfl_xor_sync(0xffffffffu, tmax1, 2));

        float mn0 = fmaxf(m0, tmax0), mn1 = fmaxf(m1, tmax1);
        float al0 = __expf(m0 - mn0), al1 = __expf(m1 - mn1);
        m0 = mn0; m1 = mn1;

        float rs0 = 0.0f, rs1 = 0.0f;
        uint32_t pa[8], pb[8];
#pragma unroll
        for (int nt = 0; nt < 8; ++nt) {
            float p0 = __expf(s[nt][0] - mn0);
            float p1 = __expf(s[nt][1] - mn0);
            float p2 = __expf(s[nt][2] - mn1);
            float p3 = __expf(s[nt][3] - mn1);
            rs0 += p0 + p1; rs1 += p2 + p3;
            pa[nt] = pack_h2(p0, p1);
            pb[nt] = pack_h2(p2, p3);
        }
        rs0 += __shfl_xor_sync(0xffffffffu, rs0, 1);
        rs0 += __shfl_xor_sync(0xffffffffu, rs0, 2);
        rs1 += __shfl_xor_sync(0xffffffffu, rs1, 1);
        rs1 += __shfl_xor_sync(0xffffffffu, rs1, 2);
        l0 = l0 * al0 + rs0;
        l1 = l1 * al1 + rs1;

#pragma unroll
        for (int nt = 0; nt < 8; ++nt) {
            o[nt][0] *= al0; o[nt][1] *= al0;
            o[nt][2] *= al1; o[nt][3] *= al1;
        }

        // ---- O += P V  (V^T fragments via ldmatrix.trans; hi + lo) ----
        const int lrow = (lane & 7) + 8 * ((lane >> 3) & 1);
        const int lcol = 8 * (lane >> 4);
#pragma unroll
        for (int kc2 = 0; kc2 < 4; ++kc2) {
            uint32_t a[4] = { pa[kc2 * 2], pb[kc2 * 2], pa[kc2 * 2 + 1], pb[kc2 * 2 + 1] };
#pragma unroll
            for (int dp = 0; dp < 4; ++dp) {
                uint32_t v0, v1, v2, v3;
                uint32_t ad = smem_u32(&Vh[kc2 * 16 + lrow][dp * 16 + lcol]);
                LDMATRIX_X4_TRANS(v0, v1, v2, v3, ad);
                MMA_F16(o[dp * 2],     a, v0, v1);
                MMA_F16(o[dp * 2 + 1], a, v2, v3);
                ad = smem_u32(&Vl[kc2 * 16 + lrow][dp * 16 + lcol]);
                LDMATRIX_X4_TRANS(v0, v1, v2, v3, ad);
                MMA_F16(o[dp * 2],     a, v0, v1);
                MMA_F16(o[dp * 2 + 1], a, v2, v3);
            }
        }
    }

    // ---- epilogue: normalize, write bf16 hi/lo for oproj ----
    float inv0 = 1.0f / l0, inv1 = 1.0f / l1;
    const size_t r0 = (size_t)(row0 + wm + grp) * DM;
    const size_t r1 = r0 + 8 * DM;
#pragma unroll
    for (int nt = 0; nt < 8; ++nt) {
        int c = h * DH + nt * 8 + tig * 2;
        float x0 = o[nt][0] * inv0, x1 = o[nt][1] * inv0;
        float y0 = o[nt][2] * inv1, y1 = o[nt][3] * inv1;
        __nv_bfloat16 hx0 = __float2bfloat16(x0), hx1 = __float2bfloat16(x1);
        __nv_bfloat162 hp; hp.x = hx0; hp.y = hx1;
        __nv_bfloat162 lp;
        lp.x = __float2bfloat16(x0 - __bfloat162float(hx0));
        lp.y = __float2bfloat16(x1 - __bfloat162float(hx1));
        *(__nv_bfloat162*)&g_ahi[r0 + c] = hp;
        *(__nv_bfloat162*)&g_alo[r0 + c] = lp;
        __nv_bfloat16 hy0 = __float2bfloat16(y0), hy1 = __float2bfloat16(y1);
        __nv_bfloat162 hq; hq.x = hy0; hq.y = hy1;
        __nv_bfloat162 lq;
        lq.x = __float2bfloat16(y0 - __bfloat162float(hy0));
        lq.y = __float2bfloat16(y1 - __bfloat162float(hy1));
        *(__nv_bfloat162*)&g_ahi[r1 + c] = hq;
        *(__nv_bfloat162*)&g_alo[r1 + c] = lq;
    }
}

// ---------------- launch -----------------------------------------------------
extern "C" void kernel_launch(void* const* d_in, const int* in_sizes, int n_in,
                              void* d_out, int out_size) {
    const float* x  = (const float*)d_in[0];
    const void*  mk = d_in[1];
    const float* Wq = (const float*)d_in[2];
    const float* bq = (const float*)d_in[3];
    const float* Wk = (const float*)d_in[4];
    const float* bk = (const float*)d_in[5];
    const float* Wv = (const float*)d_in[6];
    const float* bv = (const float*)d_in[7];
    const float* Wo = (const float*)d_in[8];
    const float* bo = (const float*)d_in[9];
    float* out = (float*)d_out;

    detect_mask_kernel<<<1, 256>>>((const unsigned char*)mk);
    expand_mask_kernel<<<(B_SZ * S_LEN + 255) / 256, 256>>>(mk);

    prep_w_kernel<<<dim3(32, 32, 4), dim3(32, 8)>>>(Wq, Wk, Wv, Wo);
    conv_x_kernel<<<(MROWS * DM + 255) / 256, 256>>>(x);

    qkv_tc_kernel<<<dim3(DM / 128, MROWS / 128, 3), 256>>>(bq, bk, bv);

    attn_tc_kernel<<<dim3(S_LEN / 128, B_SZ * NH), 256>>>();

    oproj_tc_kernel<<<dim3(DM / 128, MROWS / 128), 256>>>(bo, out);
}

// round 7
// speedup vs baseline: 3.5221x; 1.1490x over previous
#include <cuda_runtime.h>
#include <cuda_bf16.h>
#include <cuda_fp16.h>
#include <cstdint>

#define S_LEN 2048
#define B_SZ 4
#define NH 16
#define DH 64
#define DM 1024
#define MROWS (B_SZ * S_LEN)   // 8192
#define GK 1024

// ---------------- scratch (device globals; device-code references ONLY) -----
__device__ float g_maskadd[B_SZ * S_LEN];
__device__ int   g_mask_mode;

__device__ __nv_bfloat16 g_xhi[MROWS * DM];
__device__ __nv_bfloat16 g_xlo[MROWS * DM];
__device__ __nv_bfloat16 g_ahi[MROWS * DM];
__device__ __nv_bfloat16 g_alo[MROWS * DM];
__device__ __nv_bfloat16 g_wthi[4 * DM * DM];   // W^T, [N][K] K-major
__device__ __nv_bfloat16 g_wtlo[4 * DM * DM];

__device__ __half g_qhi[MROWS * DM];
__device__ __half g_qlo[MROWS * DM];
__device__ __half g_khi[MROWS * DM];
__device__ __half g_klo[MROWS * DM];
__device__ __half g_vhi[MROWS * DM];
__device__ __half g_vlo[MROWS * DM];

// ---------------- PTX helpers ------------------------------------------------
__device__ __forceinline__ uint32_t smem_u32(const void* p) {
    uint32_t a;
    asm("{ .reg .u64 t; cvta.to.shared.u64 t, %1; cvt.u32.u64 %0, t; }"
        : "=r"(a) : "l"(p));
    return a;
}

#define MMA_BF16(c, a, b0, b1)                                              \
    asm volatile("mma.sync.aligned.m16n8k16.row.col.f32.bf16.bf16.f32 "     \
                 "{%0,%1,%2,%3}, {%4,%5,%6,%7}, {%8,%9}, {%0,%1,%2,%3};"    \
                 : "+f"((c)[0]), "+f"((c)[1]), "+f"((c)[2]), "+f"((c)[3])   \
                 : "r"((a)[0]), "r"((a)[1]), "r"((a)[2]), "r"((a)[3]),      \
                   "r"(b0), "r"(b1))

#define MMA_F16(c, a, b0, b1)                                               \
    asm volatile("mma.sync.aligned.m16n8k16.row.col.f32.f16.f16.f32 "       \
                 "{%0,%1,%2,%3}, {%4,%5,%6,%7}, {%8,%9}, {%0,%1,%2,%3};"    \
                 : "+f"((c)[0]), "+f"((c)[1]), "+f"((c)[2]), "+f"((c)[3])   \
                 : "r"((a)[0]), "r"((a)[1]), "r"((a)[2]), "r"((a)[3]),      \
                   "r"(b0), "r"(b1))

#define LDMATRIX_X4_TRANS(r0, r1, r2, r3, addr)                             \
    asm volatile("ldmatrix.sync.aligned.m8n8.x4.trans.shared.b16 "          \
                 "{%0,%1,%2,%3}, [%4];"                                     \
                 : "=r"(r0), "=r"(r1), "=r"(r2), "=r"(r3) : "r"(addr))

__device__ __forceinline__ void cpa16(uint32_t dst, const void* src) {
    asm volatile("cp.async.ca.shared.global [%0], [%1], 16;"
                 :: "r"(dst), "l"(src));
}
#define CP_COMMIT()  asm volatile("cp.async.commit_group;" ::: "memory")
#define CP_WAIT(n)   asm volatile("cp.async.wait_group %0;" :: "n"(n) : "memory")

__device__ __forceinline__ uint32_t pack_h2(float a, float b) {
    __half2 h = __floats2half2_rn(a, b);
    return *(uint32_t*)&h;
}

// ---------------- mask dtype detection --------------------------------------
__global__ void detect_mask_kernel(const unsigned char* __restrict__ m) {
    __shared__ int f_nonbin, f_off;
    int tid = threadIdx.x;
    if (tid == 0) { f_nonbin = 0; f_off = 0; }
    __syncthreads();
    int loc_nb = 0, loc_off = 0;
    for (int i = tid; i < B_SZ * S_LEN; i += blockDim.x) {
        unsigned char v = m[i];
        if (v > 1) loc_nb = 1;
        if ((i & 3) && v) loc_off = 1;
    }
    if (loc_nb) atomicOr(&f_nonbin, 1);
    if (loc_off) atomicOr(&f_off, 1);
    __syncthreads();
    if (tid == 0) g_mask_mode = f_nonbin ? 2 : (f_off ? 1 : 0);
}

__global__ void expand_mask_kernel(const void* __restrict__ mraw) {
    int i = blockIdx.x * blockDim.x + threadIdx.x;
    if (i >= B_SZ * S_LEN) return;
    int mode = g_mask_mode;
    bool t;
    if (mode == 0)      t = ((const int*)mraw)[i] != 0;
    else if (mode == 1) t = ((const unsigned char*)mraw)[i] != 0;
    else                t = ((const float*)mraw)[i] != 0.0f;
    g_maskadd[i] = t ? 0.0f : -1e30f;
}

// ---------------- fp32 -> bf16 hi/lo (x) -------------------------------------
__global__ __launch_bounds__(256)
void conv_x_kernel(const float* __restrict__ src) {
    int i = blockIdx.x * blockDim.x + threadIdx.x;
    if (i >= MROWS * DM) return;
    float v = src[i];
    __nv_bfloat16 h = __float2bfloat16(v);
    g_xhi[i] = h;
    g_xlo[i] = __float2bfloat16(v - __bfloat162float(h));
}

// ---------------- W transpose + bf16 hi/lo -----------------------------------
__global__ __launch_bounds__(256)
void prep_w_kernel(const float* __restrict__ Wq, const float* __restrict__ Wk,
                   const float* __restrict__ Wv, const float* __restrict__ Wo) {
    __shared__ float t[32][33];
    int z = blockIdx.z;
    const float* W = (z == 0) ? Wq : (z == 1) ? Wk : (z == 2) ? Wv : Wo;
    __nv_bfloat16* oh = g_wthi + (size_t)z * DM * DM;
    __nv_bfloat16* ol = g_wtlo + (size_t)z * DM * DM;
    int x0 = blockIdx.x * 32, y0 = blockIdx.y * 32;
    int tx = threadIdx.x, ty = threadIdx.y;   // (32, 8)
#pragma unroll
    for (int j = 0; j < 4; ++j)
        t[ty + j * 8][tx] = W[(size_t)(y0 + ty + j * 8) * DM + x0 + tx];
    __syncthreads();
#pragma unroll
    for (int j = 0; j < 4; ++j) {
        float v = t[tx][ty + j * 8];
        __nv_bfloat16 h = __float2bfloat16(v);
        size_t o = (size_t)(x0 + ty + j * 8) * DM + y0 + tx;
        oh[o] = h;
        ol[o] = __float2bfloat16(v - __bfloat162float(h));
    }
}

// ---------------- mma.sync bf16x3 GEMM with cp.async double buffer -----------
// C[8192 x 1024] = A @ W^T + bias.  CTA 128x128, BK=32, 8 warps (4m x 2n).
// 2-stage cp.async pipeline: stage kt+1 loads overlap stage kt compute.
#define AS_STRIDE 40
#define SEG (128 * AS_STRIDE)          // elems per sub-tile
#define SEGB (SEG * 2)                 // bytes per sub-tile
#define STAGEB (4 * SEGB)              // bytes per stage (Ah,Al,Bh,Bl)
#define GEMM_SMEM (2 * STAGEB)         // 81920 bytes

template <bool HALF_OUT>
__device__ __forceinline__ void gemm_tc_body(const __nv_bfloat16* __restrict__ Ahi,
                                             const __nv_bfloat16* __restrict__ Alo,
                                             const __nv_bfloat16* __restrict__ Bhi,
                                             const __nv_bfloat16* __restrict__ Blo,
                                             const float* __restrict__ bias,
                                             float* __restrict__ Cf,
                                             __half* __restrict__ Chi,
                                             __half* __restrict__ Clo) {
    extern __shared__ __nv_bfloat16 smb[];

    const int tid  = threadIdx.x;
    const int lane = tid & 31, warp = tid >> 5;
    const int wm = (warp & 3) * 32;
    const int wn = (warp >> 2) * 64;
    const int m0 = blockIdx.y * 128;
    const int n0 = blockIdx.x * 128;
    const int grp = lane >> 2;
    const int tig = lane & 3;

    const uint32_t sb = smem_u32(smb);
    // per-thread load slots: 2 x (row, quad)
    const int r0l = tid >> 2, q0l = tid & 3;
    const int r1l = (tid + 256) >> 2, q1l = q0l;
    const uint32_t soff0 = (uint32_t)(r0l * AS_STRIDE + q0l * 8) * 2;
    const uint32_t soff1 = (uint32_t)(r1l * AS_STRIDE + q1l * 8) * 2;

    float acc[2][8][4];
#pragma unroll
    for (int mt = 0; mt < 2; ++mt)
#pragma unroll
        for (int nt = 0; nt < 8; ++nt)
#pragma unroll
            for (int e = 0; e < 4; ++e) acc[mt][nt][e] = 0.0f;

    // ---- async tile loader for step kt into stage s ----
    auto load_stage = [&](int kt, int s) {
        const uint32_t base = sb + (uint32_t)s * STAGEB;
        const size_t ga0 = (size_t)(m0 + r0l) * GK + kt * 32 + q0l * 8;
        const size_t ga1 = (size_t)(m0 + r1l) * GK + kt * 32 + q1l * 8;
        const size_t gb0 = (size_t)(n0 + r0l) * GK + kt * 32 + q0l * 8;
        const size_t gb1 = (size_t)(n0 + r1l) * GK + kt * 32 + q1l * 8;
        cpa16(base + soff0,            &Ahi[ga0]);
        cpa16(base + SEGB + soff0,     &Alo[ga0]);
        cpa16(base + 2 * SEGB + soff0, &Bhi[gb0]);
        cpa16(base + 3 * SEGB + soff0, &Blo[gb0]);
        cpa16(base + soff1,            &Ahi[ga1]);
        cpa16(base + SEGB + soff1,     &Alo[ga1]);
        cpa16(base + 2 * SEGB + soff1, &Bhi[gb1]);
        cpa16(base + 3 * SEGB + soff1, &Blo[gb1]);
    };

    load_stage(0, 0);
    CP_COMMIT();

    for (int kt = 0; kt < GK / 32; ++kt) {
        const int cur = kt & 1;
        if (kt + 1 < GK / 32) {
            load_stage(kt + 1, cur ^ 1);
            CP_COMMIT();
            CP_WAIT(1);
        } else {
            CP_WAIT(0);
        }
        __syncthreads();

        const __nv_bfloat16* Ah = smb + (size_t)cur * 4 * SEG;
        const __nv_bfloat16* Al = Ah + SEG;
        const __nv_bfloat16* Bh = Ah + 2 * SEG;
        const __nv_bfloat16* Bl = Ah + 3 * SEG;

#pragma unroll
        for (int ks = 0; ks < 2; ++ks) {
            const int kof = ks * 16 + tig * 2;
            uint32_t bh[8][2], bl[8][2];
#pragma unroll
            for (int nt = 0; nt < 8; ++nt) {
                const int nr = wn + nt * 8 + grp;
                bh[nt][0] = *(const uint32_t*)&Bh[nr * AS_STRIDE + kof];
                bh[nt][1] = *(const uint32_t*)&Bh[nr * AS_STRIDE + kof + 8];
                bl[nt][0] = *(const uint32_t*)&Bl[nr * AS_STRIDE + kof];
                bl[nt][1] = *(const uint32_t*)&Bl[nr * AS_STRIDE + kof + 8];
            }
#pragma unroll
            for (int mt = 0; mt < 2; ++mt) {
                const int mr = wm + mt * 16 + grp;
                uint32_t a_h[4], a_l[4];
                a_h[0] = *(const uint32_t*)&Ah[mr * AS_STRIDE + kof];
                a_h[1] = *(const uint32_t*)&Ah[(mr + 8) * AS_STRIDE + kof];
                a_h[2] = *(const uint32_t*)&Ah[mr * AS_STRIDE + kof + 8];
                a_h[3] = *(const uint32_t*)&Ah[(mr + 8) * AS_STRIDE + kof + 8];
                a_l[0] = *(const uint32_t*)&Al[mr * AS_STRIDE + kof];
                a_l[1] = *(const uint32_t*)&Al[(mr + 8) * AS_STRIDE + kof];
                a_l[2] = *(const uint32_t*)&Al[mr * AS_STRIDE + kof + 8];
                a_l[3] = *(const uint32_t*)&Al[(mr + 8) * AS_STRIDE + kof + 8];
#pragma unroll
                for (int nt = 0; nt < 8; ++nt) {
                    MMA_BF16(acc[mt][nt], a_h, bh[nt][0], bh[nt][1]);
                    MMA_BF16(acc[mt][nt], a_l, bh[nt][0], bh[nt][1]);
                    MMA_BF16(acc[mt][nt], a_h, bl[nt][0], bl[nt][1]);
                }
            }
        }
        __syncthreads();   // all warps done reading stage cur before it is refilled
    }

#pragma unroll
    for (int mt = 0; mt < 2; ++mt) {
#pragma unroll
        for (int nt = 0; nt < 8; ++nt) {
            int r = m0 + wm + mt * 16 + grp;
            int c = n0 + wn + nt * 8 + tig * 2;
            float2 bb = *(const float2*)&bias[c];
            float v0x = acc[mt][nt][0] + bb.x, v0y = acc[mt][nt][1] + bb.y;
            float v1x = acc[mt][nt][2] + bb.x, v1y = acc[mt][nt][3] + bb.y;
            if constexpr (HALF_OUT) {
                __half h0 = __float2half_rn(v0x), h1 = __float2half_rn(v0y);
                __half2 hp; hp.x = h0; hp.y = h1;
                __half2 lp; lp.x = __float2half_rn(v0x - __half2float(h0));
                            lp.y = __float2half_rn(v0y - __half2float(h1));
                *(__half2*)&Chi[(size_t)r * DM + c] = hp;
                *(__half2*)&Clo[(size_t)r * DM + c] = lp;
                __half g0 = __float2half_rn(v1x), g1 = __float2half_rn(v1y);
                __half2 hq; hq.x = g0; hq.y = g1;
                __half2 lq; lq.x = __float2half_rn(v1x - __half2float(g0));
                            lq.y = __float2half_rn(v1y - __half2float(g1));
                *(__half2*)&Chi[(size_t)(r + 8) * DM + c] = hq;
                *(__half2*)&Clo[(size_t)(r + 8) * DM + c] = lq;
            } else {
                float2 o0 = { v0x, v0y }, o1 = { v1x, v1y };
                *(float2*)&Cf[(size_t)r * DM + c] = o0;
                *(float2*)&Cf[(size_t)(r + 8) * DM + c] = o1;
            }
        }
    }
}

__global__ __launch_bounds__(256)
void qkv_tc_kernel(const float* __restrict__ bq, const float* __restrict__ bk,
                   const float* __restrict__ bv) {
    int z = blockIdx.z;
    const __nv_bfloat16* Bh = g_wthi + (size_t)z * DM * DM;
    const __nv_bfloat16* Bl = g_wtlo + (size_t)z * DM * DM;
    const float* bias = (z == 0) ? bq : (z == 1) ? bk : bv;
    __half* Chi = (z == 0) ? g_qhi : (z == 1) ? g_khi : g_vhi;
    __half* Clo = (z == 0) ? g_qlo : (z == 1) ? g_klo : g_vlo;
    gemm_tc_body<true>(g_xhi, g_xlo, Bh, Bl, bias, nullptr, Chi, Clo);
}

__global__ __launch_bounds__(256)
void oproj_tc_kernel(const float* __restrict__ bo, float* __restrict__ out) {
    gemm_tc_body<false>(g_ahi, g_alo, g_wthi + (size_t)3 * DM * DM,
                        g_wtlo + (size_t)3 * DM * DM, bo, out, nullptr, nullptr);
}

// ---------------- mma.sync flash attention (proven R6 code) ------------------
#define KST 72

__global__ __launch_bounds__(256)
void attn_tc_kernel() {
    __shared__ __half Kh[64][KST], Kl[64][KST], Vh[64][KST], Vl[64][KST];
    __shared__ float Ms[64];

    const int tid = threadIdx.x;
    const int lane = tid & 31, warp = tid >> 5;
    const int grp = lane >> 2, tig = lane & 3;
    const int qb = blockIdx.x, bh = blockIdx.y;
    const int b = bh >> 4, h = bh & 15;
    const int row0 = b * S_LEN + qb * 128;
    const int wm = warp * 16;

    uint32_t qh[4][4], ql[4][4];
    {
        const size_t r0 = (size_t)(row0 + wm + grp) * DM;
        const size_t r1 = r0 + 8 * DM;
#pragma unroll
        for (int kc = 0; kc < 4; ++kc) {
            int d = h * DH + kc * 16 + tig * 2;
            qh[kc][0] = *(const uint32_t*)&g_qhi[r0 + d];
            qh[kc][1] = *(const uint32_t*)&g_qhi[r1 + d];
            qh[kc][2] = *(const uint32_t*)&g_qhi[r0 + d + 8];
            qh[kc][3] = *(const uint32_t*)&g_qhi[r1 + d + 8];
            ql[kc][0] = *(const uint32_t*)&g_qlo[r0 + d];
            ql[kc][1] = *(const uint32_t*)&g_qlo[r1 + d];
            ql[kc][2] = *(const uint32_t*)&g_qlo[r0 + d + 8];
            ql[kc][3] = *(const uint32_t*)&g_qlo[r1 + d + 8];
        }
    }

    float o[8][4];
#pragma unroll
    for (int nt = 0; nt < 8; ++nt)
#pragma unroll
        for (int e = 0; e < 4; ++e) o[nt][e] = 0.0f;
    float m0 = -1e30f, m1 = -1e30f, l0 = 0.0f, l1 = 0.0f;

    uint4 pre[8];
    float pmask = 0.0f;
    const int pr = tid >> 3, pc = (tid & 7) * 8;
    const int pr2 = (tid + 256) >> 3, pc2 = (tid & 7) * 8;
    {
        const size_t base = (size_t)(b * S_LEN) * DM + h * DH;
        pre[0] = *(const uint4*)&g_khi[base + (size_t)pr * DM + pc];
        pre[1] = *(const uint4*)&g_klo[base + (size_t)pr * DM + pc];
        pre[2] = *(const uint4*)&g_vhi[base + (size_t)pr * DM + pc];
        pre[3] = *(const uint4*)&g_vlo[base + (size_t)pr * DM + pc];
        pre[4] = *(const uint4*)&g_khi[base + (size_t)pr2 * DM + pc2];
        pre[5] = *(const uint4*)&g_klo[base + (size_t)pr2 * DM + pc2];
        pre[6] = *(const uint4*)&g_vhi[base + (size_t)pr2 * DM + pc2];
        pre[7] = *(const uint4*)&g_vlo[base + (size_t)pr2 * DM + pc2];
        if (tid < 64) pmask = g_maskadd[b * S_LEN + tid];
    }

    for (int kb = 0; kb < S_LEN / 64; ++kb) {
        __syncthreads();
        *(uint4*)&Kh[pr][pc] = pre[0];
        *(uint4*)&Kl[pr][pc] = pre[1];
        *(uint4*)&Vh[pr][pc] = pre[2];
        *(uint4*)&Vl[pr][pc] = pre[3];
        *(uint4*)&Kh[pr2][pc2] = pre[4];
        *(uint4*)&Kl[pr2][pc2] = pre[5];
        *(uint4*)&Vh[pr2][pc2] = pre[6];
        *(uint4*)&Vl[pr2][pc2] = pre[7];
        if (tid < 64) Ms[tid] = pmask;
        __syncthreads();

        if (kb + 1 < S_LEN / 64) {
            const size_t base = (size_t)(b * S_LEN + (kb + 1) * 64) * DM + h * DH;
            pre[0] = *(const uint4*)&g_khi[base + (size_t)pr * DM + pc];
            pre[1] = *(const uint4*)&g_klo[base + (size_t)pr * DM + pc];
            pre[2] = *(const uint4*)&g_vhi[base + (size_t)pr * DM + pc];
            pre[3] = *(const uint4*)&g_vlo[base + (size_t)pr * DM + pc];
            pre[4] = *(const uint4*)&g_khi[base + (size_t)pr2 * DM + pc2];
            pre[5] = *(const uint4*)&g_klo[base + (size_t)pr2 * DM + pc2];
            pre[6] = *(const uint4*)&g_vhi[base + (size_t)pr2 * DM + pc2];
            pre[7] = *(const uint4*)&g_vlo[base + (size_t)pr2 * DM + pc2];
            if (tid < 64) pmask = g_maskadd[b * S_LEN + (kb + 1) * 64 + tid];
        }

        float s[8][4];
#pragma unroll
        for (int nt = 0; nt < 8; ++nt)
#pragma unroll
            for (int e = 0; e < 4; ++e) s[nt][e] = 0.0f;

#pragma unroll
        for (int kc = 0; kc < 4; ++kc) {
            const int kof = kc * 16 + tig * 2;
#pragma unroll
            for (int nt = 0; nt < 8; ++nt) {
                const int nr = nt * 8 + grp;
                uint32_t b0h = *(const uint32_t*)&Kh[nr][kof];
                uint32_t b1h = *(const uint32_t*)&Kh[nr][kof + 8];
                uint32_t b0l = *(const uint32_t*)&Kl[nr][kof];
                uint32_t b1l = *(const uint32_t*)&Kl[nr][kof + 8];
                MMA_F16(s[nt], qh[kc], b0h, b1h);
                MMA_F16(s[nt], ql[kc], b0h, b1h);
                MMA_F16(s[nt], qh[kc], b0l, b1l);
            }
        }

        float tmax0 = -1e30f, tmax1 = -1e30f;
#pragma unroll
        for (int nt = 0; nt < 8; ++nt) {
            float2 mv = *(const float2*)&Ms[nt * 8 + tig * 2];
            s[nt][0] = fmaf(s[nt][0], 0.125f, mv.x);
            s[nt][1] = fmaf(s[nt][1], 0.125f, mv.y);
            s[nt][2] = fmaf(s[nt][2], 0.125f, mv.x);
            s[nt][3] = fmaf(s[nt][3], 0.125f, mv.y);
            tmax0 = fmaxf(tmax0, fmaxf(s[nt][0], s[nt][1]));
            tmax1 = fmaxf(tmax1, fmaxf(s[nt][2], s[nt][3]));
        }
        tmax0 = fmaxf(tmax0, __shfl_xor_sync(0xffffffffu, tmax0, 1));
        tmax0 = fmaxf(tmax0, __shfl_xor_sync(0xffffffffu, tmax0, 2));
        tmax1 = fmaxf(tmax1, __shfl_xor_sync(0xffffffffu, tmax1, 1));
        tmax1 = fmaxf(tmax1, __shfl_xor_sync(0xffffffffu, tmax1, 2));

        float mn0 = fmaxf(m0, tmax0), mn1 = fmaxf(m1, tmax1);
        float al0 = __expf(m0 - mn0), al1 = __expf(m1 - mn1);
        m0 = mn0; m1 = mn1;

        float rs0 = 0.0f, rs1 = 0.0f;
        uint32_t pa[8], pb[8];
#pragma unroll
        for (int nt = 0; nt < 8; ++nt) {
            float p0 = __expf(s[nt][0] - mn0);
            float p1 = __expf(s[nt][1] - mn0);
            float p2 = __expf(s[nt][2] - mn1);
            float p3 = __expf(s[nt][3] - mn1);
            rs0 += p0 + p1; rs1 += p2 + p3;
            pa[nt] = pack_h2(p0, p1);
            pb[nt] = pack_h2(p2, p3);
        }
        rs0 += __shfl_xor_sync(0xffffffffu, rs0, 1);
        rs0 += __shfl_xor_sync(0xffffffffu, rs0, 2);
        rs1 += __shfl_xor_sync(0xffffffffu, rs1, 1);
        rs1 += __shfl_xor_sync(0xffffffffu, rs1, 2);
        l0 = l0 * al0 + rs0;
        l1 = l1 * al1 + rs1;

#pragma unroll
        for (int nt = 0; nt < 8; ++nt) {
            o[nt][0] *= al0; o[nt][1] *= al0;
            o[nt][2] *= al1; o[nt][3] *= al1;
        }

        const int lrow = (lane & 7) + 8 * ((lane >> 3) & 1);
        const int lcol = 8 * (lane >> 4);
#pragma unroll
        for (int kc2 = 0; kc2 < 4; ++kc2) {
            uint32_t a[4] = { pa[kc2 * 2], pb[kc2 * 2], pa[kc2 * 2 + 1], pb[kc2 * 2 + 1] };
#pragma unroll
            for (int dp = 0; dp < 4; ++dp) {
                uint32_t v0, v1, v2, v3;
                uint32_t ad = smem_u32(&Vh[kc2 * 16 + lrow][dp * 16 + lcol]);
                LDMATRIX_X4_TRANS(v0, v1, v2, v3, ad);
                MMA_F16(o[dp * 2],     a, v0, v1);
                MMA_F16(o[dp * 2 + 1], a, v2, v3);
                ad = smem_u32(&Vl[kc2 * 16 + lrow][dp * 16 + lcol]);
                LDMATRIX_X4_TRANS(v0, v1, v2, v3, ad);
                MMA_F16(o[dp * 2],     a, v0, v1);
                MMA_F16(o[dp * 2 + 1], a, v2, v3);
            }
        }
    }

    float inv0 = 1.0f / l0, inv1 = 1.0f / l1;
    const size_t r0 = (size_t)(row0 + wm + grp) * DM;
    const size_t r1 = r0 + 8 * DM;
#pragma unroll
    for (int nt = 0; nt < 8; ++nt) {
        int c = h * DH + nt * 8 + tig * 2;
        float x0 = o[nt][0] * inv0, x1 = o[nt][1] * inv0;
        float y0 = o[nt][2] * inv1, y1 = o[nt][3] * inv1;
        __nv_bfloat16 hx0 = __float2bfloat16(x0), hx1 = __float2bfloat16(x1);
        __nv_bfloat162 hp; hp.x = hx0; hp.y = hx1;
        __nv_bfloat162 lp;
        lp.x = __float2bfloat16(x0 - __bfloat162float(hx0));
        lp.y = __float2bfloat16(x1 - __bfloat162float(hx1));
        *(__nv_bfloat162*)&g_ahi[r0 + c] = hp;
        *(__nv_bfloat162*)&g_alo[r0 + c] = lp;
        __nv_bfloat16 hy0 = __float2bfloat16(y0), hy1 = __float2bfloat16(y1);
        __nv_bfloat162 hq; hq.x = hy0; hq.y = hy1;
        __nv_bfloat162 lq;
        lq.x = __float2bfloat16(y0 - __bfloat162float(hy0));
        lq.y = __float2bfloat16(y1 - __bfloat162float(hy1));
        *(__nv_bfloat162*)&g_ahi[r1 + c] = hq;
        *(__nv_bfloat162*)&g_alo[r1 + c] = lq;
    }
}

// ---------------- launch -----------------------------------------------------
extern "C" void kernel_launch(void* const* d_in, const int* in_sizes, int n_in,
                              void* d_out, int out_size) {
    const float* x  = (const float*)d_in[0];
    const void*  mk = d_in[1];
    const float* Wq = (const float*)d_in[2];
    const float* bq = (const float*)d_in[3];
    const float* Wk = (const float*)d_in[4];
    const float* bk = (const float*)d_in[5];
    const float* Wv = (const float*)d_in[6];
    const float* bv = (const float*)d_in[7];
    const float* Wo = (const float*)d_in[8];
    const float* bo = (const float*)d_in[9];
    float* out = (float*)d_out;

    detect_mask_kernel<<<1, 256>>>((const unsigned char*)mk);
    expand_mask_kernel<<<(B_SZ * S_LEN + 255) / 256, 256>>>(mk);

    prep_w_kernel<<<dim3(32, 32, 4), dim3(32, 8)>>>(Wq, Wk, Wv, Wo);
    conv_x_kernel<<<(MROWS * DM + 255) / 256, 256>>>(x);

    cudaFuncSetAttribute(qkv_tc_kernel,
                         cudaFuncAttributeMaxDynamicSharedMemorySize, GEMM_SMEM);
    cudaFuncSetAttribute(oproj_tc_kernel,
                         cudaFuncAttributeMaxDynamicSharedMemorySize, GEMM_SMEM);

    qkv_tc_kernel<<<dim3(DM / 128, MROWS / 128, 3), 256, GEMM_SMEM>>>(bq, bk, bv);

    attn_tc_kernel<<<dim3(S_LEN / 128, B_SZ * NH), 256>>>();

    oproj_tc_kernel<<<dim3(DM / 128, MROWS / 128), 256, GEMM_SMEM>>>(bo, out);
}

// round 8
// speedup vs baseline: 4.2781x; 1.2147x over previous
#include <cuda_runtime.h>
#include <cuda_bf16.h>
#include <cuda_fp16.h>
#include <cstdint>

#define S_LEN 2048
#define B_SZ 4
#define NH 16
#define DH 64
#define DM 1024
#define MROWS (B_SZ * S_LEN)   // 8192
#define GK 1024

// ---------------- scratch (device globals; device-code references ONLY) -----
__device__ int   g_mask_mode;
__device__ int   g_kcnt[B_SZ];
__device__ int   g_kidx[B_SZ * S_LEN];
__device__ float g_cmask[B_SZ * S_LEN];

__device__ __nv_bfloat16 g_xhi[MROWS * DM];
__device__ __nv_bfloat16 g_xlo[MROWS * DM];
__device__ __nv_bfloat16 g_ahi[MROWS * DM];
__device__ __nv_bfloat16 g_alo[MROWS * DM];
__device__ __nv_bfloat16 g_wthi[4 * DM * DM];   // W^T, [N][K] K-major
__device__ __nv_bfloat16 g_wtlo[4 * DM * DM];

__device__ __half g_qhi[MROWS * DM];
__device__ __half g_qlo[MROWS * DM];
__device__ __half g_khi[MROWS * DM];
__device__ __half g_klo[MROWS * DM];
__device__ __half g_vhi[MROWS * DM];
__device__ __half g_vlo[MROWS * DM];
// compacted (attended-only) K/V
__device__ __half g_ckhi[MROWS * DM];
__device__ __half g_cklo[MROWS * DM];
__device__ __half g_cvhi[MROWS * DM];
__device__ __half g_cvlo[MROWS * DM];

// ---------------- PTX helpers ------------------------------------------------
__device__ __forceinline__ uint32_t smem_u32(const void* p) {
    uint32_t a;
    asm("{ .reg .u64 t; cvta.to.shared.u64 t, %1; cvt.u32.u64 %0, t; }"
        : "=r"(a) : "l"(p));
    return a;
}

#define MMA_BF16(c, a, b0, b1)                                              \
    asm volatile("mma.sync.aligned.m16n8k16.row.col.f32.bf16.bf16.f32 "     \
                 "{%0,%1,%2,%3}, {%4,%5,%6,%7}, {%8,%9}, {%0,%1,%2,%3};"    \
                 : "+f"((c)[0]), "+f"((c)[1]), "+f"((c)[2]), "+f"((c)[3])   \
                 : "r"((a)[0]), "r"((a)[1]), "r"((a)[2]), "r"((a)[3]),      \
                   "r"(b0), "r"(b1))

#define MMA_F16(c, a, b0, b1)                                               \
    asm volatile("mma.sync.aligned.m16n8k16.row.col.f32.f16.f16.f32 "       \
                 "{%0,%1,%2,%3}, {%4,%5,%6,%7}, {%8,%9}, {%0,%1,%2,%3};"    \
                 : "+f"((c)[0]), "+f"((c)[1]), "+f"((c)[2]), "+f"((c)[3])   \
                 : "r"((a)[0]), "r"((a)[1]), "r"((a)[2]), "r"((a)[3]),      \
                   "r"(b0), "r"(b1))

#define LDMATRIX_X4_TRANS(r0, r1, r2, r3, addr)                             \
    asm volatile("ldmatrix.sync.aligned.m8n8.x4.trans.shared.b16 "          \
                 "{%0,%1,%2,%3}, [%4];"                                     \
                 : "=r"(r0), "=r"(r1), "=r"(r2), "=r"(r3) : "r"(addr))

__device__ __forceinline__ void cpa16(uint32_t dst, const void* src) {
    asm volatile("cp.async.ca.shared.global [%0], [%1], 16;"
                 :: "r"(dst), "l"(src));
}
#define CP_COMMIT()  asm volatile("cp.async.commit_group;" ::: "memory")
#define CP_WAIT(n)   asm volatile("cp.async.wait_group %0;" :: "n"(n) : "memory")

__device__ __forceinline__ uint32_t pack_h2(float a, float b) {
    __half2 h = __floats2half2_rn(a, b);
    return *(uint32_t*)&h;
}

__device__ __forceinline__ bool mask_true(const void* mraw, int i, int mode) {
    if (mode == 0)      return ((const int*)mraw)[i] != 0;
    else if (mode == 1) return ((const unsigned char*)mraw)[i] != 0;
    else                return ((const float*)mraw)[i] != 0.0f;
}

// ---------------- mask dtype detection --------------------------------------
__global__ void detect_mask_kernel(const unsigned char* __restrict__ m) {
    __shared__ int f_nonbin, f_off;
    int tid = threadIdx.x;
    if (tid == 0) { f_nonbin = 0; f_off = 0; }
    __syncthreads();
    int loc_nb = 0, loc_off = 0;
    for (int i = tid; i < B_SZ * S_LEN; i += blockDim.x) {
        unsigned char v = m[i];
        if (v > 1) loc_nb = 1;
        if ((i & 3) && v) loc_off = 1;
    }
    if (loc_nb) atomicOr(&f_nonbin, 1);
    if (loc_off) atomicOr(&f_off, 1);
    __syncthreads();
    if (tid == 0) g_mask_mode = f_nonbin ? 2 : (f_off ? 1 : 0);
}

// ---------------- per-batch mask prefix scan -> attended key indices ---------
__global__ __launch_bounds__(256)
void scan_mask_kernel(const void* __restrict__ mraw) {
    __shared__ int ssum[256];
    const int b = blockIdx.x;
    const int tid = threadIdx.x;
    const int mode = g_mask_mode;
    int flags[8], loc = 0;
#pragma unroll
    for (int j = 0; j < 8; ++j) {
        int i = tid * 8 + j;
        flags[j] = mask_true(mraw, b * S_LEN + i, mode) ? 1 : 0;
        loc += flags[j];
    }
    ssum[tid] = loc;
    __syncthreads();
    for (int off = 1; off < 256; off <<= 1) {
        int v = (tid >= off) ? ssum[tid - off] : 0;
        __syncthreads();
        ssum[tid] += v;
        __syncthreads();
    }
    int base = (tid > 0) ? ssum[tid - 1] : 0;
#pragma unroll
    for (int j = 0; j < 8; ++j) {
        if (flags[j]) g_kidx[b * S_LEN + base++] = tid * 8 + j;
    }
    if (tid == 255) g_kcnt[b] = ssum[255];
}

// ---------------- compact K/V rows to attended keys --------------------------
// grid (1024, B_SZ), 256 threads: 2 rows/block, 128 threads/row (uint4 cols).
__global__ __launch_bounds__(256)
void compact_kv_kernel() {
    const int tid = threadIdx.x;
    const int b = blockIdx.y;
    const int i = blockIdx.x * 2 + (tid >> 7);
    const int c = (tid & 127) * 8;
    const int cnt = g_kcnt[b];
    const size_t drow = ((size_t)b * S_LEN + i) * DM + c;
    if (i < cnt) {
        const int src = g_kidx[b * S_LEN + i];
        const size_t srow = ((size_t)b * S_LEN + src) * DM + c;
        *(uint4*)&g_ckhi[drow] = *(const uint4*)&g_khi[srow];
        *(uint4*)&g_cklo[drow] = *(const uint4*)&g_klo[srow];
        *(uint4*)&g_cvhi[drow] = *(const uint4*)&g_vhi[srow];
        *(uint4*)&g_cvlo[drow] = *(const uint4*)&g_vlo[srow];
    } else {
        uint4 z = {0, 0, 0, 0};
        *(uint4*)&g_ckhi[drow] = z;
        *(uint4*)&g_cklo[drow] = z;
        *(uint4*)&g_cvhi[drow] = z;
        *(uint4*)&g_cvlo[drow] = z;
    }
    if ((tid & 127) == 0) g_cmask[b * S_LEN + i] = (i < cnt) ? 0.0f : -1e30f;
}

// ---------------- fp32 -> bf16 hi/lo (x) -------------------------------------
__global__ __launch_bounds__(256)
void conv_x_kernel(const float* __restrict__ src) {
    int i = blockIdx.x * blockDim.x + threadIdx.x;
    if (i >= MROWS * DM) return;
    float v = src[i];
    __nv_bfloat16 h = __float2bfloat16(v);
    g_xhi[i] = h;
    g_xlo[i] = __float2bfloat16(v - __bfloat162float(h));
}

// ---------------- W transpose + bf16 hi/lo -----------------------------------
__global__ __launch_bounds__(256)
void prep_w_kernel(const float* __restrict__ Wq, const float* __restrict__ Wk,
                   const float* __restrict__ Wv, const float* __restrict__ Wo) {
    __shared__ float t[32][33];
    int z = blockIdx.z;
    const float* W = (z == 0) ? Wq : (z == 1) ? Wk : (z == 2) ? Wv : Wo;
    __nv_bfloat16* oh = g_wthi + (size_t)z * DM * DM;
    __nv_bfloat16* ol = g_wtlo + (size_t)z * DM * DM;
    int x0 = blockIdx.x * 32, y0 = blockIdx.y * 32;
    int tx = threadIdx.x, ty = threadIdx.y;   // (32, 8)
#pragma unroll
    for (int j = 0; j < 4; ++j)
        t[ty + j * 8][tx] = W[(size_t)(y0 + ty + j * 8) * DM + x0 + tx];
    __syncthreads();
#pragma unroll
    for (int j = 0; j < 4; ++j) {
        float v = t[tx][ty + j * 8];
        __nv_bfloat16 h = __float2bfloat16(v);
        size_t o = (size_t)(x0 + ty + j * 8) * DM + y0 + tx;
        oh[o] = h;
        ol[o] = __float2bfloat16(v - __bfloat162float(h));
    }
}

// ---------------- mma.sync bf16x3 GEMM with cp.async double buffer -----------
#define AS_STRIDE 40
#define SEG (128 * AS_STRIDE)
#define SEGB (SEG * 2)
#define STAGEB (4 * SEGB)
#define GEMM_SMEM (2 * STAGEB)

template <bool HALF_OUT>
__device__ __forceinline__ void gemm_tc_body(const __nv_bfloat16* __restrict__ Ahi,
                                             const __nv_bfloat16* __restrict__ Alo,
                                             const __nv_bfloat16* __restrict__ Bhi,
                                             const __nv_bfloat16* __restrict__ Blo,
                                             const float* __restrict__ bias,
                                             float* __restrict__ Cf,
                                             __half* __restrict__ Chi,
                                             __half* __restrict__ Clo) {
    extern __shared__ __nv_bfloat16 smb[];

    const int tid  = threadIdx.x;
    const int lane = tid & 31, warp = tid >> 5;
    const int wm = (warp & 3) * 32;
    const int wn = (warp >> 2) * 64;
    const int m0 = blockIdx.y * 128;
    const int n0 = blockIdx.x * 128;
    const int grp = lane >> 2;
    const int tig = lane & 3;

    const uint32_t sb = smem_u32(smb);
    const int r0l = tid >> 2, q0l = tid & 3;
    const int r1l = (tid + 256) >> 2, q1l = q0l;
    const uint32_t soff0 = (uint32_t)(r0l * AS_STRIDE + q0l * 8) * 2;
    const uint32_t soff1 = (uint32_t)(r1l * AS_STRIDE + q1l * 8) * 2;

    float acc[2][8][4];
#pragma unroll
    for (int mt = 0; mt < 2; ++mt)
#pragma unroll
        for (int nt = 0; nt < 8; ++nt)
#pragma unroll
            for (int e = 0; e < 4; ++e) acc[mt][nt][e] = 0.0f;

    auto load_stage = [&](int kt, int s) {
        const uint32_t base = sb + (uint32_t)s * STAGEB;
        const size_t ga0 = (size_t)(m0 + r0l) * GK + kt * 32 + q0l * 8;
        const size_t ga1 = (size_t)(m0 + r1l) * GK + kt * 32 + q1l * 8;
        const size_t gb0 = (size_t)(n0 + r0l) * GK + kt * 32 + q0l * 8;
        const size_t gb1 = (size_t)(n0 + r1l) * GK + kt * 32 + q1l * 8;
        cpa16(base + soff0,            &Ahi[ga0]);
        cpa16(base + SEGB + soff0,     &Alo[ga0]);
        cpa16(base + 2 * SEGB + soff0, &Bhi[gb0]);
        cpa16(base + 3 * SEGB + soff0, &Blo[gb0]);
        cpa16(base + soff1,            &Ahi[ga1]);
        cpa16(base + SEGB + soff1,     &Alo[ga1]);
        cpa16(base + 2 * SEGB + soff1, &Bhi[gb1]);
        cpa16(base + 3 * SEGB + soff1, &Blo[gb1]);
    };

    load_stage(0, 0);
    CP_COMMIT();

    for (int kt = 0; kt < GK / 32; ++kt) {
        const int cur = kt & 1;
        if (kt + 1 < GK / 32) {
            load_stage(kt + 1, cur ^ 1);
            CP_COMMIT();
            CP_WAIT(1);
        } else {
            CP_WAIT(0);
        }
        __syncthreads();

        const __nv_bfloat16* Ah = smb + (size_t)cur * 4 * SEG;
        const __nv_bfloat16* Al = Ah + SEG;
        const __nv_bfloat16* Bh = Ah + 2 * SEG;
        const __nv_bfloat16* Bl = Ah + 3 * SEG;

#pragma unroll
        for (int ks = 0; ks < 2; ++ks) {
            const int kof = ks * 16 + tig * 2;
            uint32_t bh[8][2], bl[8][2];
#pragma unroll
            for (int nt = 0; nt < 8; ++nt) {
                const int nr = wn + nt * 8 + grp;
                bh[nt][0] = *(const uint32_t*)&Bh[nr * AS_STRIDE + kof];
                bh[nt][1] = *(const uint32_t*)&Bh[nr * AS_STRIDE + kof + 8];
                bl[nt][0] = *(const uint32_t*)&Bl[nr * AS_STRIDE + kof];
                bl[nt][1] = *(const uint32_t*)&Bl[nr * AS_STRIDE + kof + 8];
            }
#pragma unroll
            for (int mt = 0; mt < 2; ++mt) {
                const int mr = wm + mt * 16 + grp;
                uint32_t a_h[4], a_l[4];
                a_h[0] = *(const uint32_t*)&Ah[mr * AS_STRIDE + kof];
                a_h[1] = *(const uint32_t*)&Ah[(mr + 8) * AS_STRIDE + kof];
                a_h[2] = *(const uint32_t*)&Ah[mr * AS_STRIDE + kof + 8];
                a_h[3] = *(const uint32_t*)&Ah[(mr + 8) * AS_STRIDE + kof + 8];
                a_l[0] = *(const uint32_t*)&Al[mr * AS_STRIDE + kof];
                a_l[1] = *(const uint32_t*)&Al[(mr + 8) * AS_STRIDE + kof];
                a_l[2] = *(const uint32_t*)&Al[mr * AS_STRIDE + kof + 8];
                a_l[3] = *(const uint32_t*)&Al[(mr + 8) * AS_STRIDE + kof + 8];
#pragma unroll
                for (int nt = 0; nt < 8; ++nt) {
                    MMA_BF16(acc[mt][nt], a_h, bh[nt][0], bh[nt][1]);
                    MMA_BF16(acc[mt][nt], a_l, bh[nt][0], bh[nt][1]);
                    MMA_BF16(acc[mt][nt], a_h, bl[nt][0], bl[nt][1]);
                }
            }
        }
        __syncthreads();
    }

#pragma unroll
    for (int mt = 0; mt < 2; ++mt) {
#pragma unroll
        for (int nt = 0; nt < 8; ++nt) {
            int r = m0 + wm + mt * 16 + grp;
            int c = n0 + wn + nt * 8 + tig * 2;
            float2 bb = *(const float2*)&bias[c];
            float v0x = acc[mt][nt][0] + bb.x, v0y = acc[mt][nt][1] + bb.y;
            float v1x = acc[mt][nt][2] + bb.x, v1y = acc[mt][nt][3] + bb.y;
            if constexpr (HALF_OUT) {
                __half h0 = __float2half_rn(v0x), h1 = __float2half_rn(v0y);
                __half2 hp; hp.x = h0; hp.y = h1;
                __half2 lp; lp.x = __float2half_rn(v0x - __half2float(h0));
                            lp.y = __float2half_rn(v0y - __half2float(h1));
                *(__half2*)&Chi[(size_t)r * DM + c] = hp;
                *(__half2*)&Clo[(size_t)r * DM + c] = lp;
                __half g0 = __float2half_rn(v1x), g1 = __float2half_rn(v1y);
                __half2 hq; hq.x = g0; hq.y = g1;
                __half2 lq; lq.x = __float2half_rn(v1x - __half2float(g0));
                            lq.y = __float2half_rn(v1y - __half2float(g1));
                *(__half2*)&Chi[(size_t)(r + 8) * DM + c] = hq;
                *(__half2*)&Clo[(size_t)(r + 8) * DM + c] = lq;
            } else {
                float2 o0 = { v0x, v0y }, o1 = { v1x, v1y };
                *(float2*)&Cf[(size_t)r * DM + c] = o0;
                *(float2*)&Cf[(size_t)(r + 8) * DM + c] = o1;
            }
        }
    }
}

__global__ __launch_bounds__(256)
void qkv_tc_kernel(const float* __restrict__ bq, const float* __restrict__ bk,
                   const float* __restrict__ bv) {
    int z = blockIdx.z;
    const __nv_bfloat16* Bh = g_wthi + (size_t)z * DM * DM;
    const __nv_bfloat16* Bl = g_wtlo + (size_t)z * DM * DM;
    const float* bias = (z == 0) ? bq : (z == 1) ? bk : bv;
    __half* Chi = (z == 0) ? g_qhi : (z == 1) ? g_khi : g_vhi;
    __half* Clo = (z == 0) ? g_qlo : (z == 1) ? g_klo : g_vlo;
    gemm_tc_body<true>(g_xhi, g_xlo, Bh, Bl, bias, nullptr, Chi, Clo);
}

__global__ __launch_bounds__(256)
void oproj_tc_kernel(const float* __restrict__ bo, float* __restrict__ out) {
    gemm_tc_body<false>(g_ahi, g_alo, g_wthi + (size_t)3 * DM * DM,
                        g_wtlo + (size_t)3 * DM * DM, bo, out, nullptr, nullptr);
}

// ---------------- mma.sync flash attention over COMPACTED keys ---------------
#define KST 72

__global__ __launch_bounds__(256)
void attn_tc_kernel() {
    __shared__ __half Kh[64][KST], Kl[64][KST], Vh[64][KST], Vl[64][KST];
    __shared__ float Ms[64];

    const int tid = threadIdx.x;
    const int lane = tid & 31, warp = tid >> 5;
    const int grp = lane >> 2, tig = lane & 3;
    const int qb = blockIdx.x, bh = blockIdx.y;
    const int b = bh >> 4, h = bh & 15;
    const int row0 = b * S_LEN + qb * 128;
    const int wm = warp * 16;

    const int cnt = g_kcnt[b];
    const int nblk = (cnt + 63) >> 6;

    uint32_t qh[4][4], ql[4][4];
    {
        const size_t r0 = (size_t)(row0 + wm + grp) * DM;
        const size_t r1 = r0 + 8 * DM;
#pragma unroll
        for (int kc = 0; kc < 4; ++kc) {
            int d = h * DH + kc * 16 + tig * 2;
            qh[kc][0] = *(const uint32_t*)&g_qhi[r0 + d];
            qh[kc][1] = *(const uint32_t*)&g_qhi[r1 + d];
            qh[kc][2] = *(const uint32_t*)&g_qhi[r0 + d + 8];
            qh[kc][3] = *(const uint32_t*)&g_qhi[r1 + d + 8];
            ql[kc][0] = *(const uint32_t*)&g_qlo[r0 + d];
            ql[kc][1] = *(const uint32_t*)&g_qlo[r1 + d];
            ql[kc][2] = *(const uint32_t*)&g_qlo[r0 + d + 8];
            ql[kc][3] = *(const uint32_t*)&g_qlo[r1 + d + 8];
        }
    }

    float o[8][4];
#pragma unroll
    for (int nt = 0; nt < 8; ++nt)
#pragma unroll
        for (int e = 0; e < 4; ++e) o[nt][e] = 0.0f;
    float m0 = -1e30f, m1 = -1e30f, l0 = 0.0f, l1 = 0.0f;

    uint4 pre[8];
    float pmask = 0.0f;
    const int pr = tid >> 3, pc = (tid & 7) * 8;
    const int pr2 = (tid + 256) >> 3, pc2 = (tid & 7) * 8;
    {
        const size_t base = (size_t)(b * S_LEN) * DM + h * DH;
        pre[0] = *(const uint4*)&g_ckhi[base + (size_t)pr * DM + pc];
        pre[1] = *(const uint4*)&g_cklo[base + (size_t)pr * DM + pc];
        pre[2] = *(const uint4*)&g_cvhi[base + (size_t)pr * DM + pc];
        pre[3] = *(const uint4*)&g_cvlo[base + (size_t)pr * DM + pc];
        pre[4] = *(const uint4*)&g_ckhi[base + (size_t)pr2 * DM + pc2];
        pre[5] = *(const uint4*)&g_cklo[base + (size_t)pr2 * DM + pc2];
        pre[6] = *(const uint4*)&g_cvhi[base + (size_t)pr2 * DM + pc2];
        pre[7] = *(const uint4*)&g_cvlo[base + (size_t)pr2 * DM + pc2];
        if (tid < 64) pmask = g_cmask[b * S_LEN + tid];
    }

    for (int kb = 0; kb < nblk; ++kb) {
        __syncthreads();
        *(uint4*)&Kh[pr][pc] = pre[0];
        *(uint4*)&Kl[pr][pc] = pre[1];
        *(uint4*)&Vh[pr][pc] = pre[2];
        *(uint4*)&Vl[pr][pc] = pre[3];
        *(uint4*)&Kh[pr2][pc2] = pre[4];
        *(uint4*)&Kl[pr2][pc2] = pre[5];
        *(uint4*)&Vh[pr2][pc2] = pre[6];
        *(uint4*)&Vl[pr2][pc2] = pre[7];
        if (tid < 64) Ms[tid] = pmask;
        __syncthreads();

        if (kb + 1 < nblk) {
            const size_t base = (size_t)(b * S_LEN + (kb + 1) * 64) * DM + h * DH;
            pre[0] = *(const uint4*)&g_ckhi[base + (size_t)pr * DM + pc];
            pre[1] = *(const uint4*)&g_cklo[base + (size_t)pr * DM + pc];
            pre[2] = *(const uint4*)&g_cvhi[base + (size_t)pr * DM + pc];
            pre[3] = *(const uint4*)&g_cvlo[base + (size_t)pr * DM + pc];
            pre[4] = *(const uint4*)&g_ckhi[base + (size_t)pr2 * DM + pc2];
            pre[5] = *(const uint4*)&g_cklo[base + (size_t)pr2 * DM + pc2];
            pre[6] = *(const uint4*)&g_cvhi[base + (size_t)pr2 * DM + pc2];
            pre[7] = *(const uint4*)&g_cvlo[base + (size_t)pr2 * DM + pc2];
            if (tid < 64) pmask = g_cmask[b * S_LEN + (kb + 1) * 64 + tid];
        }

        float s[8][4];
#pragma unroll
        for (int nt = 0; nt < 8; ++nt)
#pragma unroll
            for (int e = 0; e < 4; ++e) s[nt][e] = 0.0f;

#pragma unroll
        for (int kc = 0; kc < 4; ++kc) {
            const int kof = kc * 16 + tig * 2;
#pragma unroll
            for (int nt = 0; nt < 8; ++nt) {
                const int nr = nt * 8 + grp;
                uint32_t b0h = *(const uint32_t*)&Kh[nr][kof];
                uint32_t b1h = *(const uint32_t*)&Kh[nr][kof + 8];
                uint32_t b0l = *(const uint32_t*)&Kl[nr][kof];
                uint32_t b1l = *(const uint32_t*)&Kl[nr][kof + 8];
                MMA_F16(s[nt], qh[kc], b0h, b1h);
                MMA_F16(s[nt], ql[kc], b0h, b1h);
                MMA_F16(s[nt], qh[kc], b0l, b1l);
            }
        }

        float tmax0 = -1e30f, tmax1 = -1e30f;
#pragma unroll
        for (int nt = 0; nt < 8; ++nt) {
            float2 mv = *(const float2*)&Ms[nt * 8 + tig * 2];
            s[nt][0] = fmaf(s[nt][0], 0.125f, mv.x);
            s[nt][1] = fmaf(s[nt][1], 0.125f, mv.y);
            s[nt][2] = fmaf(s[nt][2], 0.125f, mv.x);
            s[nt][3] = fmaf(s[nt][3], 0.125f, mv.y);
            tmax0 = fmaxf(tmax0, fmaxf(s[nt][0], s[nt][1]));
            tmax1 = fmaxf(tmax1, fmaxf(s[nt][2], s[nt][3]));
        }
        tmax0 = fmaxf(tmax0, __shfl_xor_sync(0xffffffffu, tmax0, 1));
        tmax0 = fmaxf(tmax0, __shfl_xor_sync(0xffffffffu, tmax0, 2));
        tmax1 = fmaxf(tmax1, __shfl_xor_sync(0xffffffffu, tmax1, 1));
        tmax1 = fmaxf(tmax1, __shfl_xor_sync(0xffffffffu, tmax1, 2));

        float mn0 = fmaxf(m0, tmax0), mn1 = fmaxf(m1, tmax1);
        float al0 = __expf(m0 - mn0), al1 = __expf(m1 - mn1);
        m0 = mn0; m1 = mn1;

        float rs0 = 0.0f, rs1 = 0.0f;
        uint32_t pa[8], pb[8];
#pragma unroll
        for (int nt = 0; nt < 8; ++nt) {
            float p0 = __expf(s[nt][0] - mn0);
            float p1 = __expf(s[nt][1] - mn0);
            float p2 = __expf(s[nt][2] - mn1);
            float p3 = __expf(s[nt][3] - mn1);
            rs0 += p0 + p1; rs1 += p2 + p3;
            pa[nt] = pack_h2(p0, p1);
            pb[nt] = pack_h2(p2, p3);
        }
        rs0 += __shfl_xor_sync(0xffffffffu, rs0, 1);
        rs0 += __shfl_xor_sync(0xffffffffu, rs0, 2);
        rs1 += __shfl_xor_sync(0xffffffffu, rs1, 1);
        rs1 += __shfl_xor_sync(0xffffffffu, rs1, 2);
        l0 = l0 * al0 + rs0;
        l1 = l1 * al1 + rs1;

#pragma unroll
        for (int nt = 0; nt < 8; ++nt) {
            o[nt][0] *= al0; o[nt][1] *= al0;
            o[nt][2] *= al1; o[nt][3] *= al1;
        }

        const int lrow = (lane & 7) + 8 * ((lane >> 3) & 1);
        const int lcol = 8 * (lane >> 4);
#pragma unroll
        for (int kc2 = 0; kc2 < 4; ++kc2) {
            uint32_t a[4] = { pa[kc2 * 2], pb[kc2 * 2], pa[kc2 * 2 + 1], pb[kc2 * 2 + 1] };
#pragma unroll
            for (int dp = 0; dp < 4; ++dp) {
                uint32_t v0, v1, v2, v3;
                uint32_t ad = smem_u32(&Vh[kc2 * 16 + lrow][dp * 16 + lcol]);
                LDMATRIX_X4_TRANS(v0, v1, v2, v3, ad);
                MMA_F16(o[dp * 2],     a, v0, v1);
                MMA_F16(o[dp * 2 + 1], a, v2, v3);
                ad = smem_u32(&Vl[kc2 * 16 + lrow][dp * 16 + lcol]);
                LDMATRIX_X4_TRANS(v0, v1, v2, v3, ad);
                MMA_F16(o[dp * 2],     a, v0, v1);
                MMA_F16(o[dp * 2 + 1], a, v2, v3);
            }
        }
    }

    float inv0 = 1.0f / l0, inv1 = 1.0f / l1;
    const size_t r0 = (size_t)(row0 + wm + grp) * DM;
    const size_t r1 = r0 + 8 * DM;
#pragma unroll
    for (int nt = 0; nt < 8; ++nt) {
        int c = h * DH + nt * 8 + tig * 2;
        float x0 = o[nt][0] * inv0, x1 = o[nt][1] * inv0;
        float y0 = o[nt][2] * inv1, y1 = o[nt][3] * inv1;
        __nv_bfloat16 hx0 = __float2bfloat16(x0), hx1 = __float2bfloat16(x1);
        __nv_bfloat162 hp; hp.x = hx0; hp.y = hx1;
        __nv_bfloat162 lp;
        lp.x = __float2bfloat16(x0 - __bfloat162float(hx0));
        lp.y = __float2bfloat16(x1 - __bfloat162float(hx1));
        *(__nv_bfloat162*)&g_ahi[r0 + c] = hp;
        *(__nv_bfloat162*)&g_alo[r0 + c] = lp;
        __nv_bfloat16 hy0 = __float2bfloat16(y0), hy1 = __float2bfloat16(y1);
        __nv_bfloat162 hq; hq.x = hy0; hq.y = hy1;
        __nv_bfloat162 lq;
        lq.x = __float2bfloat16(y0 - __bfloat162float(hy0));
        lq.y = __float2bfloat16(y1 - __bfloat162float(hy1));
        *(__nv_bfloat162*)&g_ahi[r1 + c] = hq;
        *(__nv_bfloat162*)&g_alo[r1 + c] = lq;
    }
}

// ---------------- launch -----------------------------------------------------
extern "C" void kernel_launch(void* const* d_in, const int* in_sizes, int n_in,
                              void* d_out, int out_size) {
    const float* x  = (const float*)d_in[0];
    const void*  mk = d_in[1];
    const float* Wq = (const float*)d_in[2];
    const float* bq = (const float*)d_in[3];
    const float* Wk = (const float*)d_in[4];
    const float* bk = (const float*)d_in[5];
    const float* Wv = (const float*)d_in[6];
    const float* bv = (const float*)d_in[7];
    const float* Wo = (const float*)d_in[8];
    const float* bo = (const float*)d_in[9];
    float* out = (float*)d_out;

    detect_mask_kernel<<<1, 256>>>((const unsigned char*)mk);
    scan_mask_kernel<<<B_SZ, 256>>>(mk);

    prep_w_kernel<<<dim3(32, 32, 4), dim3(32, 8)>>>(Wq, Wk, Wv, Wo);
    conv_x_kernel<<<(MROWS * DM + 255) / 256, 256>>>(x);

    cudaFuncSetAttribute(qkv_tc_kernel,
                         cudaFuncAttributeMaxDynamicSharedMemorySize, GEMM_SMEM);
    cudaFuncSetAttribute(oproj_tc_kernel,
                         cudaFuncAttributeMaxDynamicSharedMemorySize, GEMM_SMEM);

    qkv_tc_kernel<<<dim3(DM / 128, MROWS / 128, 3), 256, GEMM_SMEM>>>(bq, bk, bv);

    compact_kv_kernel<<<dim3(S_LEN / 2, B_SZ), 256>>>();

    attn_tc_kernel<<<dim3(S_LEN / 128, B_SZ * NH), 256>>>();

    oproj_tc_kernel<<<dim3(DM / 128, MROWS / 128), 256, GEMM_SMEM>>>(bo, out);
}

// round 9
// speedup vs baseline: 4.8489x; 1.1334x over previous
#include <cuda_runtime.h>
#include <cuda_bf16.h>
#include <cuda_fp16.h>
#include <cstdint>

#define S_LEN 2048
#define B_SZ 4
#define NH 16
#define DH 64
#define DM 1024
#define MROWS (B_SZ * S_LEN)   // 8192
#define GK 1024

// ---------------- scratch (device globals; device-code references ONLY) -----
__device__ int   g_mask_mode;
__device__ int   g_kcnt[B_SZ];
__device__ int   g_kidx[B_SZ * S_LEN];
__device__ float g_cmask[B_SZ * S_LEN];

__device__ __nv_bfloat16 g_xhi[MROWS * DM];
__device__ __nv_bfloat16 g_xlo[MROWS * DM];
__device__ __nv_bfloat16 g_ahi[MROWS * DM];
__device__ __nv_bfloat16 g_alo[MROWS * DM];
__device__ __nv_bfloat16 g_wthi[4 * DM * DM];   // W^T, [N][K] K-major
__device__ __nv_bfloat16 g_wtlo[4 * DM * DM];

__device__ __half g_qhi[MROWS * DM];
__device__ __half g_qlo[MROWS * DM];
__device__ __half g_khi[MROWS * DM];
__device__ __half g_klo[MROWS * DM];
__device__ __half g_vhi[MROWS * DM];
__device__ __half g_vlo[MROWS * DM];
// compacted (attended-only) K/V
__device__ __half g_ckhi[MROWS * DM];
__device__ __half g_cvhi[MROWS * DM];
__device__ __half g_cvlo[MROWS * DM];

// ---------------- PTX helpers ------------------------------------------------
__device__ __forceinline__ uint32_t smem_u32(const void* p) {
    uint32_t a;
    asm("{ .reg .u64 t; cvta.to.shared.u64 t, %1; cvt.u32.u64 %0, t; }"
        : "=r"(a) : "l"(p));
    return a;
}

#define MMA_BF16(c, a, b0, b1)                                              \
    asm volatile("mma.sync.aligned.m16n8k16.row.col.f32.bf16.bf16.f32 "     \
                 "{%0,%1,%2,%3}, {%4,%5,%6,%7}, {%8,%9}, {%0,%1,%2,%3};"    \
                 : "+f"((c)[0]), "+f"((c)[1]), "+f"((c)[2]), "+f"((c)[3])   \
                 : "r"((a)[0]), "r"((a)[1]), "r"((a)[2]), "r"((a)[3]),      \
                   "r"(b0), "r"(b1))

#define MMA_F16(c, a, b0, b1)                                               \
    asm volatile("mma.sync.aligned.m16n8k16.row.col.f32.f16.f16.f32 "       \
                 "{%0,%1,%2,%3}, {%4,%5,%6,%7}, {%8,%9}, {%0,%1,%2,%3};"    \
                 : "+f"((c)[0]), "+f"((c)[1]), "+f"((c)[2]), "+f"((c)[3])   \
                 : "r"((a)[0]), "r"((a)[1]), "r"((a)[2]), "r"((a)[3]),      \
                   "r"(b0), "r"(b1))

#define LDMATRIX_X4_TRANS(r0, r1, r2, r3, addr)                             \
    asm volatile("ldmatrix.sync.aligned.m8n8.x4.trans.shared.b16 "          \
                 "{%0,%1,%2,%3}, [%4];"                                     \
                 : "=r"(r0), "=r"(r1), "=r"(r2), "=r"(r3) : "r"(addr))

__device__ __forceinline__ void cpa16(uint32_t dst, const void* src) {
    asm volatile("cp.async.ca.shared.global [%0], [%1], 16;"
                 :: "r"(dst), "l"(src));
}
#define CP_COMMIT()  asm volatile("cp.async.commit_group;" ::: "memory")
#define CP_WAIT(n)   asm volatile("cp.async.wait_group %0;" :: "n"(n) : "memory")

__device__ __forceinline__ uint32_t pack_h2(float a, float b) {
    __half2 h = __floats2half2_rn(a, b);
    return *(uint32_t*)&h;
}

__device__ __forceinline__ bool mask_true(const void* mraw, int i, int mode) {
    if (mode == 0)      return ((const int*)mraw)[i] != 0;
    else if (mode == 1) return ((const unsigned char*)mraw)[i] != 0;
    else                return ((const float*)mraw)[i] != 0.0f;
}

// ---------------- mask dtype detection --------------------------------------
__global__ void detect_mask_kernel(const unsigned char* __restrict__ m) {
    __shared__ int f_nonbin, f_off;
    int tid = threadIdx.x;
    if (tid == 0) { f_nonbin = 0; f_off = 0; }
    __syncthreads();
    int loc_nb = 0, loc_off = 0;
    for (int i = tid; i < B_SZ * S_LEN; i += blockDim.x) {
        unsigned char v = m[i];
        if (v > 1) loc_nb = 1;
        if ((i & 3) && v) loc_off = 1;
    }
    if (loc_nb) atomicOr(&f_nonbin, 1);
    if (loc_off) atomicOr(&f_off, 1);
    __syncthreads();
    if (tid == 0) g_mask_mode = f_nonbin ? 2 : (f_off ? 1 : 0);
}

// ---------------- per-batch mask prefix scan -> attended key indices ---------
__global__ __launch_bounds__(256)
void scan_mask_kernel(const void* __restrict__ mraw) {
    __shared__ int ssum[256];
    const int b = blockIdx.x;
    const int tid = threadIdx.x;
    const int mode = g_mask_mode;
    int flags[8], loc = 0;
#pragma unroll
    for (int j = 0; j < 8; ++j) {
        int i = tid * 8 + j;
        flags[j] = mask_true(mraw, b * S_LEN + i, mode) ? 1 : 0;
        loc += flags[j];
    }
    ssum[tid] = loc;
    __syncthreads();
    for (int off = 1; off < 256; off <<= 1) {
        int v = (tid >= off) ? ssum[tid - off] : 0;
        __syncthreads();
        ssum[tid] += v;
        __syncthreads();
    }
    int base = (tid > 0) ? ssum[tid - 1] : 0;
#pragma unroll
    for (int j = 0; j < 8; ++j) {
        if (flags[j]) g_kidx[b * S_LEN + base++] = tid * 8 + j;
    }
    if (tid == 255) g_kcnt[b] = ssum[255];
}

// ---------------- compact K/V rows to attended keys --------------------------
__global__ __launch_bounds__(256)
void compact_kv_kernel() {
    const int tid = threadIdx.x;
    const int b = blockIdx.y;
    const int i = blockIdx.x * 2 + (tid >> 7);
    const int c = (tid & 127) * 8;
    const int cnt = g_kcnt[b];
    const size_t drow = ((size_t)b * S_LEN + i) * DM + c;
    if (i < cnt) {
        const int src = g_kidx[b * S_LEN + i];
        const size_t srow = ((size_t)b * S_LEN + src) * DM + c;
        *(uint4*)&g_ckhi[drow] = *(const uint4*)&g_khi[srow];
        *(uint4*)&g_cvhi[drow] = *(const uint4*)&g_vhi[srow];
        *(uint4*)&g_cvlo[drow] = *(const uint4*)&g_vlo[srow];
    } else {
        uint4 z = {0, 0, 0, 0};
        *(uint4*)&g_ckhi[drow] = z;
        *(uint4*)&g_cvhi[drow] = z;
        *(uint4*)&g_cvlo[drow] = z;
    }
    if ((tid & 127) == 0) g_cmask[b * S_LEN + i] = (i < cnt) ? 0.0f : -1e30f;
}

// ---------------- fp32 -> bf16 hi/lo (x) -------------------------------------
__global__ __launch_bounds__(256)
void conv_x_kernel(const float* __restrict__ src) {
    int i = blockIdx.x * blockDim.x + threadIdx.x;
    if (i >= MROWS * DM) return;
    float v = src[i];
    __nv_bfloat16 h = __float2bfloat16(v);
    g_xhi[i] = h;
    g_xlo[i] = __float2bfloat16(v - __bfloat162float(h));
}

// ---------------- W transpose + bf16 hi/lo -----------------------------------
__global__ __launch_bounds__(256)
void prep_w_kernel(const float* __restrict__ Wq, const float* __restrict__ Wk,
                   const float* __restrict__ Wv, const float* __restrict__ Wo) {
    __shared__ float t[32][33];
    int z = blockIdx.z;
    const float* W = (z == 0) ? Wq : (z == 1) ? Wk : (z == 2) ? Wv : Wo;
    __nv_bfloat16* oh = g_wthi + (size_t)z * DM * DM;
    __nv_bfloat16* ol = g_wtlo + (size_t)z * DM * DM;
    int x0 = blockIdx.x * 32, y0 = blockIdx.y * 32;
    int tx = threadIdx.x, ty = threadIdx.y;   // (32, 8)
#pragma unroll
    for (int j = 0; j < 4; ++j)
        t[ty + j * 8][tx] = W[(size_t)(y0 + ty + j * 8) * DM + x0 + tx];
    __syncthreads();
#pragma unroll
    for (int j = 0; j < 4; ++j) {
        float v = t[tx][ty + j * 8];
        __nv_bfloat16 h = __float2bfloat16(v);
        size_t o = (size_t)(x0 + ty + j * 8) * DM + y0 + tx;
        oh[o] = h;
        ol[o] = __float2bfloat16(v - __bfloat162float(h));
    }
}

// ---------------- mma.sync bf16x3 GEMM with cp.async double buffer -----------
#define AS_STRIDE 40
#define SEG (128 * AS_STRIDE)
#define SEGB (SEG * 2)
#define STAGEB (4 * SEGB)
#define GEMM_SMEM (2 * STAGEB)

template <bool HALF_OUT>
__device__ __forceinline__ void gemm_tc_body(const __nv_bfloat16* __restrict__ Ahi,
                                             const __nv_bfloat16* __restrict__ Alo,
                                             const __nv_bfloat16* __restrict__ Bhi,
                                             const __nv_bfloat16* __restrict__ Blo,
                                             const float* __restrict__ bias,
                                             float* __restrict__ Cf,
                                             __half* __restrict__ Chi,
                                             __half* __restrict__ Clo) {
    extern __shared__ __nv_bfloat16 smb[];

    const int tid  = threadIdx.x;
    const int lane = tid & 31, warp = tid >> 5;
    const int wm = (warp & 3) * 32;
    const int wn = (warp >> 2) * 64;
    const int m0 = blockIdx.y * 128;
    const int n0 = blockIdx.x * 128;
    const int grp = lane >> 2;
    const int tig = lane & 3;

    const uint32_t sb = smem_u32(smb);
    const int r0l = tid >> 2, q0l = tid & 3;
    const int r1l = (tid + 256) >> 2, q1l = q0l;
    const uint32_t soff0 = (uint32_t)(r0l * AS_STRIDE + q0l * 8) * 2;
    const uint32_t soff1 = (uint32_t)(r1l * AS_STRIDE + q1l * 8) * 2;

    float acc[2][8][4];
#pragma unroll
    for (int mt = 0; mt < 2; ++mt)
#pragma unroll
        for (int nt = 0; nt < 8; ++nt)
#pragma unroll
            for (int e = 0; e < 4; ++e) acc[mt][nt][e] = 0.0f;

    auto load_stage = [&](int kt, int s) {
        const uint32_t base = sb + (uint32_t)s * STAGEB;
        const size_t ga0 = (size_t)(m0 + r0l) * GK + kt * 32 + q0l * 8;
        const size_t ga1 = (size_t)(m0 + r1l) * GK + kt * 32 + q1l * 8;
        const size_t gb0 = (size_t)(n0 + r0l) * GK + kt * 32 + q0l * 8;
        const size_t gb1 = (size_t)(n0 + r1l) * GK + kt * 32 + q1l * 8;
        cpa16(base + soff0,            &Ahi[ga0]);
        cpa16(base + SEGB + soff0,     &Alo[ga0]);
        cpa16(base + 2 * SEGB + soff0, &Bhi[gb0]);
        cpa16(base + 3 * SEGB + soff0, &Blo[gb0]);
        cpa16(base + soff1,            &Ahi[ga1]);
        cpa16(base + SEGB + soff1,     &Alo[ga1]);
        cpa16(base + 2 * SEGB + soff1, &Bhi[gb1]);
        cpa16(base + 3 * SEGB + soff1, &Blo[gb1]);
    };

    load_stage(0, 0);
    CP_COMMIT();

    for (int kt = 0; kt < GK / 32; ++kt) {
        const int cur = kt & 1;
        if (kt + 1 < GK / 32) {
            load_stage(kt + 1, cur ^ 1);
            CP_COMMIT();
            CP_WAIT(1);
        } else {
            CP_WAIT(0);
        }
        __syncthreads();

        const __nv_bfloat16* Ah = smb + (size_t)cur * 4 * SEG;
        const __nv_bfloat16* Al = Ah + SEG;
        const __nv_bfloat16* Bh = Ah + 2 * SEG;
        const __nv_bfloat16* Bl = Ah + 3 * SEG;

#pragma unroll
        for (int ks = 0; ks < 2; ++ks) {
            const int kof = ks * 16 + tig * 2;
            uint32_t bh[8][2], bl[8][2];
#pragma unroll
            for (int nt = 0; nt < 8; ++nt) {
                const int nr = wn + nt * 8 + grp;
                bh[nt][0] = *(const uint32_t*)&Bh[nr * AS_STRIDE + kof];
                bh[nt][1] = *(const uint32_t*)&Bh[nr * AS_STRIDE + kof + 8];
                bl[nt][0] = *(const uint32_t*)&Bl[nr * AS_STRIDE + kof];
                bl[nt][1] = *(const uint32_t*)&Bl[nr * AS_STRIDE + kof + 8];
            }
#pragma unroll
            for (int mt = 0; mt < 2; ++mt) {
                const int mr = wm + mt * 16 + grp;
                uint32_t a_h[4], a_l[4];
                a_h[0] = *(const uint32_t*)&Ah[mr * AS_STRIDE + kof];
                a_h[1] = *(const uint32_t*)&Ah[(mr + 8) * AS_STRIDE + kof];
                a_h[2] = *(const uint32_t*)&Ah[mr * AS_STRIDE + kof + 8];
                a_h[3] = *(const uint32_t*)&Ah[(mr + 8) * AS_STRIDE + kof + 8];
                a_l[0] = *(const uint32_t*)&Al[mr * AS_STRIDE + kof];
                a_l[1] = *(const uint32_t*)&Al[(mr + 8) * AS_STRIDE + kof];
                a_l[2] = *(const uint32_t*)&Al[mr * AS_STRIDE + kof + 8];
                a_l[3] = *(const uint32_t*)&Al[(mr + 8) * AS_STRIDE + kof + 8];
#pragma unroll
                for (int nt = 0; nt < 8; ++nt) {
                    MMA_BF16(acc[mt][nt], a_h, bh[nt][0], bh[nt][1]);
                    MMA_BF16(acc[mt][nt], a_l, bh[nt][0], bh[nt][1]);
                    MMA_BF16(acc[mt][nt], a_h, bl[nt][0], bl[nt][1]);
                }
            }
        }
        __syncthreads();
    }

#pragma unroll
    for (int mt = 0; mt < 2; ++mt) {
#pragma unroll
        for (int nt = 0; nt < 8; ++nt) {
            int r = m0 + wm + mt * 16 + grp;
            int c = n0 + wn + nt * 8 + tig * 2;
            float2 bb = *(const float2*)&bias[c];
            float v0x = acc[mt][nt][0] + bb.x, v0y = acc[mt][nt][1] + bb.y;
            float v1x = acc[mt][nt][2] + bb.x, v1y = acc[mt][nt][3] + bb.y;
            if constexpr (HALF_OUT) {
                __half h0 = __float2half_rn(v0x), h1 = __float2half_rn(v0y);
                __half2 hp; hp.x = h0; hp.y = h1;
                __half2 lp; lp.x = __float2half_rn(v0x - __half2float(h0));
                            lp.y = __float2half_rn(v0y - __half2float(h1));
                *(__half2*)&Chi[(size_t)r * DM + c] = hp;
                *(__half2*)&Clo[(size_t)r * DM + c] = lp;
                __half g0 = __float2half_rn(v1x), g1 = __float2half_rn(v1y);
                __half2 hq; hq.x = g0; hq.y = g1;
                __half2 lq; lq.x = __float2half_rn(v1x - __half2float(g0));
                            lq.y = __float2half_rn(v1y - __half2float(g1));
                *(__half2*)&Chi[(size_t)(r + 8) * DM + c] = hq;
                *(__half2*)&Clo[(size_t)(r + 8) * DM + c] = lq;
            } else {
                float2 o0 = { v0x, v0y }, o1 = { v1x, v1y };
                *(float2*)&Cf[(size_t)r * DM + c] = o0;
                *(float2*)&Cf[(size_t)(r + 8) * DM + c] = o1;
            }
        }
    }
}

__global__ __launch_bounds__(256)
void qkv_tc_kernel(const float* __restrict__ bq, const float* __restrict__ bk,
                   const float* __restrict__ bv) {
    int z = blockIdx.z;
    const __nv_bfloat16* Bh = g_wthi + (size_t)z * DM * DM;
    const __nv_bfloat16* Bl = g_wtlo + (size_t)z * DM * DM;
    const float* bias = (z == 0) ? bq : (z == 1) ? bk : bv;
    __half* Chi = (z == 0) ? g_qhi : (z == 1) ? g_khi : g_vhi;
    __half* Clo = (z == 0) ? g_qlo : (z == 1) ? g_klo : g_vlo;
    gemm_tc_body<true>(g_xhi, g_xlo, Bh, Bl, bias, nullptr, Chi, Clo);
}

__global__ __launch_bounds__(256)
void oproj_tc_kernel(const float* __restrict__ bo, float* __restrict__ out) {
    gemm_tc_body<false>(g_ahi, g_alo, g_wthi + (size_t)3 * DM * DM,
                        g_wtlo + (size_t)3 * DM * DM, bo, out, nullptr, nullptr);
}

// ---------------- flash attention: 1-pass fp16 QK, cp.async 2-stage ----------
#define KST 72
#define ASEG (64 * KST)              // halfs per buffer
#define ASTG (3 * ASEG)              // halfs per stage (Kh, Vh, Vl)
#define ATT_SMEM (2 * ASTG * 2 + 2 * 64 * 4)   // 55808 bytes

__global__ __launch_bounds__(256, 2)
void attn_tc_kernel() {
    extern __shared__ __half asmem[];
    float* Msb = (float*)(asmem + 2 * ASTG);   // [2][64]

    const int tid = threadIdx.x;
    const int lane = tid & 31, warp = tid >> 5;
    const int grp = lane >> 2, tig = lane & 3;
    const int qb = blockIdx.x, bh = blockIdx.y;
    const int b = bh >> 4, h = bh & 15;
    const int row0 = b * S_LEN + qb * 128;
    const int wm = warp * 16;

    const int cnt = g_kcnt[b];
    const int nblk = (cnt + 63) >> 6;

    const uint32_t sb = smem_u32(asmem);
    const uint32_t msb = smem_u32(Msb);
    const int pr = tid >> 3, pc = (tid & 7) * 8;    // rows 0..31 / +32

    // Q fragments (hi only — single-pass QK)
    uint32_t qh[4][4];
    {
        const size_t r0 = (size_t)(row0 + wm + grp) * DM;
        const size_t r1 = r0 + 8 * DM;
#pragma unroll
        for (int kc = 0; kc < 4; ++kc) {
            int d = h * DH + kc * 16 + tig * 2;
            qh[kc][0] = *(const uint32_t*)&g_qhi[r0 + d];
            qh[kc][1] = *(const uint32_t*)&g_qhi[r1 + d];
            qh[kc][2] = *(const uint32_t*)&g_qhi[r0 + d + 8];
            qh[kc][3] = *(const uint32_t*)&g_qhi[r1 + d + 8];
        }
    }

    float o[8][4];
#pragma unroll
    for (int nt = 0; nt < 8; ++nt)
#pragma unroll
        for (int e = 0; e < 4; ++e) o[nt][e] = 0.0f;
    float m0 = -1e30f, m1 = -1e30f, l0 = 0.0f, l1 = 0.0f;

    auto load_stage = [&](int kb, int s) {
        const size_t gbase = (size_t)(b * S_LEN + kb * 64) * DM + h * DH;
        const uint32_t sbase = sb + (uint32_t)s * (ASTG * 2);
        const size_t g0 = gbase + (size_t)pr * DM + pc;
        const size_t g1 = gbase + (size_t)(pr + 32) * DM + pc;
        const uint32_t s0 = (uint32_t)(pr * KST + pc) * 2;
        const uint32_t s1 = (uint32_t)((pr + 32) * KST + pc) * 2;
        cpa16(sbase + s0,                &g_ckhi[g0]);
        cpa16(sbase + s1,                &g_ckhi[g1]);
        cpa16(sbase + ASEG * 2 + s0,     &g_cvhi[g0]);
        cpa16(sbase + ASEG * 2 + s1,     &g_cvhi[g1]);
        cpa16(sbase + 2 * ASEG * 2 + s0, &g_cvlo[g0]);
        cpa16(sbase + 2 * ASEG * 2 + s1, &g_cvlo[g1]);
        if (tid < 16)
            cpa16(msb + (uint32_t)s * 256 + tid * 16,
                  &g_cmask[b * S_LEN + kb * 64 + tid * 4]);
    };

    load_stage(0, 0);
    CP_COMMIT();

    for (int kb = 0; kb < nblk; ++kb) {
        const int cur = kb & 1;
        if (kb + 1 < nblk) {
            load_stage(kb + 1, cur ^ 1);
            CP_COMMIT();
            CP_WAIT(1);
        } else {
            CP_WAIT(0);
        }
        __syncthreads();

        const __half* Kh = asmem + (size_t)cur * ASTG;
        const __half* Vh = Kh + ASEG;
        const __half* Vl = Kh + 2 * ASEG;
        const float* Ms = Msb + cur * 64;

        // ---- S = Q K^T (single fp16 pass) ----
        float s[8][4];
#pragma unroll
        for (int nt = 0; nt < 8; ++nt)
#pragma unroll
            for (int e = 0; e < 4; ++e) s[nt][e] = 0.0f;

#pragma unroll
        for (int kc = 0; kc < 4; ++kc) {
            const int kof = kc * 16 + tig * 2;
#pragma unroll
            for (int nt = 0; nt < 8; ++nt) {
                const int nr = nt * 8 + grp;
                uint32_t b0 = *(const uint32_t*)&Kh[nr * KST + kof];
                uint32_t b1 = *(const uint32_t*)&Kh[nr * KST + kof + 8];
                MMA_F16(s[nt], qh[kc], b0, b1);
            }
        }

        // ---- mask + scale + online softmax ----
        float tmax0 = -1e30f, tmax1 = -1e30f;
#pragma unroll
        for (int nt = 0; nt < 8; ++nt) {
            float2 mv = *(const float2*)&Ms[nt * 8 + tig * 2];
            s[nt][0] = fmaf(s[nt][0], 0.125f, mv.x);
            s[nt][1] = fmaf(s[nt][1], 0.125f, mv.y);
            s[nt][2] = fmaf(s[nt][2], 0.125f, mv.x);
            s[nt][3] = fmaf(s[nt][3], 0.125f, mv.y);
            tmax0 = fmaxf(tmax0, fmaxf(s[nt][0], s[nt][1]));
            tmax1 = fmaxf(tmax1, fmaxf(s[nt][2], s[nt][3]));
        }
        tmax0 = fmaxf(tmax0, __shfl_xor_sync(0xffffffffu, tmax0, 1));
        tmax0 = fmaxf(tmax0, __shfl_xor_sync(0xffffffffu, tmax0, 2));
        tmax1 = fmaxf(tmax1, __shfl_xor_sync(0xffffffffu, tmax1, 1));
        tmax1 = fmaxf(tmax1, __shfl_xor_sync(0xffffffffu, tmax1, 2));

        float mn0 = fmaxf(m0, tmax0), mn1 = fmaxf(m1, tmax1);
        float al0 = __expf(m0 - mn0), al1 = __expf(m1 - mn1);
        m0 = mn0; m1 = mn1;

        float rs0 = 0.0f, rs1 = 0.0f;
        uint32_t pa[8], pb[8];
#pragma unroll
        for (int nt = 0; nt < 8; ++nt) {
            float p0 = __expf(s[nt][0] - mn0);
            float p1 = __expf(s[nt][1] - mn0);
            float p2 = __expf(s[nt][2] - mn1);
            float p3 = __expf(s[nt][3] - mn1);
            rs0 += p0 + p1; rs1 += p2 + p3;
            pa[nt] = pack_h2(p0, p1);
            pb[nt] = pack_h2(p2, p3);
        }
        rs0 += __shfl_xor_sync(0xffffffffu, rs0, 1);
        rs0 += __shfl_xor_sync(0xffffffffu, rs0, 2);
        rs1 += __shfl_xor_sync(0xffffffffu, rs1, 1);
        rs1 += __shfl_xor_sync(0xffffffffu, rs1, 2);
        l0 = l0 * al0 + rs0;
        l1 = l1 * al1 + rs1;

#pragma unroll
        for (int nt = 0; nt < 8; ++nt) {
            o[nt][0] *= al0; o[nt][1] *= al0;
            o[nt][2] *= al1; o[nt][3] *= al1;
        }

        // ---- O += P V  (V^T via ldmatrix.trans; hi + lo) ----
        const int lrow = (lane & 7) + 8 * ((lane >> 3) & 1);
        const int lcol = 8 * (lane >> 4);
#pragma unroll
        for (int kc2 = 0; kc2 < 4; ++kc2) {
            uint32_t a[4] = { pa[kc2 * 2], pb[kc2 * 2], pa[kc2 * 2 + 1], pb[kc2 * 2 + 1] };
#pragma unroll
            for (int dp = 0; dp < 4; ++dp) {
                uint32_t v0, v1, v2, v3;
                uint32_t ad = smem_u32(&Vh[(kc2 * 16 + lrow) * KST + dp * 16 + lcol]);
                LDMATRIX_X4_TRANS(v0, v1, v2, v3, ad);
                MMA_F16(o[dp * 2],     a, v0, v1);
                MMA_F16(o[dp * 2 + 1], a, v2, v3);
                ad = smem_u32(&Vl[(kc2 * 16 + lrow) * KST + dp * 16 + lcol]);
                LDMATRIX_X4_TRANS(v0, v1, v2, v3, ad);
                MMA_F16(o[dp * 2],     a, v0, v1);
                MMA_F16(o[dp * 2 + 1], a, v2, v3);
            }
        }
        __syncthreads();
    }

    // ---- epilogue: normalize, write bf16 hi/lo for oproj ----
    float inv0 = 1.0f / l0, inv1 = 1.0f / l1;
    const size_t r0 = (size_t)(row0 + wm + grp) * DM;
    const size_t r1 = r0 + 8 * DM;
#pragma unroll
    for (int nt = 0; nt < 8; ++nt) {
        int c = h * DH + nt * 8 + tig * 2;
        float x0 = o[nt][0] * inv0, x1 = o[nt][1] * inv0;
        float y0 = o[nt][2] * inv1, y1 = o[nt][3] * inv1;
        __nv_bfloat16 hx0 = __float2bfloat16(x0), hx1 = __float2bfloat16(x1);
        __nv_bfloat162 hp; hp.x = hx0; hp.y = hx1;
        __nv_bfloat162 lp;
        lp.x = __float2bfloat16(x0 - __bfloat162float(hx0));
        lp.y = __float2bfloat16(x1 - __bfloat162float(hx1));
        *(__nv_bfloat162*)&g_ahi[r0 + c] = hp;
        *(__nv_bfloat162*)&g_alo[r0 + c] = lp;
        __nv_bfloat16 hy0 = __float2bfloat16(y0), hy1 = __float2bfloat16(y1);
        __nv_bfloat162 hq; hq.x = hy0; hq.y = hy1;
        __nv_bfloat162 lq;
        lq.x = __float2bfloat16(y0 - __bfloat162float(hy0));
        lq.y = __float2bfloat16(y1 - __bfloat162float(hy1));
        *(__nv_bfloat162*)&g_ahi[r1 + c] = hq;
        *(__nv_bfloat162*)&g_alo[r1 + c] = lq;
    }
}

// ---------------- launch -----------------------------------------------------
extern "C" void kernel_launch(void* const* d_in, const int* in_sizes, int n_in,
                              void* d_out, int out_size) {
    const float* x  = (const float*)d_in[0];
    const void*  mk = d_in[1];
    const float* Wq = (const float*)d_in[2];
    const float* bq = (const float*)d_in[3];
    const float* Wk = (const float*)d_in[4];
    const float* bk = (const float*)d_in[5];
    const float* Wv = (const float*)d_in[6];
    const float* bv = (const float*)d_in[7];
    const float* Wo = (const float*)d_in[8];
    const float* bo = (const float*)d_in[9];
    float* out = (float*)d_out;

    detect_mask_kernel<<<1, 256>>>((const unsigned char*)mk);
    scan_mask_kernel<<<B_SZ, 256>>>(mk);

    prep_w_kernel<<<dim3(32, 32, 4), dim3(32, 8)>>>(Wq, Wk, Wv, Wo);
    conv_x_kernel<<<(MROWS * DM + 255) / 256, 256>>>(x);

    cudaFuncSetAttribute(qkv_tc_kernel,
                         cudaFuncAttributeMaxDynamicSharedMemorySize, GEMM_SMEM);
    cudaFuncSetAttribute(oproj_tc_kernel,
                         cudaFuncAttributeMaxDynamicSharedMemorySize, GEMM_SMEM);
    cudaFuncSetAttribute(attn_tc_kernel,
                         cudaFuncAttributeMaxDynamicSharedMemorySize, ATT_SMEM);

    qkv_tc_kernel<<<dim3(DM / 128, MROWS / 128, 3), 256, GEMM_SMEM>>>(bq, bk, bv);

    compact_kv_kernel<<<dim3(S_LEN / 2, B_SZ), 256>>>();

    attn_tc_kernel<<<dim3(S_LEN / 128, B_SZ * NH), 256, ATT_SMEM>>>();

    oproj_tc_kernel<<<dim3(DM / 128, MROWS / 128), 256, GEMM_SMEM>>>(bo, out);
}

// round 11
// speedup vs baseline: 6.3529x; 1.3102x over previous
#include <cuda_runtime.h>
#include <cuda_bf16.h>
#include <cuda_fp16.h>
#include <cstdint>

#define S_LEN 2048
#define B_SZ 4
#define NH 16
#define DH 64
#define DM 1024
#define MROWS (B_SZ * S_LEN)   // 8192
#define GK 1024

// ---------------- scratch (device globals; device-code references ONLY) -----
__device__ int   g_mask_mode;
__device__ int   g_kcnt[B_SZ];
__device__ int   g_kidx[B_SZ * S_LEN];
__device__ float g_cmask[B_SZ * S_LEN];

__device__ __half g_xhi[MROWS * DM];
__device__ __half g_xlo[MROWS * DM];
__device__ __half g_ahi[MROWS * DM];
__device__ __half g_alo[MROWS * DM];
__device__ __half g_wth[4 * DM * DM];    // W^T fp16 hi, [N][K] K-major

__device__ __half g_qhi[MROWS * DM];
__device__ __half g_khi[MROWS * DM];
__device__ __half g_vhi[MROWS * DM];
__device__ __half g_vlo[MROWS * DM];
// compacted (attended-only) K/V
__device__ __half g_ckhi[MROWS * DM];
__device__ __half g_cvhi[MROWS * DM];
__device__ __half g_cvlo[MROWS * DM];

// ---------------- PTX helpers ------------------------------------------------
__device__ __forceinline__ uint32_t smem_u32(const void* p) {
    uint32_t a;
    asm("{ .reg .u64 t; cvta.to.shared.u64 t, %1; cvt.u32.u64 %0, t; }"
        : "=r"(a) : "l"(p));
    return a;
}

#define MMA_F16(c, a, b0, b1)                                               \
    asm volatile("mma.sync.aligned.m16n8k16.row.col.f32.f16.f16.f32 "       \
                 "{%0,%1,%2,%3}, {%4,%5,%6,%7}, {%8,%9}, {%0,%1,%2,%3};"    \
                 : "+f"((c)[0]), "+f"((c)[1]), "+f"((c)[2]), "+f"((c)[3])   \
                 : "r"((a)[0]), "r"((a)[1]), "r"((a)[2]), "r"((a)[3]),      \
                   "r"(b0), "r"(b1))

#define LDMATRIX_X4_TRANS(r0, r1, r2, r3, addr)                             \
    asm volatile("ldmatrix.sync.aligned.m8n8.x4.trans.shared.b16 "          \
                 "{%0,%1,%2,%3}, [%4];"                                     \
                 : "=r"(r0), "=r"(r1), "=r"(r2), "=r"(r3) : "r"(addr))

__device__ __forceinline__ void cpa16(uint32_t dst, const void* src) {
    asm volatile("cp.async.ca.shared.global [%0], [%1], 16;"
                 :: "r"(dst), "l"(src));
}
#define CP_COMMIT()  asm volatile("cp.async.commit_group;" ::: "memory")
#define CP_WAIT(n)   asm volatile("cp.async.wait_group %0;" :: "n"(n) : "memory")

__device__ __forceinline__ uint32_t pack_h2(float a, float b) {
    __half2 h = __floats2half2_rn(a, b);
    return *(uint32_t*)&h;
}

__device__ __forceinline__ bool mask_true(const void* mraw, int i, int mode) {
    if (mode == 0)      return ((const int*)mraw)[i] != 0;
    else if (mode == 1) return ((const unsigned char*)mraw)[i] != 0;
    else                return ((const float*)mraw)[i] != 0.0f;
}

// ---------------- mask dtype detection --------------------------------------
__global__ void detect_mask_kernel(const unsigned char* __restrict__ m) {
    __shared__ int f_nonbin, f_off;
    int tid = threadIdx.x;
    if (tid == 0) { f_nonbin = 0; f_off = 0; }
    __syncthreads();
    int loc_nb = 0, loc_off = 0;
    for (int i = tid; i < B_SZ * S_LEN; i += blockDim.x) {
        unsigned char v = m[i];
        if (v > 1) loc_nb = 1;
        if ((i & 3) && v) loc_off = 1;
    }
    if (loc_nb) atomicOr(&f_nonbin, 1);
    if (loc_off) atomicOr(&f_off, 1);
    __syncthreads();
    if (tid == 0) g_mask_mode = f_nonbin ? 2 : (f_off ? 1 : 0);
}

// ---------------- per-batch mask prefix scan -> attended key indices ---------
__global__ __launch_bounds__(256)
void scan_mask_kernel(const void* __restrict__ mraw) {
    __shared__ int ssum[256];
    const int b = blockIdx.x;
    const int tid = threadIdx.x;
    const int mode = g_mask_mode;
    int flags[8], loc = 0;
#pragma unroll
    for (int j = 0; j < 8; ++j) {
        int i = tid * 8 + j;
        flags[j] = mask_true(mraw, b * S_LEN + i, mode) ? 1 : 0;
        loc += flags[j];
    }
    ssum[tid] = loc;
    __syncthreads();
    for (int off = 1; off < 256; off <<= 1) {
        int v = (tid >= off) ? ssum[tid - off] : 0;
        __syncthreads();
        ssum[tid] += v;
        __syncthreads();
    }
    int base = (tid > 0) ? ssum[tid - 1] : 0;
#pragma unroll
    for (int j = 0; j < 8; ++j) {
        if (flags[j]) g_kidx[b * S_LEN + base++] = tid * 8 + j;
    }
    if (tid == 255) g_kcnt[b] = ssum[255];
}

// ---------------- compact K/V rows to attended keys --------------------------
__global__ __launch_bounds__(256)
void compact_kv_kernel() {
    const int tid = threadIdx.x;
    const int b = blockIdx.y;
    const int i = blockIdx.x * 2 + (tid >> 7);
    const int c = (tid & 127) * 8;
    const int cnt = g_kcnt[b];
    const size_t drow = ((size_t)b * S_LEN + i) * DM + c;
    if (i < cnt) {
        const int src = g_kidx[b * S_LEN + i];
        const size_t srow = ((size_t)b * S_LEN + src) * DM + c;
        *(uint4*)&g_ckhi[drow] = *(const uint4*)&g_khi[srow];
        *(uint4*)&g_cvhi[drow] = *(const uint4*)&g_vhi[srow];
        *(uint4*)&g_cvlo[drow] = *(const uint4*)&g_vlo[srow];
    } else {
        uint4 z = {0, 0, 0, 0};
        *(uint4*)&g_ckhi[drow] = z;
        *(uint4*)&g_cvhi[drow] = z;
        *(uint4*)&g_cvlo[drow] = z;
    }
    if ((tid & 127) == 0) g_cmask[b * S_LEN + i] = (i < cnt) ? 0.0f : -1e30f;
}

// ---------------- fp32 -> fp16 hi/lo (x) -------------------------------------
__global__ __launch_bounds__(256)
void conv_x_kernel(const float* __restrict__ src) {
    int i = blockIdx.x * blockDim.x + threadIdx.x;
    if (i >= MROWS * DM) return;
    float v = src[i];
    __half h = __float2half_rn(v);
    g_xhi[i] = h;
    g_xlo[i] = __float2half_rn(v - __half2float(h));
}

// ---------------- W transpose + fp16 (hi only) -------------------------------
__global__ __launch_bounds__(256)
void prep_w_kernel(const float* __restrict__ Wq, const float* __restrict__ Wk,
                   const float* __restrict__ Wv, const float* __restrict__ Wo) {
    __shared__ float t[32][33];
    int z = blockIdx.z;
    const float* W = (z == 0) ? Wq : (z == 1) ? Wk : (z == 2) ? Wv : Wo;
    __half* oh = g_wth + (size_t)z * DM * DM;
    int x0 = blockIdx.x * 32, y0 = blockIdx.y * 32;
    int tx = threadIdx.x, ty = threadIdx.y;   // (32, 8)
#pragma unroll
    for (int j = 0; j < 4; ++j)
        t[ty + j * 8][tx] = W[(size_t)(y0 + ty + j * 8) * DM + x0 + tx];
    __syncthreads();
#pragma unroll
    for (int j = 0; j < 4; ++j) {
        float v = t[tx][ty + j * 8];
        oh[(size_t)(x0 + ty + j * 8) * DM + y0 + tx] = __float2half_rn(v);
    }
}

// ---------------- mma.sync fp16x2 GEMM with cp.async double buffer -----------
// C = A @ W^T + bias.  CTA 128x128, BK=32, 8 warps (4m x 2n).
// 2 passes: Ahi*Wh + Alo*Wh (W fp16-truncated; dropped a*Wlo ~1.4e-4 rel).
#define AS_STRIDE 40
#define SEG (128 * AS_STRIDE)
#define SEGB (SEG * 2)
#define STAGEB (3 * SEGB)            // Ahi, Alo, Bh
#define GEMM_SMEM (2 * STAGEB)       // 61440 bytes -> 2 CTAs/SM

template <bool HALF_OUT>
__device__ __forceinline__ void gemm_tc_body(const __half* __restrict__ Ahi,
                                             const __half* __restrict__ Alo,
                                             const __half* __restrict__ Bh_g,
                                             const float* __restrict__ bias,
                                             float* __restrict__ Cf,
                                             __half* __restrict__ Chi,
                                             __half* __restrict__ Clo) {
    extern __shared__ __half smh[];

    const int tid  = threadIdx.x;
    const int lane = tid & 31, warp = tid >> 5;
    const int wm = (warp & 3) * 32;
    const int wn = (warp >> 2) * 64;
    const int m0 = blockIdx.y * 128;
    const int n0 = blockIdx.x * 128;
    const int grp = lane >> 2;
    const int tig = lane & 3;

    const uint32_t sb = smem_u32(smh);
    const int r0l = tid >> 2, q0l = tid & 3;
    const int r1l = (tid + 256) >> 2;
    const uint32_t soff0 = (uint32_t)(r0l * AS_STRIDE + q0l * 8) * 2;
    const uint32_t soff1 = (uint32_t)(r1l * AS_STRIDE + q0l * 8) * 2;

    float acc[2][8][4];
#pragma unroll
    for (int mt = 0; mt < 2; ++mt)
#pragma unroll
        for (int nt = 0; nt < 8; ++nt)
#pragma unroll
            for (int e = 0; e < 4; ++e) acc[mt][nt][e] = 0.0f;

    auto load_stage = [&](int kt, int s) {
        const uint32_t base = sb + (uint32_t)s * STAGEB;
        const size_t ga0 = (size_t)(m0 + r0l) * GK + kt * 32 + q0l * 8;
        const size_t ga1 = (size_t)(m0 + r1l) * GK + kt * 32 + q0l * 8;
        const size_t gb0 = (size_t)(n0 + r0l) * GK + kt * 32 + q0l * 8;
        const size_t gb1 = (size_t)(n0 + r1l) * GK + kt * 32 + q0l * 8;
        cpa16(base + soff0,            &Ahi[ga0]);
        cpa16(base + SEGB + soff0,     &Alo[ga0]);
        cpa16(base + 2 * SEGB + soff0, &Bh_g[gb0]);
        cpa16(base + soff1,            &Ahi[ga1]);
        cpa16(base + SEGB + soff1,     &Alo[ga1]);
        cpa16(base + 2 * SEGB + soff1, &Bh_g[gb1]);
    };

    load_stage(0, 0);
    CP_COMMIT();

    for (int kt = 0; kt < GK / 32; ++kt) {
        const int cur = kt & 1;
        if (kt + 1 < GK / 32) {
            load_stage(kt + 1, cur ^ 1);
            CP_COMMIT();
            CP_WAIT(1);
        } else {
            CP_WAIT(0);
        }
        __syncthreads();

        const __half* Ah = smh + (size_t)cur * 3 * SEG;
        const __half* Al = Ah + SEG;
        const __half* Bs = Ah + 2 * SEG;

#pragma unroll
        for (int ks = 0; ks < 2; ++ks) {
            const int kof = ks * 16 + tig * 2;
            uint32_t bh[8][2];
#pragma unroll
            for (int nt = 0; nt < 8; ++nt) {
                const int nr = wn + nt * 8 + grp;
                bh[nt][0] = *(const uint32_t*)&Bs[nr * AS_STRIDE + kof];
                bh[nt][1] = *(const uint32_t*)&Bs[nr * AS_STRIDE + kof + 8];
            }
#pragma unroll
            for (int mt = 0; mt < 2; ++mt) {
                const int mr = wm + mt * 16 + grp;
                uint32_t a_h[4], a_l[4];
                a_h[0] = *(const uint32_t*)&Ah[mr * AS_STRIDE + kof];
                a_h[1] = *(const uint32_t*)&Ah[(mr + 8) * AS_STRIDE + kof];
                a_h[2] = *(const uint32_t*)&Ah[mr * AS_STRIDE + kof + 8];
                a_h[3] = *(const uint32_t*)&Ah[(mr + 8) * AS_STRIDE + kof + 8];
                a_l[0] = *(const uint32_t*)&Al[mr * AS_STRIDE + kof];
                a_l[1] = *(const uint32_t*)&Al[(mr + 8) * AS_STRIDE + kof];
                a_l[2] = *(const uint32_t*)&Al[mr * AS_STRIDE + kof + 8];
                a_l[3] = *(const uint32_t*)&Al[(mr + 8) * AS_STRIDE + kof + 8];
#pragma unroll
                for (int nt = 0; nt < 8; ++nt) {
                    MMA_F16(acc[mt][nt], a_h, bh[nt][0], bh[nt][1]);
                    MMA_F16(acc[mt][nt], a_l, bh[nt][0], bh[nt][1]);
                }
            }
        }
        __syncthreads();
    }

#pragma unroll
    for (int mt = 0; mt < 2; ++mt) {
#pragma unroll
        for (int nt = 0; nt < 8; ++nt) {
            int r = m0 + wm + mt * 16 + grp;
            int c = n0 + wn + nt * 8 + tig * 2;
            float2 bb = *(const float2*)&bias[c];
            float v0x = acc[mt][nt][0] + bb.x, v0y = acc[mt][nt][1] + bb.y;
            float v1x = acc[mt][nt][2] + bb.x, v1y = acc[mt][nt][3] + bb.y;
            if constexpr (HALF_OUT) {
                __half h0 = __float2half_rn(v0x), h1 = __float2half_rn(v0y);
                __half2 hp; hp.x = h0; hp.y = h1;
                *(__half2*)&Chi[(size_t)r * DM + c] = hp;
                __half g0 = __float2half_rn(v1x), g1 = __float2half_rn(v1y);
                __half2 hq; hq.x = g0; hq.y = g1;
                *(__half2*)&Chi[(size_t)(r + 8) * DM + c] = hq;
                if (Clo) {
                    __half2 lp; lp.x = __float2half_rn(v0x - __half2float(h0));
                                lp.y = __float2half_rn(v0y - __half2float(h1));
                    *(__half2*)&Clo[(size_t)r * DM + c] = lp;
                    __half2 lq; lq.x = __float2half_rn(v1x - __half2float(g0));
                                lq.y = __float2half_rn(v1y - __half2float(g1));
                    *(__half2*)&Clo[(size_t)(r + 8) * DM + c] = lq;
                }
            } else {
                float2 o0 = { v0x, v0y }, o1 = { v1x, v1y };
                *(float2*)&Cf[(size_t)r * DM + c] = o0;
                *(float2*)&Cf[(size_t)(r + 8) * DM + c] = o1;
            }
        }
    }
}

__global__ __launch_bounds__(256, 2)
void qkv_tc_kernel(const float* __restrict__ bq, const float* __restrict__ bk,
                   const float* __restrict__ bv) {
    int z = blockIdx.z;
    const __half* Bh = g_wth + (size_t)z * DM * DM;
    const float* bias = (z == 0) ? bq : (z == 1) ? bk : bv;
    __half* Chi = (z == 0) ? g_qhi : (z == 1) ? g_khi : g_vhi;
    __half* Clo = (z == 2) ? g_vlo : nullptr;   // only V needs a lo stream
    gemm_tc_body<true>(g_xhi, g_xlo, Bh, bias, nullptr, Chi, Clo);
}

__global__ __launch_bounds__(256, 2)
void oproj_tc_kernel(const float* __restrict__ bo, float* __restrict__ out) {
    gemm_tc_body<false>(g_ahi, g_alo, g_wth + (size_t)3 * DM * DM,
                        bo, out, nullptr, nullptr);
}

// ---------------- flash attention: 1-pass fp16 QK, cp.async 2-stage ----------
#define KST 72
#define ASEG (64 * KST)
#define ASTG (3 * ASEG)              // Kh, Vh, Vl
#define ATT_SMEM (2 * ASTG * 2 + 2 * 64 * 4)   // 55808 bytes

__global__ __launch_bounds__(256, 2)
void attn_tc_kernel() {
    extern __shared__ __half asmem[];
    float* Msb = (float*)(asmem + 2 * ASTG);   // [2][64]

    const int tid = threadIdx.x;
    const int lane = tid & 31, warp = tid >> 5;
    const int grp = lane >> 2, tig = lane & 3;
    const int qb = blockIdx.x, bh = blockIdx.y;
    const int b = bh >> 4, h = bh & 15;
    const int row0 = b * S_LEN + qb * 128;
    const int wm = warp * 16;

    const int cnt = g_kcnt[b];
    const int nblk = (cnt + 63) >> 6;

    const uint32_t sb = smem_u32(asmem);
    const uint32_t msb = smem_u32(Msb);
    const int pr = tid >> 3, pc = (tid & 7) * 8;

    uint32_t qh[4][4];
    {
        const size_t r0 = (size_t)(row0 + wm + grp) * DM;
        const size_t r1 = r0 + 8 * DM;
#pragma unroll
        for (int kc = 0; kc < 4; ++kc) {
            int d = h * DH + kc * 16 + tig * 2;
            qh[kc][0] = *(const uint32_t*)&g_qhi[r0 + d];
            qh[kc][1] = *(const uint32_t*)&g_qhi[r1 + d];
            qh[kc][2] = *(const uint32_t*)&g_qhi[r0 + d + 8];
            qh[kc][3] = *(const uint32_t*)&g_qhi[r1 + d + 8];
        }
    }

    float o[8][4];
#pragma unroll
    for (int nt = 0; nt < 8; ++nt)
#pragma unroll
        for (int e = 0; e < 4; ++e) o[nt][e] = 0.0f;
    float m0 = -1e30f, m1 = -1e30f, l0 = 0.0f, l1 = 0.0f;

    auto load_stage = [&](int kb, int s) {
        const size_t gbase = (size_t)(b * S_LEN + kb * 64) * DM + h * DH;
        const uint32_t sbase = sb + (uint32_t)s * (ASTG * 2);
        const size_t g0 = gbase + (size_t)pr * DM + pc;
        const size_t g1 = gbase + (size_t)(pr + 32) * DM + pc;
        const uint32_t s0 = (uint32_t)(pr * KST + pc) * 2;
        const uint32_t s1 = (uint32_t)((pr + 32) * KST + pc) * 2;
        cpa16(sbase + s0,                &g_ckhi[g0]);
        cpa16(sbase + s1,                &g_ckhi[g1]);
        cpa16(sbase + ASEG * 2 + s0,     &g_cvhi[g0]);
        cpa16(sbase + ASEG * 2 + s1,     &g_cvhi[g1]);
        cpa16(sbase + 2 * ASEG * 2 + s0, &g_cvlo[g0]);
        cpa16(sbase + 2 * ASEG * 2 + s1, &g_cvlo[g1]);
        if (tid < 16)
            cpa16(msb + (uint32_t)s * 256 + tid * 16,
                  &g_cmask[b * S_LEN + kb * 64 + tid * 4]);
    };

    load_stage(0, 0);
    CP_COMMIT();

    for (int kb = 0; kb < nblk; ++kb) {
        const int cur = kb & 1;
        if (kb + 1 < nblk) {
            load_stage(kb + 1, cur ^ 1);
            CP_COMMIT();
            CP_WAIT(1);
        } else {
            CP_WAIT(0);
        }
        __syncthreads();

        const __half* Kh = asmem + (size_t)cur * ASTG;
        const __half* Vh = Kh + ASEG;
        const __half* Vl = Kh + 2 * ASEG;
        const float* Ms = Msb + cur * 64;

        float s[8][4];
#pragma unroll
        for (int nt = 0; nt < 8; ++nt)
#pragma unroll
            for (int e = 0; e < 4; ++e) s[nt][e] = 0.0f;

#pragma unroll
        for (int kc = 0; kc < 4; ++kc) {
            const int kof = kc * 16 + tig * 2;
#pragma unroll
            for (int nt = 0; nt < 8; ++nt) {
                const int nr = nt * 8 + grp;
                uint32_t b0 = *(const uint32_t*)&Kh[nr * KST + kof];
                uint32_t b1 = *(const uint32_t*)&Kh[nr * KST + kof + 8];
                MMA_F16(s[nt], qh[kc], b0, b1);
            }
        }

        float tmax0 = -1e30f, tmax1 = -1e30f;
#pragma unroll
        for (int nt = 0; nt < 8; ++nt) {
            float2 mv = *(const float2*)&Ms[nt * 8 + tig * 2];
            s[nt][0] = fmaf(s[nt][0], 0.125f, mv.x);
            s[nt][1] = fmaf(s[nt][1], 0.125f, mv.y);
            s[nt][2] = fmaf(s[nt][2], 0.125f, mv.x);
            s[nt][3] = fmaf(s[nt][3], 0.125f, mv.y);
            tmax0 = fmaxf(tmax0, fmaxf(s[nt][0], s[nt][1]));
            tmax1 = fmaxf(tmax1, fmaxf(s[nt][2], s[nt][3]));
        }
        tmax0 = fmaxf(tmax0, __shfl_xor_sync(0xffffffffu, tmax0, 1));
        tmax0 = fmaxf(tmax0, __shfl_xor_sync(0xffffffffu, tmax0, 2));
        tmax1 = fmaxf(tmax1, __shfl_xor_sync(0xffffffffu, tmax1, 1));
        tmax1 = fmaxf(tmax1, __shfl_xor_sync(0xffffffffu, tmax1, 2));

        float mn0 = fmaxf(m0, tmax0), mn1 = fmaxf(m1, tmax1);
        float al0 = __expf(m0 - mn0), al1 = __expf(m1 - mn1);
        m0 = mn0; m1 = mn1;

        float rs0 = 0.0f, rs1 = 0.0f;
        uint32_t pa[8], pb[8];
#pragma unroll
        for (int nt = 0; nt < 8; ++nt) {
            float p0 = __expf(s[nt][0] - mn0);
            float p1 = __expf(s[nt][1] - mn0);
            float p2 = __expf(s[nt][2] - mn1);
            float p3 = __expf(s[nt][3] - mn1);
            rs0 += p0 + p1; rs1 += p2 + p3;
            pa[nt] = pack_h2(p0, p1);
            pb[nt] = pack_h2(p2, p3);
        }
        rs0 += __shfl_xor_sync(0xffffffffu, rs0, 1);
        rs0 += __shfl_xor_sync(0xffffffffu, rs0, 2);
        rs1 += __shfl_xor_sync(0xffffffffu, rs1, 1);
        rs1 += __shfl_xor_sync(0xffffffffu, rs1, 2);
        l0 = l0 * al0 + rs0;
        l1 = l1 * al1 + rs1;

#pragma unroll
        for (int nt = 0; nt < 8; ++nt) {
            o[nt][0] *= al0; o[nt][1] *= al0;
            o[nt][2] *= al1; o[nt][3] *= al1;
        }

        const int lrow = (lane & 7) + 8 * ((lane >> 3) & 1);
        const int lcol = 8 * (lane >> 4);
#pragma unroll
        for (int kc2 = 0; kc2 < 4; ++kc2) {
            uint32_t a[4] = { pa[kc2 * 2], pb[kc2 * 2], pa[kc2 * 2 + 1], pb[kc2 * 2 + 1] };
#pragma unroll
            for (int dp = 0; dp < 4; ++dp) {
                uint32_t v0, v1, v2, v3;
                uint32_t ad = smem_u32(&Vh[(kc2 * 16 + lrow) * KST + dp * 16 + lcol]);
                LDMATRIX_X4_TRANS(v0, v1, v2, v3, ad);
                MMA_F16(o[dp * 2],     a, v0, v1);
                MMA_F16(o[dp * 2 + 1], a, v2, v3);
                ad = smem_u32(&Vl[(kc2 * 16 + lrow) * KST + dp * 16 + lcol]);
                LDMATRIX_X4_TRANS(v0, v1, v2, v3, ad);
                MMA_F16(o[dp * 2],     a, v0, v1);
                MMA_F16(o[dp * 2 + 1], a, v2, v3);
            }
        }
        __syncthreads();
    }

    // ---- epilogue: normalize, write fp16 hi/lo for oproj ----
    float inv0 = 1.0f / l0, inv1 = 1.0f / l1;
    const size_t r0 = (size_t)(row0 + wm + grp) * DM;
    const size_t r1 = r0 + 8 * DM;
#pragma unroll
    for (int nt = 0; nt < 8; ++nt) {
        int c = h * DH + nt * 8 + tig * 2;
        float x0 = o[nt][0] * inv0, x1 = o[nt][1] * inv0;
        float y0 = o[nt][2] * inv1, y1 = o[nt][3] * inv1;
        __half hx0 = __float2half_rn(x0), hx1 = __float2half_rn(x1);
        __half2 hp; hp.x = hx0; hp.y = hx1;
        __half2 lp; lp.x = __float2half_rn(x0 - __half2float(hx0));
                    lp.y = __float2half_rn(x1 - __half2float(hx1));
        *(__half2*)&g_ahi[r0 + c] = hp;
        *(__half2*)&g_alo[r0 + c] = lp;
        __half hy0 = __float2half_rn(y0), hy1 = __float2half_rn(y1);
        __half2 hq; hq.x = hy0; hq.y = hy1;
        __half2 lq; lq.x = __float2half_rn(y0 - __half2float(hy0));
                    lq.y = __float2half_rn(y1 - __half2float(hy1));
        *(__half2*)&g_ahi[r1 + c] = hq;
        *(__half2*)&g_alo[r1 + c] = lq;
    }
}

// ---------------- launch -----------------------------------------------------
extern "C" void kernel_launch(void* const* d_in, const int* in_sizes, int n_in,
                              void* d_out, int out_size) {
    const float* x  = (const float*)d_in[0];
    const void*  mk = d_in[1];
    const float* Wq = (const float*)d_in[2];
    const float* bq = (const float*)d_in[3];
    const float* Wk = (const float*)d_in[4];
    const float* bk = (const float*)d_in[5];
    const float* Wv = (const float*)d_in[6];
    const float* bv = (const float*)d_in[7];
    const float* Wo = (const float*)d_in[8];
    const float* bo = (const float*)d_in[9];
    float* out = (float*)d_out;

    detect_mask_kernel<<<1, 256>>>((const unsigned char*)mk);
    scan_mask_kernel<<<B_SZ, 256>>>(mk);

    prep_w_kernel<<<dim3(32, 32, 4), dim3(32, 8)>>>(Wq, Wk, Wv, Wo);
    conv_x_kernel<<<(MROWS * DM + 255) / 256, 256>>>(x);

    cudaFuncSetAttribute(qkv_tc_kernel,
                         cudaFuncAttributeMaxDynamicSharedMemorySize, GEMM_SMEM);
    cudaFuncSetAttribute(oproj_tc_kernel,
                         cudaFuncAttributeMaxDynamicSharedMemorySize, GEMM_SMEM);
    cudaFuncSetAttribute(attn_tc_kernel,
                         cudaFuncAttributeMaxDynamicSharedMemorySize, ATT_SMEM);

    qkv_tc_kernel<<<dim3(DM / 128, MROWS / 128, 3), 256, GEMM_SMEM>>>(bq, bk, bv);

    compact_kv_kernel<<<dim3(S_LEN / 2, B_SZ), 256>>>();

    attn_tc_kernel<<<dim3(S_LEN / 128, B_SZ * NH), 256, ATT_SMEM>>>();

    oproj_tc_kernel<<<dim3(DM / 128, MROWS / 128), 256, GEMM_SMEM>>>(bo, out);
}

// round 12
// speedup vs baseline: 7.6901x; 1.2105x over previous
#include <cuda_runtime.h>
#include <cuda_bf16.h>
#include <cuda_fp16.h>
#include <cstdint>

#define S_LEN 2048
#define B_SZ 4
#define NH 16
#define DH 64
#define DM 1024
#define MROWS (B_SZ * S_LEN)   // 8192
#define GK 1024

// ---------------- scratch (device globals; device-code references ONLY) -----
__device__ int   g_mask_mode;
__device__ int   g_kcnt[B_SZ];
__device__ int   g_kidx[B_SZ * S_LEN];
__device__ float g_cmask[B_SZ * S_LEN];

__device__ __half g_xhi[MROWS * DM];
__device__ __half g_xlo[MROWS * DM];
__device__ __half g_ahi[MROWS * DM];
__device__ __half g_alo[MROWS * DM];
__device__ __half g_wth[4 * DM * DM];    // W^T fp16, [N][K] K-major

__device__ __half g_qhi[MROWS * DM];
__device__ __half g_khi[MROWS * DM];
__device__ __half g_vhi[MROWS * DM];
// compacted (attended-only) K/V
__device__ __half g_ckhi[MROWS * DM];
__device__ __half g_cvhi[MROWS * DM];

// ---------------- PTX helpers ------------------------------------------------
__device__ __forceinline__ uint32_t smem_u32(const void* p) {
    uint32_t a;
    asm("{ .reg .u64 t; cvta.to.shared.u64 t, %1; cvt.u32.u64 %0, t; }"
        : "=r"(a) : "l"(p));
    return a;
}

#define MMA_F16(c, a, b0, b1)                                               \
    asm volatile("mma.sync.aligned.m16n8k16.row.col.f32.f16.f16.f32 "       \
                 "{%0,%1,%2,%3}, {%4,%5,%6,%7}, {%8,%9}, {%0,%1,%2,%3};"    \
                 : "+f"((c)[0]), "+f"((c)[1]), "+f"((c)[2]), "+f"((c)[3])   \
                 : "r"((a)[0]), "r"((a)[1]), "r"((a)[2]), "r"((a)[3]),      \
                   "r"(b0), "r"(b1))

#define LDMATRIX_X4_TRANS(r0, r1, r2, r3, addr)                             \
    asm volatile("ldmatrix.sync.aligned.m8n8.x4.trans.shared.b16 "          \
                 "{%0,%1,%2,%3}, [%4];"                                     \
                 : "=r"(r0), "=r"(r1), "=r"(r2), "=r"(r3) : "r"(addr))

__device__ __forceinline__ void cpa16(uint32_t dst, const void* src) {
    asm volatile("cp.async.ca.shared.global [%0], [%1], 16;"
                 :: "r"(dst), "l"(src));
}
#define CP_COMMIT()  asm volatile("cp.async.commit_group;" ::: "memory")
#define CP_WAIT(n)   asm volatile("cp.async.wait_group %0;" :: "n"(n) : "memory")

__device__ __forceinline__ uint32_t pack_h2(float a, float b) {
    __half2 h = __floats2half2_rn(a, b);
    return *(uint32_t*)&h;
}

__device__ __forceinline__ bool mask_true(const void* mraw, int i, int mode) {
    if (mode == 0)      return ((const int*)mraw)[i] != 0;
    else if (mode == 1) return ((const unsigned char*)mraw)[i] != 0;
    else                return ((const float*)mraw)[i] != 0.0f;
}

// ---------------- mask dtype detection --------------------------------------
__global__ void detect_mask_kernel(const unsigned char* __restrict__ m) {
    __shared__ int f_nonbin, f_off;
    int tid = threadIdx.x;
    if (tid == 0) { f_nonbin = 0; f_off = 0; }
    __syncthreads();
    int loc_nb = 0, loc_off = 0;
    for (int i = tid; i < B_SZ * S_LEN; i += blockDim.x) {
        unsigned char v = m[i];
        if (v > 1) loc_nb = 1;
        if ((i & 3) && v) loc_off = 1;
    }
    if (loc_nb) atomicOr(&f_nonbin, 1);
    if (loc_off) atomicOr(&f_off, 1);
    __syncthreads();
    if (tid == 0) g_mask_mode = f_nonbin ? 2 : (f_off ? 1 : 0);
}

// ---------------- per-batch mask prefix scan -> attended key indices ---------
__global__ __launch_bounds__(256)
void scan_mask_kernel(const void* __restrict__ mraw) {
    __shared__ int ssum[256];
    const int b = blockIdx.x;
    const int tid = threadIdx.x;
    const int mode = g_mask_mode;
    int flags[8], loc = 0;
#pragma unroll
    for (int j = 0; j < 8; ++j) {
        int i = tid * 8 + j;
        flags[j] = mask_true(mraw, b * S_LEN + i, mode) ? 1 : 0;
        loc += flags[j];
    }
    ssum[tid] = loc;
    __syncthreads();
    for (int off = 1; off < 256; off <<= 1) {
        int v = (tid >= off) ? ssum[tid - off] : 0;
        __syncthreads();
        ssum[tid] += v;
        __syncthreads();
    }
    int base = (tid > 0) ? ssum[tid - 1] : 0;
#pragma unroll
    for (int j = 0; j < 8; ++j) {
        if (flags[j]) g_kidx[b * S_LEN + base++] = tid * 8 + j;
    }
    if (tid == 255) g_kcnt[b] = ssum[255];
}

// ---------------- compact K/V rows to attended keys --------------------------
__global__ __launch_bounds__(256)
void compact_kv_kernel() {
    const int tid = threadIdx.x;
    const int b = blockIdx.y;
    const int i = blockIdx.x * 2 + (tid >> 7);
    const int c = (tid & 127) * 8;
    const int cnt = g_kcnt[b];
    const size_t drow = ((size_t)b * S_LEN + i) * DM + c;
    if (i < cnt) {
        const int src = g_kidx[b * S_LEN + i];
        const size_t srow = ((size_t)b * S_LEN + src) * DM + c;
        *(uint4*)&g_ckhi[drow] = *(const uint4*)&g_khi[srow];
        *(uint4*)&g_cvhi[drow] = *(const uint4*)&g_vhi[srow];
    } else {
        uint4 z = {0, 0, 0, 0};
        *(uint4*)&g_ckhi[drow] = z;
        *(uint4*)&g_cvhi[drow] = z;
    }
    if ((tid & 127) == 0) g_cmask[b * S_LEN + i] = (i < cnt) ? 0.0f : -1e30f;
}

// ---------------- fp32 -> fp16 hi/lo (x) -------------------------------------
__global__ __launch_bounds__(256)
void conv_x_kernel(const float* __restrict__ src) {
    int i = blockIdx.x * blockDim.x + threadIdx.x;
    if (i >= MROWS * DM) return;
    float v = src[i];
    __half h = __float2half_rn(v);
    g_xhi[i] = h;
    g_xlo[i] = __float2half_rn(v - __half2float(h));
}

// ---------------- W transpose + fp16 -----------------------------------------
__global__ __launch_bounds__(256)
void prep_w_kernel(const float* __restrict__ Wq, const float* __restrict__ Wk,
                   const float* __restrict__ Wv, const float* __restrict__ Wo) {
    __shared__ float t[32][33];
    int z = blockIdx.z;
    const float* W = (z == 0) ? Wq : (z == 1) ? Wk : (z == 2) ? Wv : Wo;
    __half* oh = g_wth + (size_t)z * DM * DM;
    int x0 = blockIdx.x * 32, y0 = blockIdx.y * 32;
    int tx = threadIdx.x, ty = threadIdx.y;   // (32, 8)
#pragma unroll
    for (int j = 0; j < 4; ++j)
        t[ty + j * 8][tx] = W[(size_t)(y0 + ty + j * 8) * DM + x0 + tx];
    __syncthreads();
#pragma unroll
    for (int j = 0; j < 4; ++j) {
        float v = t[tx][ty + j * 8];
        oh[(size_t)(x0 + ty + j * 8) * DM + y0 + tx] = __float2half_rn(v);
    }
}

// ---------------- mma.sync fp16 GEMM, cp.async double buffer ------------------
// C = A @ W^T + bias.  CTA 128x128, BK=32, 8 warps (4m x 2n).
// two_pass: Ahi*W + Alo*W (for V/out); else single Ahi*W (Q/K — consumed as
// fp16 anyway, added logit error ~1e-4).
#define AS_STRIDE 40
#define SEG (128 * AS_STRIDE)
#define SEGB (SEG * 2)
#define STAGEB (3 * SEGB)            // Ahi, Alo, Bh slots (Alo unused if 1-pass)
#define GEMM_SMEM (2 * STAGEB)       // 61440 bytes -> 2 CTAs/SM

template <bool HALF_OUT>
__device__ __forceinline__ void gemm_tc_body(const __half* __restrict__ Ahi,
                                             const __half* __restrict__ Alo,
                                             const __half* __restrict__ Bh_g,
                                             const float* __restrict__ bias,
                                             float* __restrict__ Cf,
                                             __half* __restrict__ Chi,
                                             __half* __restrict__ Clo,
                                             bool two_pass) {
    extern __shared__ __half smh[];

    const int tid  = threadIdx.x;
    const int lane = tid & 31, warp = tid >> 5;
    const int wm = (warp & 3) * 32;
    const int wn = (warp >> 2) * 64;
    const int m0 = blockIdx.y * 128;
    const int n0 = blockIdx.x * 128;
    const int grp = lane >> 2;
    const int tig = lane & 3;

    const uint32_t sb = smem_u32(smh);
    const int r0l = tid >> 2, q0l = tid & 3;
    const int r1l = (tid + 256) >> 2;
    const uint32_t soff0 = (uint32_t)(r0l * AS_STRIDE + q0l * 8) * 2;
    const uint32_t soff1 = (uint32_t)(r1l * AS_STRIDE + q0l * 8) * 2;

    float acc[2][8][4];
#pragma unroll
    for (int mt = 0; mt < 2; ++mt)
#pragma unroll
        for (int nt = 0; nt < 8; ++nt)
#pragma unroll
            for (int e = 0; e < 4; ++e) acc[mt][nt][e] = 0.0f;

    auto load_stage = [&](int kt, int s) {
        const uint32_t base = sb + (uint32_t)s * STAGEB;
        const size_t ga0 = (size_t)(m0 + r0l) * GK + kt * 32 + q0l * 8;
        const size_t ga1 = (size_t)(m0 + r1l) * GK + kt * 32 + q0l * 8;
        const size_t gb0 = (size_t)(n0 + r0l) * GK + kt * 32 + q0l * 8;
        const size_t gb1 = (size_t)(n0 + r1l) * GK + kt * 32 + q0l * 8;
        cpa16(base + soff0,            &Ahi[ga0]);
        cpa16(base + 2 * SEGB + soff0, &Bh_g[gb0]);
        cpa16(base + soff1,            &Ahi[ga1]);
        cpa16(base + 2 * SEGB + soff1, &Bh_g[gb1]);
        if (two_pass) {
            cpa16(base + SEGB + soff0, &Alo[ga0]);
            cpa16(base + SEGB + soff1, &Alo[ga1]);
        }
    };

    load_stage(0, 0);
    CP_COMMIT();

    for (int kt = 0; kt < GK / 32; ++kt) {
        const int cur = kt & 1;
        if (kt + 1 < GK / 32) {
            load_stage(kt + 1, cur ^ 1);
            CP_COMMIT();
            CP_WAIT(1);
        } else {
            CP_WAIT(0);
        }
        __syncthreads();

        const __half* Ah = smh + (size_t)cur * 3 * SEG;
        const __half* Al = Ah + SEG;
        const __half* Bs = Ah + 2 * SEG;

#pragma unroll
        for (int ks = 0; ks < 2; ++ks) {
            const int kof = ks * 16 + tig * 2;
            uint32_t bh[8][2];
#pragma unroll
            for (int nt = 0; nt < 8; ++nt) {
                const int nr = wn + nt * 8 + grp;
                bh[nt][0] = *(const uint32_t*)&Bs[nr * AS_STRIDE + kof];
                bh[nt][1] = *(const uint32_t*)&Bs[nr * AS_STRIDE + kof + 8];
            }
#pragma unroll
            for (int mt = 0; mt < 2; ++mt) {
                const int mr = wm + mt * 16 + grp;
                uint32_t a_h[4];
                a_h[0] = *(const uint32_t*)&Ah[mr * AS_STRIDE + kof];
                a_h[1] = *(const uint32_t*)&Ah[(mr + 8) * AS_STRIDE + kof];
                a_h[2] = *(const uint32_t*)&Ah[mr * AS_STRIDE + kof + 8];
                a_h[3] = *(const uint32_t*)&Ah[(mr + 8) * AS_STRIDE + kof + 8];
#pragma unroll
                for (int nt = 0; nt < 8; ++nt)
                    MMA_F16(acc[mt][nt], a_h, bh[nt][0], bh[nt][1]);
                if (two_pass) {
                    uint32_t a_l[4];
                    a_l[0] = *(const uint32_t*)&Al[mr * AS_STRIDE + kof];
                    a_l[1] = *(const uint32_t*)&Al[(mr + 8) * AS_STRIDE + kof];
                    a_l[2] = *(const uint32_t*)&Al[mr * AS_STRIDE + kof + 8];
                    a_l[3] = *(const uint32_t*)&Al[(mr + 8) * AS_STRIDE + kof + 8];
#pragma unroll
                    for (int nt = 0; nt < 8; ++nt)
                        MMA_F16(acc[mt][nt], a_l, bh[nt][0], bh[nt][1]);
                }
            }
        }
        __syncthreads();
    }

#pragma unroll
    for (int mt = 0; mt < 2; ++mt) {
#pragma unroll
        for (int nt = 0; nt < 8; ++nt) {
            int r = m0 + wm + mt * 16 + grp;
            int c = n0 + wn + nt * 8 + tig * 2;
            float2 bb = *(const float2*)&bias[c];
            float v0x = acc[mt][nt][0] + bb.x, v0y = acc[mt][nt][1] + bb.y;
            float v1x = acc[mt][nt][2] + bb.x, v1y = acc[mt][nt][3] + bb.y;
            if constexpr (HALF_OUT) {
                __half h0 = __float2half_rn(v0x), h1 = __float2half_rn(v0y);
                __half2 hp; hp.x = h0; hp.y = h1;
                *(__half2*)&Chi[(size_t)r * DM + c] = hp;
                __half g0 = __float2half_rn(v1x), g1 = __float2half_rn(v1y);
                __half2 hq; hq.x = g0; hq.y = g1;
                *(__half2*)&Chi[(size_t)(r + 8) * DM + c] = hq;
                (void)Clo;
            } else {
                float2 o0 = { v0x, v0y }, o1 = { v1x, v1y };
                *(float2*)&Cf[(size_t)r * DM + c] = o0;
                *(float2*)&Cf[(size_t)(r + 8) * DM + c] = o1;
            }
        }
    }
}

__global__ __launch_bounds__(256, 2)
void qkv_tc_kernel(const float* __restrict__ bq, const float* __restrict__ bk,
                   const float* __restrict__ bv) {
    int z = blockIdx.z;
    const __half* Bh = g_wth + (size_t)z * DM * DM;
    const float* bias = (z == 0) ? bq : (z == 1) ? bk : bv;
    __half* Chi = (z == 0) ? g_qhi : (z == 1) ? g_khi : g_vhi;
    // Q/K: consumed as fp16 in attention -> 1-pass suffices. V: 2-pass.
    gemm_tc_body<true>(g_xhi, g_xlo, Bh, bias, nullptr, Chi, nullptr, z == 2);
}

__global__ __launch_bounds__(256, 2)
void oproj_tc_kernel(const float* __restrict__ bo, float* __restrict__ out) {
    gemm_tc_body<false>(g_ahi, g_alo, g_wth + (size_t)3 * DM * DM,
                        bo, out, nullptr, nullptr, true);
}

// ---------------- flash attention: fp16 QK + fp16 V, cp.async 2-stage --------
#define KST 72
#define ASEG (64 * KST)
#define ASTG (2 * ASEG)              // Kh, Vh
#define ATT_SMEM (2 * ASTG * 2 + 2 * 64 * 4)   // 37376 bytes

__global__ __launch_bounds__(256, 2)
void attn_tc_kernel() {
    extern __shared__ __half asmem[];
    float* Msb = (float*)(asmem + 2 * ASTG);   // [2][64]

    const int tid = threadIdx.x;
    const int lane = tid & 31, warp = tid >> 5;
    const int grp = lane >> 2, tig = lane & 3;
    const int qb = blockIdx.x, bh = blockIdx.y;
    const int b = bh >> 4, h = bh & 15;
    const int row0 = b * S_LEN + qb * 128;
    const int wm = warp * 16;

    const int cnt = g_kcnt[b];
    const int nblk = (cnt + 63) >> 6;

    const uint32_t sb = smem_u32(asmem);
    const uint32_t msb = smem_u32(Msb);
    const int pr = tid >> 3, pc = (tid & 7) * 8;

    uint32_t qh[4][4];
    {
        const size_t r0 = (size_t)(row0 + wm + grp) * DM;
        const size_t r1 = r0 + 8 * DM;
#pragma unroll
        for (int kc = 0; kc < 4; ++kc) {
            int d = h * DH + kc * 16 + tig * 2;
            qh[kc][0] = *(const uint32_t*)&g_qhi[r0 + d];
            qh[kc][1] = *(const uint32_t*)&g_qhi[r1 + d];
            qh[kc][2] = *(const uint32_t*)&g_qhi[r0 + d + 8];
            qh[kc][3] = *(const uint32_t*)&g_qhi[r1 + d + 8];
        }
    }

    float o[8][4];
#pragma unroll
    for (int nt = 0; nt < 8; ++nt)
#pragma unroll
        for (int e = 0; e < 4; ++e) o[nt][e] = 0.0f;
    float m0 = -1e30f, m1 = -1e30f, l0 = 0.0f, l1 = 0.0f;

    auto load_stage = [&](int kb, int s) {
        const size_t gbase = (size_t)(b * S_LEN + kb * 64) * DM + h * DH;
        const uint32_t sbase = sb + (uint32_t)s * (ASTG * 2);
        const size_t g0 = gbase + (size_t)pr * DM + pc;
        const size_t g1 = gbase + (size_t)(pr + 32) * DM + pc;
        const uint32_t s0 = (uint32_t)(pr * KST + pc) * 2;
        const uint32_t s1 = (uint32_t)((pr + 32) * KST + pc) * 2;
        cpa16(sbase + s0,            &g_ckhi[g0]);
        cpa16(sbase + s1,            &g_ckhi[g1]);
        cpa16(sbase + ASEG * 2 + s0, &g_cvhi[g0]);
        cpa16(sbase + ASEG * 2 + s1, &g_cvhi[g1]);
        if (tid < 16)
            cpa16(msb + (uint32_t)s * 256 + tid * 16,
                  &g_cmask[b * S_LEN + kb * 64 + tid * 4]);
    };

    load_stage(0, 0);
    CP_COMMIT();

    for (int kb = 0; kb < nblk; ++kb) {
        const int cur = kb & 1;
        if (kb + 1 < nblk) {
            load_stage(kb + 1, cur ^ 1);
            CP_COMMIT();
            CP_WAIT(1);
        } else {
            CP_WAIT(0);
        }
        __syncthreads();

        const __half* Kh = asmem + (size_t)cur * ASTG;
        const __half* Vh = Kh + ASEG;
        const float* Ms = Msb + cur * 64;

        float s[8][4];
#pragma unroll
        for (int nt = 0; nt < 8; ++nt)
#pragma unroll
            for (int e = 0; e < 4; ++e) s[nt][e] = 0.0f;

#pragma unroll
        for (int kc = 0; kc < 4; ++kc) {
            const int kof = kc * 16 + tig * 2;
#pragma unroll
            for (int nt = 0; nt < 8; ++nt) {
                const int nr = nt * 8 + grp;
                uint32_t b0 = *(const uint32_t*)&Kh[nr * KST + kof];
                uint32_t b1 = *(const uint32_t*)&Kh[nr * KST + kof + 8];
                MMA_F16(s[nt], qh[kc], b0, b1);
            }
        }

        float tmax0 = -1e30f, tmax1 = -1e30f;
#pragma unroll
        for (int nt = 0; nt < 8; ++nt) {
            float2 mv = *(const float2*)&Ms[nt * 8 + tig * 2];
            s[nt][0] = fmaf(s[nt][0], 0.125f, mv.x);
            s[nt][1] = fmaf(s[nt][1], 0.125f, mv.y);
            s[nt][2] = fmaf(s[nt][2], 0.125f, mv.x);
            s[nt][3] = fmaf(s[nt][3], 0.125f, mv.y);
            tmax0 = fmaxf(tmax0, fmaxf(s[nt][0], s[nt][1]));
            tmax1 = fmaxf(tmax1, fmaxf(s[nt][2], s[nt][3]));
        }
        tmax0 = fmaxf(tmax0, __shfl_xor_sync(0xffffffffu, tmax0, 1));
        tmax0 = fmaxf(tmax0, __shfl_xor_sync(0xffffffffu, tmax0, 2));
        tmax1 = fmaxf(tmax1, __shfl_xor_sync(0xffffffffu, tmax1, 1));
        tmax1 = fmaxf(tmax1, __shfl_xor_sync(0xffffffffu, tmax1, 2));

        float mn0 = fmaxf(m0, tmax0), mn1 = fmaxf(m1, tmax1);
        float al0 = __expf(m0 - mn0), al1 = __expf(m1 - mn1);
        m0 = mn0; m1 = mn1;

        float rs0 = 0.0f, rs1 = 0.0f;
        uint32_t pa[8], pb[8];
#pragma unroll
        for (int nt = 0; nt < 8; ++nt) {
            float p0 = __expf(s[nt][0] - mn0);
            float p1 = __expf(s[nt][1] - mn0);
            float p2 = __expf(s[nt][2] - mn1);
            float p3 = __expf(s[nt][3] - mn1);
            rs0 += p0 + p1; rs1 += p2 + p3;
            pa[nt] = pack_h2(p0, p1);
            pb[nt] = pack_h2(p2, p3);
        }
        rs0 += __shfl_xor_sync(0xffffffffu, rs0, 1);
        rs0 += __shfl_xor_sync(0xffffffffu, rs0, 2);
        rs1 += __shfl_xor_sync(0xffffffffu, rs1, 1);
        rs1 += __shfl_xor_sync(0xffffffffu, rs1, 2);
        l0 = l0 * al0 + rs0;
        l1 = l1 * al1 + rs1;

#pragma unroll
        for (int nt = 0; nt < 8; ++nt) {
            o[nt][0] *= al0; o[nt][1] *= al0;
            o[nt][2] *= al1; o[nt][3] *= al1;
        }

        const int lrow = (lane & 7) + 8 * ((lane >> 3) & 1);
        const int lcol = 8 * (lane >> 4);
#pragma unroll
        for (int kc2 = 0; kc2 < 4; ++kc2) {
            uint32_t a[4] = { pa[kc2 * 2], pb[kc2 * 2], pa[kc2 * 2 + 1], pb[kc2 * 2 + 1] };
#pragma unroll
            for (int dp = 0; dp < 4; ++dp) {
                uint32_t v0, v1, v2, v3;
                uint32_t ad = smem_u32(&Vh[(kc2 * 16 + lrow) * KST + dp * 16 + lcol]);
                LDMATRIX_X4_TRANS(v0, v1, v2, v3, ad);
                MMA_F16(o[dp * 2],     a, v0, v1);
                MMA_F16(o[dp * 2 + 1], a, v2, v3);
            }
        }
        __syncthreads();
    }

    // ---- epilogue: normalize, write fp16 hi/lo for oproj ----
    float inv0 = 1.0f / l0, inv1 = 1.0f / l1;
    const size_t r0 = (size_t)(row0 + wm + grp) * DM;
    const size_t r1 = r0 + 8 * DM;
#pragma unroll
    for (int nt = 0; nt < 8; ++nt) {
        int c = h * DH + nt * 8 + tig * 2;
        float x0 = o[nt][0] * inv0, x1 = o[nt][1] * inv0;
        float y0 = o[nt][2] * inv1, y1 = o[nt][3] * inv1;
        __half hx0 = __float2half_rn(x0), hx1 = __float2half_rn(x1);
        __half2 hp; hp.x = hx0; hp.y = hx1;
        __half2 lp; lp.x = __float2half_rn(x0 - __half2float(hx0));
                    lp.y = __float2half_rn(x1 - __half2float(hx1));
        *(__half2*)&g_ahi[r0 + c] = hp;
        *(__half2*)&g_alo[r0 + c] = lp;
        __half hy0 = __float2half_rn(y0), hy1 = __float2half_rn(y1);
        __half2 hq; hq.x = hy0; hq.y = hy1;
        __half2 lq; lq.x = __float2half_rn(y0 - __half2float(hy0));
                    lq.y = __float2half_rn(y1 - __half2float(hy1));
        *(__half2*)&g_ahi[r1 + c] = hq;
        *(__half2*)&g_alo[r1 + c] = lq;
    }
}

// ---------------- launch -----------------------------------------------------
extern "C" void kernel_launch(void* const* d_in, const int* in_sizes, int n_in,
                              void* d_out, int out_size) {
    const float* x  = (const float*)d_in[0];
    const void*  mk = d_in[1];
    const float* Wq = (const float*)d_in[2];
    const float* bq = (const float*)d_in[3];
    const float* Wk = (const float*)d_in[4];
    const float* bk = (const float*)d_in[5];
    const float* Wv = (const float*)d_in[6];
    const float* bv = (const float*)d_in[7];
    const float* Wo = (const float*)d_in[8];
    const float* bo = (const float*)d_in[9];
    float* out = (float*)d_out;

    detect_mask_kernel<<<1, 256>>>((const unsigned char*)mk);
    scan_mask_kernel<<<B_SZ, 256>>>(mk);

    prep_w_kernel<<<dim3(32, 32, 4), dim3(32, 8)>>>(Wq, Wk, Wv, Wo);
    conv_x_kernel<<<(MROWS * DM + 255) / 256, 256>>>(x);

    cudaFuncSetAttribute(qkv_tc_kernel,
                         cudaFuncAttributeMaxDynamicSharedMemorySize, GEMM_SMEM);
    cudaFuncSetAttribute(oproj_tc_kernel,
                         cudaFuncAttributeMaxDynamicSharedMemorySize, GEMM_SMEM);
    cudaFuncSetAttribute(attn_tc_kernel,
                         cudaFuncAttributeMaxDynamicSharedMemorySize, ATT_SMEM);

    qkv_tc_kernel<<<dim3(DM / 128, MROWS / 128, 3), 256, GEMM_SMEM>>>(bq, bk, bv);

    compact_kv_kernel<<<dim3(S_LEN / 2, B_SZ), 256>>>();

    attn_tc_kernel<<<dim3(S_LEN / 128, B_SZ * NH), 256, ATT_SMEM>>>();

    oproj_tc_kernel<<<dim3(DM / 128, MROWS / 128), 256, GEMM_SMEM>>>(bo, out);
}

// round 13
// speedup vs baseline: 9.4344x; 1.2268x over previous
#include <cuda_runtime.h>
#include <cuda_bf16.h>
#include <cuda_fp16.h>
#include <cstdint>

#define S_LEN 2048
#define B_SZ 4
#define NH 16
#define DH 64
#define DM 1024
#define MROWS (B_SZ * S_LEN)   // 8192
#define GK 1024

// ---------------- scratch (device globals; device-code references ONLY) -----
// NOTE: compacted-K/V padding rows (rank >= kcnt) are NEVER written by any
// kernel; they stay at the guaranteed zero-initialization of __device__
// globals, and cmask=-1e30 makes their probabilities exactly 0.
__device__ int   g_mask_mode;
__device__ int   g_kcnt[B_SZ];
__device__ int   g_rank[B_SZ * S_LEN];    // global dest row or -1
__device__ float g_cmask[B_SZ * S_LEN];

__device__ __half g_xhi[MROWS * DM];
__device__ __half g_ahi[MROWS * DM];
__device__ __half g_wth[4 * DM * DM];     // W^T fp16, [N][K] K-major

__device__ __half g_qhi[MROWS * DM];
__device__ __half g_ckhi[MROWS * DM];     // compacted K (written by GEMM)
__device__ __half g_cvhi[MROWS * DM];     // compacted V (written by GEMM)

// ---------------- PTX helpers ------------------------------------------------
__device__ __forceinline__ uint32_t smem_u32(const void* p) {
    uint32_t a;
    asm("{ .reg .u64 t; cvta.to.shared.u64 t, %1; cvt.u32.u64 %0, t; }"
        : "=r"(a) : "l"(p));
    return a;
}

#define MMA_F16(c, a, b0, b1)                                               \
    asm volatile("mma.sync.aligned.m16n8k16.row.col.f32.f16.f16.f32 "       \
                 "{%0,%1,%2,%3}, {%4,%5,%6,%7}, {%8,%9}, {%0,%1,%2,%3};"    \
                 : "+f"((c)[0]), "+f"((c)[1]), "+f"((c)[2]), "+f"((c)[3])   \
                 : "r"((a)[0]), "r"((a)[1]), "r"((a)[2]), "r"((a)[3]),      \
                   "r"(b0), "r"(b1))

#define LDMATRIX_X4_TRANS(r0, r1, r2, r3, addr)                             \
    asm volatile("ldmatrix.sync.aligned.m8n8.x4.trans.shared.b16 "          \
                 "{%0,%1,%2,%3}, [%4];"                                     \
                 : "=r"(r0), "=r"(r1), "=r"(r2), "=r"(r3) : "r"(addr))

__device__ __forceinline__ void cpa16(uint32_t dst, const void* src) {
    asm volatile("cp.async.ca.shared.global [%0], [%1], 16;"
                 :: "r"(dst), "l"(src));
}
#define CP_COMMIT()  asm volatile("cp.async.commit_group;" ::: "memory")
#define CP_WAIT(n)   asm volatile("cp.async.wait_group %0;" :: "n"(n) : "memory")

__device__ __forceinline__ uint32_t pack_h2(float a, float b) {
    __half2 h = __floats2half2_rn(a, b);
    return *(uint32_t*)&h;
}

__device__ __forceinline__ bool mask_true(const void* mraw, int i, int mode) {
    if (mode == 0)      return ((const int*)mraw)[i] != 0;
    else if (mode == 1) return ((const unsigned char*)mraw)[i] != 0;
    else                return ((const float*)mraw)[i] != 0.0f;
}

// ---------------- mask dtype detection --------------------------------------
__global__ void detect_mask_kernel(const unsigned char* __restrict__ m) {
    __shared__ int f_nonbin, f_off;
    int tid = threadIdx.x;
    if (tid == 0) { f_nonbin = 0; f_off = 0; }
    __syncthreads();
    int loc_nb = 0, loc_off = 0;
    for (int i = tid; i < B_SZ * S_LEN; i += blockDim.x) {
        unsigned char v = m[i];
        if (v > 1) loc_nb = 1;
        if ((i & 3) && v) loc_off = 1;
    }
    if (loc_nb) atomicOr(&f_nonbin, 1);
    if (loc_off) atomicOr(&f_off, 1);
    __syncthreads();
    if (tid == 0) g_mask_mode = f_nonbin ? 2 : (f_off ? 1 : 0);
}

// ---------------- per-batch mask prefix scan -> rank map + cmask -------------
__global__ __launch_bounds__(256)
void scan_mask_kernel(const void* __restrict__ mraw) {
    __shared__ int ssum[256];
    const int b = blockIdx.x;
    const int tid = threadIdx.x;
    const int mode = g_mask_mode;
    int flags[8], loc = 0;
#pragma unroll
    for (int j = 0; j < 8; ++j) {
        int i = tid * 8 + j;
        flags[j] = mask_true(mraw, b * S_LEN + i, mode) ? 1 : 0;
        loc += flags[j];
    }
    ssum[tid] = loc;
    __syncthreads();
    for (int off = 1; off < 256; off <<= 1) {
        int v = (tid >= off) ? ssum[tid - off] : 0;
        __syncthreads();
        ssum[tid] += v;
        __syncthreads();
    }
    int base = (tid > 0) ? ssum[tid - 1] : 0;
    const int cnt = ssum[255];
#pragma unroll
    for (int j = 0; j < 8; ++j) {
        int i = tid * 8 + j;
        g_rank[b * S_LEN + i] = flags[j] ? (b * S_LEN + base++) : -1;
        g_cmask[b * S_LEN + i] = (i < cnt) ? 0.0f : -1e30f;
    }
    if (tid == 255) g_kcnt[b] = cnt;
}

// ---------------- fp32 -> fp16 (x) -------------------------------------------
__global__ __launch_bounds__(256)
void conv_x_kernel(const float* __restrict__ src) {
    int i = blockIdx.x * blockDim.x + threadIdx.x;
    if (i >= MROWS * DM) return;
    g_xhi[i] = __float2half_rn(src[i]);
}

// ---------------- W transpose + fp16 -----------------------------------------
__global__ __launch_bounds__(256)
void prep_w_kernel(const float* __restrict__ Wq, const float* __restrict__ Wk,
                   const float* __restrict__ Wv, const float* __restrict__ Wo) {
    __shared__ float t[32][33];
    int z = blockIdx.z;
    const float* W = (z == 0) ? Wq : (z == 1) ? Wk : (z == 2) ? Wv : Wo;
    __half* oh = g_wth + (size_t)z * DM * DM;
    int x0 = blockIdx.x * 32, y0 = blockIdx.y * 32;
    int tx = threadIdx.x, ty = threadIdx.y;   // (32, 8)
#pragma unroll
    for (int j = 0; j < 4; ++j)
        t[ty + j * 8][tx] = W[(size_t)(y0 + ty + j * 8) * DM + x0 + tx];
    __syncthreads();
#pragma unroll
    for (int j = 0; j < 4; ++j) {
        float v = t[tx][ty + j * 8];
        oh[(size_t)(x0 + ty + j * 8) * DM + y0 + tx] = __float2half_rn(v);
    }
}

// ---------------- mma.sync fp16 GEMM, cp.async double buffer ------------------
// C = A @ W^T + bias.  CTA 128x128, BK=32, 8 warps (4m x 2n), single fp16 pass.
// Optional remap: per-output-row destination (or -1 = drop) for fused K/V
// compaction.
#define AS_STRIDE 40
#define SEG (128 * AS_STRIDE)
#define SEGB (SEG * 2)
#define STAGEB (2 * SEGB)            // A, B
#define GEMM_SMEM (2 * STAGEB)       // 40960 bytes

template <bool HALF_OUT>
__device__ __forceinline__ void gemm_tc_body(const __half* __restrict__ Ah_g,
                                             const __half* __restrict__ Bh_g,
                                             const float* __restrict__ bias,
                                             float* __restrict__ Cf,
                                             __half* __restrict__ Chi,
                                             const int* __restrict__ remap) {
    extern __shared__ __half smh[];

    const int tid  = threadIdx.x;
    const int lane = tid & 31, warp = tid >> 5;
    const int wm = (warp & 3) * 32;
    const int wn = (warp >> 2) * 64;
    const int m0 = blockIdx.y * 128;
    const int n0 = blockIdx.x * 128;
    const int grp = lane >> 2;
    const int tig = lane & 3;

    const uint32_t sb = smem_u32(smh);
    const int r0l = tid >> 2, q0l = tid & 3;
    const int r1l = (tid + 256) >> 2;
    const uint32_t soff0 = (uint32_t)(r0l * AS_STRIDE + q0l * 8) * 2;
    const uint32_t soff1 = (uint32_t)(r1l * AS_STRIDE + q0l * 8) * 2;

    float acc[2][8][4];
#pragma unroll
    for (int mt = 0; mt < 2; ++mt)
#pragma unroll
        for (int nt = 0; nt < 8; ++nt)
#pragma unroll
            for (int e = 0; e < 4; ++e) acc[mt][nt][e] = 0.0f;

    auto load_stage = [&](int kt, int s) {
        const uint32_t base = sb + (uint32_t)s * STAGEB;
        const size_t ga0 = (size_t)(m0 + r0l) * GK + kt * 32 + q0l * 8;
        const size_t ga1 = (size_t)(m0 + r1l) * GK + kt * 32 + q0l * 8;
        const size_t gb0 = (size_t)(n0 + r0l) * GK + kt * 32 + q0l * 8;
        const size_t gb1 = (size_t)(n0 + r1l) * GK + kt * 32 + q0l * 8;
        cpa16(base + soff0,        &Ah_g[ga0]);
        cpa16(base + SEGB + soff0, &Bh_g[gb0]);
        cpa16(base + soff1,        &Ah_g[ga1]);
        cpa16(base + SEGB + soff1, &Bh_g[gb1]);
    };

    load_stage(0, 0);
    CP_COMMIT();

    for (int kt = 0; kt < GK / 32; ++kt) {
        const int cur = kt & 1;
        if (kt + 1 < GK / 32) {
            load_stage(kt + 1, cur ^ 1);
            CP_COMMIT();
            CP_WAIT(1);
        } else {
            CP_WAIT(0);
        }
        __syncthreads();

        const __half* Ah = smh + (size_t)cur * 2 * SEG;
        const __half* Bs = Ah + SEG;

#pragma unroll
        for (int ks = 0; ks < 2; ++ks) {
            const int kof = ks * 16 + tig * 2;
            uint32_t bh[8][2];
#pragma unroll
            for (int nt = 0; nt < 8; ++nt) {
                const int nr = wn + nt * 8 + grp;
                bh[nt][0] = *(const uint32_t*)&Bs[nr * AS_STRIDE + kof];
                bh[nt][1] = *(const uint32_t*)&Bs[nr * AS_STRIDE + kof + 8];
            }
#pragma unroll
            for (int mt = 0; mt < 2; ++mt) {
                const int mr = wm + mt * 16 + grp;
                uint32_t a_h[4];
                a_h[0] = *(const uint32_t*)&Ah[mr * AS_STRIDE + kof];
                a_h[1] = *(const uint32_t*)&Ah[(mr + 8) * AS_STRIDE + kof];
                a_h[2] = *(const uint32_t*)&Ah[mr * AS_STRIDE + kof + 8];
                a_h[3] = *(const uint32_t*)&Ah[(mr + 8) * AS_STRIDE + kof + 8];
#pragma unroll
                for (int nt = 0; nt < 8; ++nt)
                    MMA_F16(acc[mt][nt], a_h, bh[nt][0], bh[nt][1]);
            }
        }
        __syncthreads();
    }

#pragma unroll
    for (int mt = 0; mt < 2; ++mt) {
        const int r = m0 + wm + mt * 16 + grp;
        int d0 = r, d1 = r + 8;
        if (HALF_OUT && remap) {
            d0 = remap[r];
            d1 = remap[r + 8];
        }
#pragma unroll
        for (int nt = 0; nt < 8; ++nt) {
            int c = n0 + wn + nt * 8 + tig * 2;
            float2 bb = *(const float2*)&bias[c];
            float v0x = acc[mt][nt][0] + bb.x, v0y = acc[mt][nt][1] + bb.y;
            float v1x = acc[mt][nt][2] + bb.x, v1y = acc[mt][nt][3] + bb.y;
            if constexpr (HALF_OUT) {
                if (d0 >= 0) {
                    __half2 hp; hp.x = __float2half_rn(v0x); hp.y = __float2half_rn(v0y);
                    *(__half2*)&Chi[(size_t)d0 * DM + c] = hp;
                }
                if (d1 >= 0) {
                    __half2 hq; hq.x = __float2half_rn(v1x); hq.y = __float2half_rn(v1y);
                    *(__half2*)&Chi[(size_t)d1 * DM + c] = hq;
                }
            } else {
                float2 o0 = { v0x, v0y }, o1 = { v1x, v1y };
                *(float2*)&Cf[(size_t)r * DM + c] = o0;
                *(float2*)&Cf[(size_t)(r + 8) * DM + c] = o1;
            }
        }
    }
}

__global__ __launch_bounds__(256, 2)
void qkv_tc_kernel(const float* __restrict__ bq, const float* __restrict__ bk,
                   const float* __restrict__ bv) {
    int z = blockIdx.z;
    const __half* Bh = g_wth + (size_t)z * DM * DM;
    const float* bias = (z == 0) ? bq : (z == 1) ? bk : bv;
    __half* Chi = (z == 0) ? g_qhi : (z == 1) ? g_ckhi : g_cvhi;
    const int* remap = (z == 0) ? nullptr : g_rank;   // K/V write compacted rows
    gemm_tc_body<true>(g_xhi, Bh, bias, nullptr, Chi, remap);
}

__global__ __launch_bounds__(256, 2)
void oproj_tc_kernel(const float* __restrict__ bo, float* __restrict__ out) {
    gemm_tc_body<false>(g_ahi, g_wth + (size_t)3 * DM * DM, bo, out,
                        nullptr, nullptr);
}

// ---------------- flash attention: fp16 QK + fp16 V, cp.async 2-stage --------
#define KST 72
#define ASEG (64 * KST)
#define ASTG (2 * ASEG)              // Kh, Vh
#define ATT_SMEM (2 * ASTG * 2 + 2 * 64 * 4)   // 37376 bytes

__global__ __launch_bounds__(256, 2)
void attn_tc_kernel() {
    extern __shared__ __half asmem[];
    float* Msb = (float*)(asmem + 2 * ASTG);   // [2][64]

    const int tid = threadIdx.x;
    const int lane = tid & 31, warp = tid >> 5;
    const int grp = lane >> 2, tig = lane & 3;
    const int qb = blockIdx.x, bh = blockIdx.y;
    const int b = bh >> 4, h = bh & 15;
    const int row0 = b * S_LEN + qb * 128;
    const int wm = warp * 16;

    const int cnt = g_kcnt[b];
    const int nblk = (cnt + 63) >> 6;

    const uint32_t sb = smem_u32(asmem);
    const uint32_t msb = smem_u32(Msb);
    const int pr = tid >> 3, pc = (tid & 7) * 8;

    uint32_t qh[4][4];
    {
        const size_t r0 = (size_t)(row0 + wm + grp) * DM;
        const size_t r1 = r0 + 8 * DM;
#pragma unroll
        for (int kc = 0; kc < 4; ++kc) {
            int d = h * DH + kc * 16 + tig * 2;
            qh[kc][0] = *(const uint32_t*)&g_qhi[r0 + d];
            qh[kc][1] = *(const uint32_t*)&g_qhi[r1 + d];
            qh[kc][2] = *(const uint32_t*)&g_qhi[r0 + d + 8];
            qh[kc][3] = *(const uint32_t*)&g_qhi[r1 + d + 8];
        }
    }

    float o[8][4];
#pragma unroll
    for (int nt = 0; nt < 8; ++nt)
#pragma unroll
        for (int e = 0; e < 4; ++e) o[nt][e] = 0.0f;
    float m0 = -1e30f, m1 = -1e30f, l0 = 0.0f, l1 = 0.0f;

    auto load_stage = [&](int kb, int s) {
        const size_t gbase = (size_t)(b * S_LEN + kb * 64) * DM + h * DH;
        const uint32_t sbase = sb + (uint32_t)s * (ASTG * 2);
        const size_t g0 = gbase + (size_t)pr * DM + pc;
        const size_t g1 = gbase + (size_t)(pr + 32) * DM + pc;
        const uint32_t s0 = (uint32_t)(pr * KST + pc) * 2;
        const uint32_t s1 = (uint32_t)((pr + 32) * KST + pc) * 2;
        cpa16(sbase + s0,            &g_ckhi[g0]);
        cpa16(sbase + s1,            &g_ckhi[g1]);
        cpa16(sbase + ASEG * 2 + s0, &g_cvhi[g0]);
        cpa16(sbase + ASEG * 2 + s1, &g_cvhi[g1]);
        if (tid < 16)
            cpa16(msb + (uint32_t)s * 256 + tid * 16,
                  &g_cmask[b * S_LEN + kb * 64 + tid * 4]);
    };

    load_stage(0, 0);
    CP_COMMIT();

    for (int kb = 0; kb < nblk; ++kb) {
        const int cur = kb & 1;
        if (kb + 1 < nblk) {
            load_stage(kb + 1, cur ^ 1);
            CP_COMMIT();
            CP_WAIT(1);
        } else {
            CP_WAIT(0);
        }
        __syncthreads();

        const __half* Kh = asmem + (size_t)cur * ASTG;
        const __half* Vh = Kh + ASEG;
        const float* Ms = Msb + cur * 64;

        float s[8][4];
#pragma unroll
        for (int nt = 0; nt < 8; ++nt)
#pragma unroll
            for (int e = 0; e < 4; ++e) s[nt][e] = 0.0f;

#pragma unroll
        for (int kc = 0; kc < 4; ++kc) {
            const int kof = kc * 16 + tig * 2;
#pragma unroll
            for (int nt = 0; nt < 8; ++nt) {
                const int nr = nt * 8 + grp;
                uint32_t b0 = *(const uint32_t*)&Kh[nr * KST + kof];
                uint32_t b1 = *(const uint32_t*)&Kh[nr * KST + kof + 8];
                MMA_F16(s[nt], qh[kc], b0, b1);
            }
        }

        float tmax0 = -1e30f, tmax1 = -1e30f;
#pragma unroll
        for (int nt = 0; nt < 8; ++nt) {
            float2 mv = *(const float2*)&Ms[nt * 8 + tig * 2];
            s[nt][0] = fmaf(s[nt][0], 0.125f, mv.x);
            s[nt][1] = fmaf(s[nt][1], 0.125f, mv.y);
            s[nt][2] = fmaf(s[nt][2], 0.125f, mv.x);
            s[nt][3] = fmaf(s[nt][3], 0.125f, mv.y);
            tmax0 = fmaxf(tmax0, fmaxf(s[nt][0], s[nt][1]));
            tmax1 = fmaxf(tmax1, fmaxf(s[nt][2], s[nt][3]));
        }
        tmax0 = fmaxf(tmax0, __shfl_xor_sync(0xffffffffu, tmax0, 1));
        tmax0 = fmaxf(tmax0, __shfl_xor_sync(0xffffffffu, tmax0, 2));
        tmax1 = fmaxf(tmax1, __shfl_xor_sync(0xffffffffu, tmax1, 1));
        tmax1 = fmaxf(tmax1, __shfl_xor_sync(0xffffffffu, tmax1, 2));

        float mn0 = fmaxf(m0, tmax0), mn1 = fmaxf(m1, tmax1);
        float al0 = __expf(m0 - mn0), al1 = __expf(m1 - mn1);
        m0 = mn0; m1 = mn1;

        float rs0 = 0.0f, rs1 = 0.0f;
        uint32_t pa[8], pb[8];
#pragma unroll
        for (int nt = 0; nt < 8; ++nt) {
            float p0 = __expf(s[nt][0] - mn0);
            float p1 = __expf(s[nt][1] - mn0);
            float p2 = __expf(s[nt][2] - mn1);
            float p3 = __expf(s[nt][3] - mn1);
            rs0 += p0 + p1; rs1 += p2 + p3;
            pa[nt] = pack_h2(p0, p1);
            pb[nt] = pack_h2(p2, p3);
        }
        rs0 += __shfl_xor_sync(0xffffffffu, rs0, 1);
        rs0 += __shfl_xor_sync(0xffffffffu, rs0, 2);
        rs1 += __shfl_xor_sync(0xffffffffu, rs1, 1);
        rs1 += __shfl_xor_sync(0xffffffffu, rs1, 2);
        l0 = l0 * al0 + rs0;
        l1 = l1 * al1 + rs1;

#pragma unroll
        for (int nt = 0; nt < 8; ++nt) {
            o[nt][0] *= al0; o[nt][1] *= al0;
            o[nt][2] *= al1; o[nt][3] *= al1;
        }

        const int lrow = (lane & 7) + 8 * ((lane >> 3) & 1);
        const int lcol = 8 * (lane >> 4);
#pragma unroll
        for (int kc2 = 0; kc2 < 4; ++kc2) {
            uint32_t a[4] = { pa[kc2 * 2], pb[kc2 * 2], pa[kc2 * 2 + 1], pb[kc2 * 2 + 1] };
#pragma unroll
            for (int dp = 0; dp < 4; ++dp) {
                uint32_t v0, v1, v2, v3;
                uint32_t ad = smem_u32(&Vh[(kc2 * 16 + lrow) * KST + dp * 16 + lcol]);
                LDMATRIX_X4_TRANS(v0, v1, v2, v3, ad);
                MMA_F16(o[dp * 2],     a, v0, v1);
                MMA_F16(o[dp * 2 + 1], a, v2, v3);
            }
        }
        __syncthreads();
    }

    // ---- epilogue: normalize, write fp16 for oproj ----
    float inv0 = 1.0f / l0, inv1 = 1.0f / l1;
    const size_t r0 = (size_t)(row0 + wm + grp) * DM;
    const size_t r1 = r0 + 8 * DM;
#pragma unroll
    for (int nt = 0; nt < 8; ++nt) {
        int c = h * DH + nt * 8 + tig * 2;
        __half2 hp; hp.x = __float2half_rn(o[nt][0] * inv0);
                    hp.y = __float2half_rn(o[nt][1] * inv0);
        *(__half2*)&g_ahi[r0 + c] = hp;
        __half2 hq; hq.x = __float2half_rn(o[nt][2] * inv1);
                    hq.y = __float2half_rn(o[nt][3] * inv1);
        *(__half2*)&g_ahi[r1 + c] = hq;
    }
}

// ---------------- launch -----------------------------------------------------
extern "C" void kernel_launch(void* const* d_in, const int* in_sizes, int n_in,
                              void* d_out, int out_size) {
    const float* x  = (const float*)d_in[0];
    const void*  mk = d_in[1];
    const float* Wq = (const float*)d_in[2];
    const float* bq = (const float*)d_in[3];
    const float* Wk = (const float*)d_in[4];
    const float* bk = (const float*)d_in[5];
    const float* Wv = (const float*)d_in[6];
    const float* bv = (const float*)d_in[7];
    const float* Wo = (const float*)d_in[8];
    const float* bo = (const float*)d_in[9];
    float* out = (float*)d_out;

    detect_mask_kernel<<<1, 256>>>((const unsigned char*)mk);
    scan_mask_kernel<<<B_SZ, 256>>>(mk);

    prep_w_kernel<<<dim3(32, 32, 4), dim3(32, 8)>>>(Wq, Wk, Wv, Wo);
    conv_x_kernel<<<(MROWS * DM + 255) / 256, 256>>>(x);

    cudaFuncSetAttribute(qkv_tc_kernel,
                         cudaFuncAttributeMaxDynamicSharedMemorySize, GEMM_SMEM);
    cudaFuncSetAttribute(oproj_tc_kernel,
                         cudaFuncAttributeMaxDynamicSharedMemorySize, GEMM_SMEM);
    cudaFuncSetAttribute(attn_tc_kernel,
                         cudaFuncAttributeMaxDynamicSharedMemorySize, ATT_SMEM);

    qkv_tc_kernel<<<dim3(DM / 128, MROWS / 128, 3), 256, GEMM_SMEM>>>(bq, bk, bv);

    attn_tc_kernel<<<dim3(S_LEN / 128, B_SZ * NH), 256, ATT_SMEM>>>();

    oproj_tc_kernel<<<dim3(DM / 128, MROWS / 128), 256, GEMM_SMEM>>>(bo, out);
}